// round 5
// baseline (speedup 1.0000x reference)
#include <cuda_runtime.h>
#include <math.h>
#include <stdint.h>

// ---------------- problem constants ----------------
#define BATCH   2048
#define TT      64
#define BT      (BATCH * TT)      // 131072 rows
#define C       384
#define NH      8
#define HD      48
#define C4      1536
#define QKVN    1152

#define QF      32639.0f          // 127*256 + 127
#define S_ATT   8.0f              // fixed scale bound for attention outputs
#define S_HID   8.0f              // fixed scale bound for ffn hidden

// ---------------- device scratch ----------------
__device__ __align__(256) int8_t g_h_hi[BT * C],    g_h_lo[BT * C];
__device__ __align__(256) float  g_sa_ln[BT];
__device__ __align__(256) float  g_qkv[BT * QKVN];
__device__ __align__(256) int8_t g_attn_hi[BT * C], g_attn_lo[BT * C];
__device__ __align__(256) float  g_x2[BT * C];
__device__ __align__(256) int8_t g_hid_hi[BT * C4], g_hid_lo[BT * C4];
// weights [N,K] s8 hi/lo + per-N-row scales
__device__ __align__(256) int8_t g_wqkv_hi[QKVN * C], g_wqkv_lo[QKVN * C];
__device__ __align__(256) float  g_sb_qkv[QKVN];
__device__ __align__(256) int8_t g_wp_hi[C * C],      g_wp_lo[C * C];
__device__ __align__(256) float  g_sb_p[C];
__device__ __align__(256) int8_t g_w1_hi[C4 * C],     g_w1_lo[C4 * C];
__device__ __align__(256) float  g_sb_1[C4];
__device__ __align__(256) int8_t g_w2_hi[C * C4],     g_w2_lo[C * C4];
__device__ __align__(256) float  g_sb_2[C];

// ---------------- PTX helpers (base-arch PTX only) ----------------
__device__ __forceinline__ uint32_t smem_u32(const void* p) {
    uint32_t a;
    asm("{ .reg .u64 t; cvta.to.shared.u64 t, %1; cvt.u32.u64 %0, t; }" : "=r"(a) : "l"(p));
    return a;
}
__device__ __forceinline__ void cpa16(uint32_t dst, const void* src) {
    asm volatile("cp.async.cg.shared.global [%0], [%1], 16;" :: "r"(dst), "l"(src));
}
#define CP_COMMIT() asm volatile("cp.async.commit_group;" ::: "memory")
#define CP_WAIT(n)  asm volatile("cp.async.wait_group %0;" :: "n"(n) : "memory")

__device__ __forceinline__ void ldsm_x4(uint32_t a, uint32_t* r) {
    asm volatile("ldmatrix.sync.aligned.m8n8.x4.shared.b16 {%0,%1,%2,%3}, [%4];"
                 : "=r"(r[0]), "=r"(r[1]), "=r"(r[2]), "=r"(r[3]) : "r"(a));
}
__device__ __forceinline__ void imma(int* d, const uint32_t* a, const uint32_t* b) {
    asm volatile("mma.sync.aligned.m16n8k32.row.col.s32.s8.s8.s32 "
                 "{%0,%1,%2,%3}, {%4,%5,%6,%7}, {%8,%9}, {%0,%1,%2,%3};"
                 : "+r"(d[0]), "+r"(d[1]), "+r"(d[2]), "+r"(d[3])
                 : "r"(a[0]), "r"(a[1]), "r"(a[2]), "r"(a[3]), "r"(b[0]), "r"(b[1]));
}

// split signed 16-bit fixed point into two s8 planes: v_int = 256*hi + lo
__device__ __forceinline__ void qsplit(float v, float inv, int8_t& h, int8_t& l) {
    int q = __float2int_rn(fminf(fmaxf(v * inv, -QF), QF));
    int lo = (int)(int8_t)(q & 0xFF);
    h = (int8_t)((q - lo) >> 8);
    l = (int8_t)lo;
}

// ---------------- weight prep: one warp per output row n of [N,K] ----------------
__global__ void prep_qkv_q(const float* __restrict__ Wq, const float* __restrict__ Wk,
                           const float* __restrict__ Wv,
                           int8_t* __restrict__ hi, int8_t* __restrict__ lo,
                           float* __restrict__ sB) {
    int n = blockIdx.x * (blockDim.x >> 5) + (threadIdx.x >> 5);
    int lane = threadIdx.x & 31;
    if (n >= QKVN) return;
    int m = n / C, hd = n % C;
    int h = hd / HD, d = hd % HD;
    const float* W = (m == 0) ? Wq : ((m == 1) ? Wk : Wv);
    const float* col = W + (size_t)h * C * HD + d;
    float mx = 0.f;
    for (int k = lane; k < C; k += 32) mx = fmaxf(mx, fabsf(col[(size_t)k * HD]));
#pragma unroll
    for (int o = 16; o; o >>= 1) mx = fmaxf(mx, __shfl_xor_sync(0xffffffffu, mx, o));
    mx = fmaxf(mx, 1e-20f);
    float inv = QF / mx;
    if (lane == 0) sB[n] = mx / QF;
    for (int k = lane; k < C; k += 32) {
        int8_t hh, ll;
        qsplit(col[(size_t)k * HD], inv, hh, ll);
        hi[(size_t)n * C + k] = hh;
        lo[(size_t)n * C + k] = ll;
    }
}

__global__ void prep_w_q(const float* __restrict__ src /*[K,N]*/,
                         int8_t* __restrict__ hi, int8_t* __restrict__ lo,
                         float* __restrict__ sB, int K, int N) {
    int n = blockIdx.x * (blockDim.x >> 5) + (threadIdx.x >> 5);
    int lane = threadIdx.x & 31;
    if (n >= N) return;
    float mx = 0.f;
    for (int k = lane; k < K; k += 32) mx = fmaxf(mx, fabsf(src[(size_t)k * N + n]));
#pragma unroll
    for (int o = 16; o; o >>= 1) mx = fmaxf(mx, __shfl_xor_sync(0xffffffffu, mx, o));
    mx = fmaxf(mx, 1e-20f);
    float inv = QF / mx;
    if (lane == 0) sB[n] = mx / QF;
    for (int k = lane; k < K; k += 32) {
        int8_t hh, ll;
        qsplit(src[(size_t)k * N + n], inv, hh, ll);
        hi[(size_t)n * K + k] = hh;
        lo[(size_t)n * K + k] = ll;
    }
}

// ---------------- layernorm: one warp per row, quantized s8 hi/lo + row scale ----------------
__global__ void ln_q_kernel(const float* __restrict__ x, const float* __restrict__ g,
                            const float* __restrict__ b,
                            int8_t* __restrict__ out_hi, int8_t* __restrict__ out_lo,
                            float* __restrict__ sA) {
    int row  = blockIdx.x * blockDim.y + threadIdx.y;
    int lane = threadIdx.x;
    const float* xr = x + (size_t)row * C;
    float4 v[3];
    float sum = 0.f, sq = 0.f;
#pragma unroll
    for (int i = 0; i < 3; i++) {
        v[i] = *(const float4*)(xr + i * 128 + lane * 4);
        sum += v[i].x + v[i].y + v[i].z + v[i].w;
        sq  += v[i].x * v[i].x + v[i].y * v[i].y + v[i].z * v[i].z + v[i].w * v[i].w;
    }
#pragma unroll
    for (int o = 16; o; o >>= 1) {
        sum += __shfl_xor_sync(0xffffffffu, sum, o);
        sq  += __shfl_xor_sync(0xffffffffu, sq, o);
    }
    float mean = sum * (1.0f / C);
    float var  = sq * (1.0f / C) - mean * mean;
    float rstd = rsqrtf(var + 1e-5f);
    float o4[12];
    float mx = 0.f;
#pragma unroll
    for (int i = 0; i < 3; i++) {
        int col = i * 128 + lane * 4;
        float4 gg = *(const float4*)(g + col);
        float4 bb = *(const float4*)(b + col);
        o4[i*4+0] = (v[i].x - mean) * rstd * gg.x + bb.x;
        o4[i*4+1] = (v[i].y - mean) * rstd * gg.y + bb.y;
        o4[i*4+2] = (v[i].z - mean) * rstd * gg.z + bb.z;
        o4[i*4+3] = (v[i].w - mean) * rstd * gg.w + bb.w;
#pragma unroll
        for (int j = 0; j < 4; j++) mx = fmaxf(mx, fabsf(o4[i*4+j]));
    }
#pragma unroll
    for (int o = 16; o; o >>= 1) mx = fmaxf(mx, __shfl_xor_sync(0xffffffffu, mx, o));
    mx = fmaxf(mx, 1e-20f);
    float inv = QF / mx;
    if (lane == 0) sA[row] = mx / QF;
    size_t rbase = (size_t)row * C;
#pragma unroll
    for (int i = 0; i < 3; i++) {
        int col = i * 128 + lane * 4;
        int8_t h0, l0, h1, l1, h2, l2, h3, l3;
        qsplit(o4[i*4+0], inv, h0, l0); qsplit(o4[i*4+1], inv, h1, l1);
        qsplit(o4[i*4+2], inv, h2, l2); qsplit(o4[i*4+3], inv, h3, l3);
        *(char4*)(out_hi + rbase + col) = make_char4(h0, h1, h2, h3);
        *(char4*)(out_lo + rbase + col) = make_char4(l0, l1, l2, l3);
    }
}

// ---------------- IMMA GEMM: out[M,N] = A[M,K] @ B[N,K]^T, s8 hi/lo fixed-point ----------------
// MODE 0: store fp32
// MODE 1: +bias +res, store fp32
// MODE 2: +bias, relu, quantize (fixed scale) -> s8 hi/lo
#define BKQ 64                    // K per stage (s8)
#define STAGE_BYTES 32768         // 4 tiles (Ahi,Alo,Bhi,Blo) x 8KB
#define NSTAGE 3
#define GEMM_SMEM (NSTAGE * STAGE_BYTES)
// tile = [128 rows][64 bytes]; 16B chunk c of row r stored at c ^ ((r + (r>>2)) & 3)

__device__ __forceinline__ uint32_t lm_addr(uint32_t base, int r, int cc) {
    return base + r * 64 + ((cc ^ ((r + (r >> 2)) & 3)) << 4);
}

__device__ __forceinline__ void tile_load(uint32_t sdst, const int8_t* __restrict__ gsrc,
                                          int ld, int tid) {
    int r = tid >> 2, c = tid & 3;
    uint32_t dst = sdst + r * 64 + ((c ^ ((r + (r >> 2)) & 3)) << 4);
    cpa16(dst, gsrc + (size_t)r * ld + c * 16);
}

template <int MODE>
__global__ __launch_bounds__(512, 1) void imma_gemm(
    const int8_t* __restrict__ Ahi, const int8_t* __restrict__ Alo,
    const int8_t* __restrict__ Bhi, const int8_t* __restrict__ Blo,
    const float* __restrict__ sA, float sAc,
    const float* __restrict__ sB,
    const float* __restrict__ bias, const float* __restrict__ res,
    float* __restrict__ outf, int8_t* __restrict__ qout_hi, int8_t* __restrict__ qout_lo,
    float qinv, int N, int K)
{
    extern __shared__ char smem[];
    const uint32_t sb = smem_u32(smem);
    const int tid  = threadIdx.x;
    const int lane = tid & 31;
    const int wid  = tid >> 5;
    const int wm   = wid >> 3;     // 0..1  (64 rows each)
    const int wn   = wid & 7;      // 0..7  (16 cols each)
    const int cb   = blockIdx.x * 128;
    const int rb   = blockIdx.y * 128;
    const int NC   = K / BKQ;

    const int8_t* Ahi_t = Ahi + (size_t)rb * K;
    const int8_t* Alo_t = Alo + (size_t)rb * K;
    const int8_t* Bhi_t = Bhi + (size_t)cb * K;
    const int8_t* Blo_t = Blo + (size_t)cb * K;

    int acc0[4][2][4], acc1[4][2][4];
#pragma unroll
    for (int i = 0; i < 4; i++)
#pragma unroll
        for (int j = 0; j < 2; j++)
#pragma unroll
            for (int q = 0; q < 4; q++) { acc0[i][j][q] = 0; acc1[i][j][q] = 0; }

    // ldmatrix lane geometry (x4: sel = lane>>3 picks matrix)
    const int arow_l = wm * 64 + (lane & 7) + (((lane >> 3) & 1) << 3);
    const int brow_l = wn * 16 + (lane & 7) + (((lane >> 3) & 1) << 3);
    const int ccadd  = lane >> 4;   // 0/1: second 16B chunk of the k32

#define ISSUE(cn, s) do {                                              \
        int _kc = (cn) * BKQ;                                          \
        uint32_t _st = sb + (s) * STAGE_BYTES;                         \
        tile_load(_st,         Ahi_t + _kc, K, tid);                   \
        tile_load(_st + 8192,  Alo_t + _kc, K, tid);                   \
        tile_load(_st + 16384, Bhi_t + _kc, K, tid);                   \
        tile_load(_st + 24576, Blo_t + _kc, K, tid);                   \
        CP_COMMIT();                                                   \
    } while (0)

    ISSUE(0, 0);
    ISSUE(1, 1);

    int s = 0, s2 = 2;
    for (int c = 0; c < NC; c++) {
        if (c + 1 < NC) CP_WAIT(1); else CP_WAIT(0);
        __syncthreads();
        if (c + 2 < NC) ISSUE(c + 2, s2);
        uint32_t st = sb + s * STAGE_BYTES;
#pragma unroll
        for (int kk = 0; kk < 2; kk++) {
            const int c0 = 2 * kk + ccadd;
            uint32_t av[4][4], bhv[4], blv[4];
            // A_hi fragments (4 m16 tiles)
#pragma unroll
            for (int mt = 0; mt < 4; mt++)
                ldsm_x4(lm_addr(st, arow_l + mt * 16, c0), av[mt]);
            // B_hi (both n8 tiles)
            ldsm_x4(lm_addr(st + 16384, brow_l, c0), bhv);
            uint32_t bh0[2] = { bhv[0], bhv[2] }, bh1[2] = { bhv[1], bhv[3] };
#pragma unroll
            for (int mt = 0; mt < 4; mt++) {
                imma(acc0[mt][0], av[mt], bh0);
                imma(acc0[mt][1], av[mt], bh1);
            }
            // B_lo
            ldsm_x4(lm_addr(st + 24576, brow_l, c0), blv);
            uint32_t bl0[2] = { blv[0], blv[2] }, bl1[2] = { blv[1], blv[3] };
#pragma unroll
            for (int mt = 0; mt < 4; mt++) {
                imma(acc1[mt][0], av[mt], bl0);
                imma(acc1[mt][1], av[mt], bl1);
            }
            // A_lo overwrites A_hi
#pragma unroll
            for (int mt = 0; mt < 4; mt++)
                ldsm_x4(lm_addr(st + 8192, arow_l + mt * 16, c0), av[mt]);
#pragma unroll
            for (int mt = 0; mt < 4; mt++) {
                imma(acc1[mt][0], av[mt], bh0);
                imma(acc1[mt][1], av[mt], bh1);
            }
        }
        s  = (s == 2)  ? 0 : s + 1;
        s2 = (s2 == 2) ? 0 : s2 + 1;
    }
#undef ISSUE

    // epilogue: dequant = sa*sb*(65536*acc0 + 256*acc1)
    const int g  = lane >> 2;
    const int tq = lane & 3;
#pragma unroll
    for (int mt = 0; mt < 4; mt++) {
        int r0 = rb + wm * 64 + mt * 16 + g;
        float sa0 = sA ? sA[r0] : sAc;
        float sa1 = sA ? sA[r0 + 8] : sAc;
#pragma unroll
        for (int nt = 0; nt < 2; nt++) {
            int col = cb + wn * 16 + nt * 8 + tq * 2;
            float sb0 = sB[col], sb1 = sB[col + 1];
            float f0 = fmaf(65536.f, (float)acc0[mt][nt][0], 256.f * (float)acc1[mt][nt][0]);
            float f1 = fmaf(65536.f, (float)acc0[mt][nt][1], 256.f * (float)acc1[mt][nt][1]);
            float f2 = fmaf(65536.f, (float)acc0[mt][nt][2], 256.f * (float)acc1[mt][nt][2]);
            float f3 = fmaf(65536.f, (float)acc0[mt][nt][3], 256.f * (float)acc1[mt][nt][3]);
            float d0 = sa0 * sb0 * f0, d1 = sa0 * sb1 * f1;
            float d2 = sa1 * sb0 * f2, d3 = sa1 * sb1 * f3;
            if (MODE >= 1) {
                float2 bb = *(const float2*)(bias + col);
                d0 += bb.x; d1 += bb.y; d2 += bb.x; d3 += bb.y;
            }
            if (MODE == 1) {
                float2 ra  = *(const float2*)(res + (size_t)r0 * N + col);
                float2 rbv = *(const float2*)(res + (size_t)(r0 + 8) * N + col);
                d0 += ra.x; d1 += ra.y; d2 += rbv.x; d3 += rbv.y;
            }
            if (MODE == 2) {
                d0 = fmaxf(d0, 0.f); d1 = fmaxf(d1, 0.f);
                d2 = fmaxf(d2, 0.f); d3 = fmaxf(d3, 0.f);
                int8_t h0, l0, h1, l1;
                qsplit(d0, qinv, h0, l0); qsplit(d1, qinv, h1, l1);
                *(char2*)(qout_hi + (size_t)r0 * N + col) = make_char2(h0, h1);
                *(char2*)(qout_lo + (size_t)r0 * N + col) = make_char2(l0, l1);
                qsplit(d2, qinv, h0, l0); qsplit(d3, qinv, h1, l1);
                *(char2*)(qout_hi + (size_t)(r0 + 8) * N + col) = make_char2(h0, h1);
                *(char2*)(qout_lo + (size_t)(r0 + 8) * N + col) = make_char2(l0, l1);
            } else {
                *(float2*)(outf + (size_t)r0 * N + col)       = make_float2(d0, d1);
                *(float2*)(outf + (size_t)(r0 + 8) * N + col) = make_float2(d2, d3);
            }
        }
    }
}

// ---------------- attention: one CTA per (batch, head), fp32 compute, s8 fixed-scale out ----------------
__global__ __launch_bounds__(128) void attn_kernel(const float* __restrict__ qkv,
                                                   int8_t* __restrict__ out_hi,
                                                   int8_t* __restrict__ out_lo) {
    extern __shared__ float sm[];
    float* qs = sm;                   // [64][48]
    float* ks = qs + 64 * 48;
    float* vs = ks + 64 * 48;
    float* ws = vs + 64 * 48;         // [64][64]

    const int bh = blockIdx.x;
    const int b  = bh >> 3;
    const int h  = bh & 7;
    const int tid = threadIdx.x;
    const size_t base = (size_t)b * TT * QKVN + (size_t)h * HD;

    for (int idx = tid; idx < 64 * 12; idx += 128) {
        int t  = idx / 12;
        int c4 = (idx % 12) * 4;
        const float* p = qkv + base + (size_t)t * QKVN + c4;
        *(float4*)&qs[t * 48 + c4] = *(const float4*)p;
        *(float4*)&ks[t * 48 + c4] = *(const float4*)(p + C);
        *(float4*)&vs[t * 48 + c4] = *(const float4*)(p + 2 * C);
    }
    __syncthreads();

    const float scale = 2.449489742783178f;  // 48 * 384^-0.5

    for (int idx = tid; idx < 64 * 64; idx += 128) {
        int i = idx >> 6, j = idx & 63;
        if (j > i) continue;
        float sx = 0.f, sy = 0.f, sz = 0.f, sw = 0.f;
#pragma unroll
        for (int d4 = 0; d4 < 12; d4++) {
            float4 qv = *(const float4*)&qs[i * 48 + d4 * 4];
            float4 kv = *(const float4*)&ks[j * 48 + d4 * 4];
            sx += qv.x * kv.x; sy += qv.y * kv.y;
            sz += qv.z * kv.z; sw += qv.w * kv.w;
        }
        ws[i * 64 + j] = (sx + sy + sz + sw) * scale;
    }
    __syncthreads();

    if (tid < 64) {
        int i = tid;
        float m = -1e30f;
        for (int j = 0; j <= i; j++) m = fmaxf(m, ws[i * 64 + j]);
        float s = 0.f;
        for (int j = 0; j <= i; j++) {
            float e = expf(ws[i * 64 + j] - m);
            ws[i * 64 + j] = e;
            s += e;
        }
        float inv = 1.f / s;
        for (int j = 0; j <= i; j++) ws[i * 64 + j] *= inv;
    }
    __syncthreads();

    const float qinv = QF / S_ATT;
    for (int idx = tid; idx < 64 * 12; idx += 128) {
        int i  = idx / 12;
        int d4 = (idx % 12) * 4;
        float ax = 0.f, ay = 0.f, az = 0.f, aw = 0.f;
        for (int j = 0; j <= i; j++) {
            float w = ws[i * 64 + j];
            float4 vv = *(const float4*)&vs[j * 48 + d4];
            ax += w * vv.x; ay += w * vv.y; az += w * vv.z; aw += w * vv.w;
        }
        size_t o = (size_t)(b * TT + i) * C + h * HD + d4;
        int8_t h0, l0, h1, l1, h2, l2, h3, l3;
        qsplit(ax, qinv, h0, l0); qsplit(ay, qinv, h1, l1);
        qsplit(az, qinv, h2, l2); qsplit(aw, qinv, h3, l3);
        *(char4*)(out_hi + o) = make_char4(h0, h1, h2, h3);
        *(char4*)(out_lo + o) = make_char4(l0, l1, l2, l3);
    }
}

// ---------------- launch ----------------
extern "C" void kernel_launch(void* const* d_in, const int* in_sizes, int n_in,
                              void* d_out, int out_size) {
    const float* x     = (const float*)d_in[0];
    const float* ln1_g = (const float*)d_in[1];
    const float* ln1_b = (const float*)d_in[2];
    const float* ln2_g = (const float*)d_in[3];
    const float* ln2_b = (const float*)d_in[4];
    const float* Wq    = (const float*)d_in[5];
    const float* Wk    = (const float*)d_in[6];
    const float* Wv    = (const float*)d_in[7];
    const float* Wp    = (const float*)d_in[8];
    const float* bp    = (const float*)d_in[9];
    const float* W1    = (const float*)d_in[10];
    const float* b1    = (const float*)d_in[11];
    const float* W2    = (const float*)d_in[12];
    const float* b2    = (const float*)d_in[13];
    float* out = (float*)d_out;

    int8_t *ph_hi, *ph_lo, *pattn_hi, *pattn_lo, *phid_hi, *phid_lo;
    int8_t *pwqkv_hi, *pwqkv_lo, *pwp_hi, *pwp_lo, *pw1_hi, *pw1_lo, *pw2_hi, *pw2_lo;
    float *pqkv, *px2, *psa, *psb_qkv, *psb_p, *psb_1, *psb_2;
    cudaGetSymbolAddress((void**)&ph_hi, g_h_hi);       cudaGetSymbolAddress((void**)&ph_lo, g_h_lo);
    cudaGetSymbolAddress((void**)&psa, g_sa_ln);
    cudaGetSymbolAddress((void**)&pqkv, g_qkv);
    cudaGetSymbolAddress((void**)&pattn_hi, g_attn_hi); cudaGetSymbolAddress((void**)&pattn_lo, g_attn_lo);
    cudaGetSymbolAddress((void**)&px2, g_x2);
    cudaGetSymbolAddress((void**)&phid_hi, g_hid_hi);   cudaGetSymbolAddress((void**)&phid_lo, g_hid_lo);
    cudaGetSymbolAddress((void**)&pwqkv_hi, g_wqkv_hi); cudaGetSymbolAddress((void**)&pwqkv_lo, g_wqkv_lo);
    cudaGetSymbolAddress((void**)&psb_qkv, g_sb_qkv);
    cudaGetSymbolAddress((void**)&pwp_hi, g_wp_hi);     cudaGetSymbolAddress((void**)&pwp_lo, g_wp_lo);
    cudaGetSymbolAddress((void**)&psb_p, g_sb_p);
    cudaGetSymbolAddress((void**)&pw1_hi, g_w1_hi);     cudaGetSymbolAddress((void**)&pw1_lo, g_w1_lo);
    cudaGetSymbolAddress((void**)&psb_1, g_sb_1);
    cudaGetSymbolAddress((void**)&pw2_hi, g_w2_hi);     cudaGetSymbolAddress((void**)&pw2_lo, g_w2_lo);
    cudaGetSymbolAddress((void**)&psb_2, g_sb_2);

    static int attr_set = 0;
    const int attn_smem = (3 * 64 * 48 + 64 * 64) * (int)sizeof(float);
    if (!attr_set) {
        cudaFuncSetAttribute(attn_kernel, cudaFuncAttributeMaxDynamicSharedMemorySize, attn_smem);
        cudaFuncSetAttribute(imma_gemm<0>, cudaFuncAttributeMaxDynamicSharedMemorySize, GEMM_SMEM);
        cudaFuncSetAttribute(imma_gemm<1>, cudaFuncAttributeMaxDynamicSharedMemorySize, GEMM_SMEM);
        cudaFuncSetAttribute(imma_gemm<2>, cudaFuncAttributeMaxDynamicSharedMemorySize, GEMM_SMEM);
        attr_set = 1;
    }

    // weight prep (quantize + transpose to [N,K] s8 hi/lo, per-row scale)
    prep_qkv_q<<<QKVN / 8, 256>>>(Wq, Wk, Wv, pwqkv_hi, pwqkv_lo, psb_qkv);
    prep_w_q<<<C / 8, 256>>>(Wp, pwp_hi, pwp_lo, psb_p, C, C);
    prep_w_q<<<C4 / 8, 256>>>(W1, pw1_hi, pw1_lo, psb_1, C, C4);
    prep_w_q<<<C / 8, 256>>>(W2, pw2_hi, pw2_lo, psb_2, C4, C);

    const float sa_att = S_ATT / QF;
    const float sa_hid = S_HID / QF;

    // LN1 -> s8 + row scale
    ln_q_kernel<<<BT / 8, dim3(32, 8)>>>(x, ln1_g, ln1_b, ph_hi, ph_lo, psa);
    // QKV: [BT,384] x [1152,384]^T -> fp32
    imma_gemm<0><<<dim3(QKVN / 128, BT / 128), 512, GEMM_SMEM>>>(
        ph_hi, ph_lo, pwqkv_hi, pwqkv_lo, psa, 0.f, psb_qkv,
        nullptr, nullptr, pqkv, nullptr, nullptr, 0.f, QKVN, C);
    // attention -> s8 fixed scale
    attn_kernel<<<BATCH * NH, 128, attn_smem>>>(pqkv, pattn_hi, pattn_lo);
    // proj + bias + residual -> fp32 x2
    imma_gemm<1><<<dim3(C / 128, BT / 128), 512, GEMM_SMEM>>>(
        pattn_hi, pattn_lo, pwp_hi, pwp_lo, nullptr, sa_att, psb_p,
        bp, x, px2, nullptr, nullptr, 0.f, C, C);
    // LN2 -> s8 + row scale
    ln_q_kernel<<<BT / 8, dim3(32, 8)>>>(px2, ln2_g, ln2_b, ph_hi, ph_lo, psa);
    // FFN1 + bias + relu -> s8 hidden (fixed scale)
    imma_gemm<2><<<dim3(C4 / 128, BT / 128), 512, GEMM_SMEM>>>(
        ph_hi, ph_lo, pw1_hi, pw1_lo, psa, 0.f, psb_1,
        b1, nullptr, nullptr, phid_hi, phid_lo, QF / S_HID, C4, C);
    // FFN2 + bias + residual -> out
    imma_gemm<1><<<dim3(C / 128, BT / 128), 512, GEMM_SMEM>>>(
        phid_hi, phid_lo, pw2_hi, pw2_lo, nullptr, sa_hid, psb_2,
        b2, px2, out, nullptr, nullptr, 0.f, C, C4);
}

// round 6
// speedup vs baseline: 2.9239x; 2.9239x over previous
#include <cuda_runtime.h>
#include <cuda_fp16.h>
#include <math.h>
#include <stdint.h>

// ---------------- problem constants ----------------
#define BATCH   2048
#define TT      64
#define BT      (BATCH * TT)      // 131072 rows
#define C       384
#define NH      8
#define HD      48
#define C4      1536
#define QKVN    1152

typedef __half f16;

// ---------------- device scratch ----------------
__device__ __align__(256) f16   g_h_hi[BT * C],   g_h_lo[BT * C];
__device__ __align__(256) float g_qkv[BT * QKVN];
__device__ __align__(256) f16   g_attn_hi[BT * C], g_attn_lo[BT * C];
__device__ __align__(256) float g_x2[BT * C];
__device__ __align__(256) f16   g_hid_hi[BT * C4], g_hid_lo[BT * C4];
__device__ __align__(256) f16   g_wqkv_hi[QKVN * C], g_wqkv_lo[QKVN * C];
__device__ __align__(256) f16   g_wp_hi[C * C],      g_wp_lo[C * C];
__device__ __align__(256) f16   g_w1_hi[C4 * C],     g_w1_lo[C4 * C];
__device__ __align__(256) f16   g_w2_hi[C * C4],     g_w2_lo[C * C4];

// ---------------- PTX helpers (base-arch only) ----------------
__device__ __forceinline__ uint32_t smem_u32(const void* p) {
    uint32_t a;
    asm("{ .reg .u64 t; cvta.to.shared.u64 t, %1; cvt.u32.u64 %0, t; }" : "=r"(a) : "l"(p));
    return a;
}
__device__ __forceinline__ void cpa16(uint32_t dst, const void* src) {
    asm volatile("cp.async.cg.shared.global [%0], [%1], 16;" :: "r"(dst), "l"(src));
}
#define CP_COMMIT() asm volatile("cp.async.commit_group;" ::: "memory")
#define CP_WAIT(n)  asm volatile("cp.async.wait_group %0;" :: "n"(n) : "memory")

__device__ __forceinline__ void ldsm_x4(uint32_t a, uint32_t* r) {
    asm volatile("ldmatrix.sync.aligned.m8n8.x4.shared.b16 {%0,%1,%2,%3}, [%4];"
                 : "=r"(r[0]), "=r"(r[1]), "=r"(r[2]), "=r"(r[3]) : "r"(a));
}
__device__ __forceinline__ void mma_16816(float* d, const uint32_t* a, const uint32_t* b) {
    asm volatile("mma.sync.aligned.m16n8k16.row.col.f32.f16.f16.f32 "
                 "{%0,%1,%2,%3}, {%4,%5,%6,%7}, {%8,%9}, {%0,%1,%2,%3};"
                 : "+f"(d[0]), "+f"(d[1]), "+f"(d[2]), "+f"(d[3])
                 : "r"(a[0]), "r"(a[1]), "r"(a[2]), "r"(a[3]), "r"(b[0]), "r"(b[1]));
}

// ---------------- fp16 hi/lo split ----------------
__device__ __forceinline__ void split_h(float v, f16& h, f16& l) {
    h = __float2half_rn(v);
    l = __float2half_rn(v - __half2float(h));
}

// ---------------- weight prep ----------------
__global__ void prep_qkv_kernel(const float* __restrict__ Wq, const float* __restrict__ Wk,
                                const float* __restrict__ Wv,
                                f16* __restrict__ hi, f16* __restrict__ lo) {
    int idx = blockIdx.x * blockDim.x + threadIdx.x;
    if (idx >= QKVN * C) return;
    int n = idx / C, k = idx % C;
    int m = n / C, hd = n % C;
    int h = hd / HD, d = hd % HD;
    const float* W = (m == 0) ? Wq : ((m == 1) ? Wk : Wv);
    split_h(W[(size_t)h * C * HD + (size_t)k * HD + d], hi[idx], lo[idx]);
}

__global__ void prep_t_kernel(const float* __restrict__ src, f16* __restrict__ hi,
                              f16* __restrict__ lo, int K, int N) {
    int idx = blockIdx.x * blockDim.x + threadIdx.x;
    if (idx >= K * N) return;
    int k = idx / N, n = idx % N;
    split_h(src[idx], hi[(size_t)n * K + k], lo[(size_t)n * K + k]);
}

// ---------------- layernorm: one warp per row, outputs hi/lo fp16 ----------------
__global__ void ln_kernel(const float* __restrict__ x, const float* __restrict__ g,
                          const float* __restrict__ b,
                          f16* __restrict__ out_hi, f16* __restrict__ out_lo) {
    int row  = blockIdx.x * blockDim.y + threadIdx.y;
    int lane = threadIdx.x;
    const float* xr = x + (size_t)row * C;
    float4 v[3];
    float sum = 0.f, sq = 0.f;
#pragma unroll
    for (int i = 0; i < 3; i++) {
        v[i] = *(const float4*)(xr + i * 128 + lane * 4);
        sum += v[i].x + v[i].y + v[i].z + v[i].w;
        sq  += v[i].x * v[i].x + v[i].y * v[i].y + v[i].z * v[i].z + v[i].w * v[i].w;
    }
#pragma unroll
    for (int o = 16; o; o >>= 1) {
        sum += __shfl_xor_sync(0xffffffffu, sum, o);
        sq  += __shfl_xor_sync(0xffffffffu, sq, o);
    }
    float mean = sum * (1.0f / C);
    float var  = sq * (1.0f / C) - mean * mean;
    float rstd = rsqrtf(var + 1e-5f);
    size_t rbase = (size_t)row * C;
#pragma unroll
    for (int i = 0; i < 3; i++) {
        int col = i * 128 + lane * 4;
        float4 gg = *(const float4*)(g + col);
        float4 bb = *(const float4*)(b + col);
        float o0 = (v[i].x - mean) * rstd * gg.x + bb.x;
        float o1 = (v[i].y - mean) * rstd * gg.y + bb.y;
        float o2 = (v[i].z - mean) * rstd * gg.z + bb.z;
        float o3 = (v[i].w - mean) * rstd * gg.w + bb.w;
        f16 h0, l0, h1, l1, h2, l2, h3, l3;
        split_h(o0, h0, l0); split_h(o1, h1, l1);
        split_h(o2, h2, l2); split_h(o3, h3, l3);
        __half2 hA = __halves2half2(h0, h1), hB = __halves2half2(h2, h3);
        __half2 lA = __halves2half2(l0, l1), lB = __halves2half2(l2, l3);
        *(__half2*)(out_hi + rbase + col)     = hA;
        *(__half2*)(out_hi + rbase + col + 2) = hB;
        *(__half2*)(out_lo + rbase + col)     = lA;
        *(__half2*)(out_lo + rbase + col + 2) = lB;
    }
}

// ---------------- HMMA GEMM: out[M,N] = A[M,K] @ B[N,K]^T, fp16 hi/lo split ----------------
// Per-CTA term count: 3 terms (hi*hi + hi*lo + lo*hi) when cb < n3, else
// 2 terms (hi*hi + hi*lo) — the lo_A tile is then neither loaded nor used.
// MODE 0: store fp32 | MODE 1: +bias +res, fp32 | MODE 2: +bias, relu, fp16 split
#define BMT 128
#define BNT 128
#define BKT 32
#define STAGE_BYTES 32768
#define NSTAGE 3
#define GEMM_SMEM (NSTAGE * STAGE_BYTES)
// stage: Ahi @0, Alo @8192, Bhi @16384, Blo @24576; row = 64B (32 f16)
// 16B-chunk swizzle: chunk c of row r at c ^ ((r>>1)&3)

__device__ __forceinline__ void tile_load(uint32_t sdst, const f16* __restrict__ g,
                                          int ld, int tid) {
#pragma unroll
    for (int i = 0; i < 2; i++) {
        int id = tid + i * 256;
        int r = id >> 2, c = id & 3;
        uint32_t dst = sdst + r * 64 + ((c ^ ((r >> 1) & 3)) << 4);
        cpa16(dst, g + (size_t)r * ld + c * 8);
    }
}

__device__ __forceinline__ void compute_stage(uint32_t st, int arow, int a_kc,
                                              int bn, int b_kc, bool three,
                                              float (&acc)[4][4][4]) {
#pragma unroll
    for (int ks = 0; ks < 2; ks++) {
        const int akc = ks * 2 + a_kc;
        const int bkc = ks * 2 + b_kc;
        uint32_t a[4][4], bh[2][4], bl[2][4];
        // A_hi
#pragma unroll
        for (int ma = 0; ma < 4; ma++) {
            int r = arow + ma * 16;
            ldsm_x4(st + r * 64 + ((akc ^ ((r >> 1) & 3)) << 4), a[ma]);
        }
        // B_hi
#pragma unroll
        for (int p = 0; p < 2; p++) {
            int n = bn + p * 16;
            ldsm_x4(st + 16384 + n * 64 + ((bkc ^ ((n >> 1) & 3)) << 4), bh[p]);
        }
#pragma unroll
        for (int ma = 0; ma < 4; ma++)
#pragma unroll
            for (int na = 0; na < 4; na++)
                mma_16816(acc[ma][na], a[ma], &bh[na >> 1][(na & 1) * 2]);
        // B_lo
#pragma unroll
        for (int p = 0; p < 2; p++) {
            int n = bn + p * 16;
            ldsm_x4(st + 24576 + n * 64 + ((bkc ^ ((n >> 1) & 3)) << 4), bl[p]);
        }
#pragma unroll
        for (int ma = 0; ma < 4; ma++)
#pragma unroll
            for (int na = 0; na < 4; na++)
                mma_16816(acc[ma][na], a[ma], &bl[na >> 1][(na & 1) * 2]);
        if (three) {
            // A_lo overwrites A_hi
#pragma unroll
            for (int ma = 0; ma < 4; ma++) {
                int r = arow + ma * 16;
                ldsm_x4(st + 8192 + r * 64 + ((akc ^ ((r >> 1) & 3)) << 4), a[ma]);
            }
#pragma unroll
            for (int ma = 0; ma < 4; ma++)
#pragma unroll
                for (int na = 0; na < 4; na++)
                    mma_16816(acc[ma][na], a[ma], &bh[na >> 1][(na & 1) * 2]);
        }
    }
}

template <int MODE>
__global__ __launch_bounds__(256, 2) void mma_gemm(
    const f16* __restrict__ Ahi, const f16* __restrict__ Alo,
    const f16* __restrict__ Bhi, const f16* __restrict__ Blo,
    const float* __restrict__ bias, const float* __restrict__ res,
    float* __restrict__ outf, f16* __restrict__ out_hi, f16* __restrict__ out_lo,
    int N, int K, int n3)
{
    extern __shared__ char smem[];
    const uint32_t sb = smem_u32(smem);
    const int tid  = threadIdx.x;
    const int lane = tid & 31;
    const int wid  = tid >> 5;
    const int wm   = wid >> 2;     // 0..1
    const int wn   = wid & 3;      // 0..3
    const int cb   = blockIdx.x * BNT;
    const int rb   = blockIdx.y * BMT;
    const int NC   = K / BKT;
    const bool three = (cb < n3);

    const f16* Ahi_t = Ahi + (size_t)rb * K;
    const f16* Alo_t = Alo + (size_t)rb * K;
    const f16* Bhi_t = Bhi + (size_t)cb * K;
    const f16* Blo_t = Blo + (size_t)cb * K;

    float acc[4][4][4];
#pragma unroll
    for (int i = 0; i < 4; i++)
#pragma unroll
        for (int j = 0; j < 4; j++)
#pragma unroll
            for (int q = 0; q < 4; q++) acc[i][j][q] = 0.f;

    const int arow = wm * 64 + (lane & 15);
    const int a_kc = lane >> 4;
    const int bn   = wn * 32 + ((lane >> 4) << 3) + (lane & 7);
    const int b_kc = (lane >> 3) & 1;

#define ISSUE(cn, s) do {                                              \
        int _kc = (cn) * BKT;                                          \
        uint32_t _st = sb + (s) * STAGE_BYTES;                         \
        tile_load(_st,         Ahi_t + _kc, K, tid);                   \
        if (three) tile_load(_st + 8192, Alo_t + _kc, K, tid);         \
        tile_load(_st + 16384, Bhi_t + _kc, K, tid);                   \
        tile_load(_st + 24576, Blo_t + _kc, K, tid);                   \
        CP_COMMIT();                                                   \
    } while (0)

    ISSUE(0, 0);
    ISSUE(1, 1);

    int s = 0, s2 = 2;
    for (int c = 0; c < NC; c++) {
        if (c + 1 < NC) CP_WAIT(1); else CP_WAIT(0);
        __syncthreads();
        if (c + 2 < NC) ISSUE(c + 2, s2);
        compute_stage(sb + s * STAGE_BYTES, arow, a_kc, bn, b_kc, three, acc);
        s  = (s == 2)  ? 0 : s + 1;
        s2 = (s2 == 2) ? 0 : s2 + 1;
    }
#undef ISSUE

    // epilogue
    const int g  = lane >> 2;
    const int tg = lane & 3;
#pragma unroll
    for (int ma = 0; ma < 4; ma++) {
        int r0 = rb + wm * 64 + ma * 16 + g;
#pragma unroll
        for (int na = 0; na < 4; na++) {
            int col = cb + wn * 32 + na * 8 + tg * 2;
            float d0 = acc[ma][na][0], d1 = acc[ma][na][1];
            float d2 = acc[ma][na][2], d3 = acc[ma][na][3];
            if (MODE >= 1) {
                float2 bb = *(const float2*)(bias + col);
                d0 += bb.x; d1 += bb.y; d2 += bb.x; d3 += bb.y;
            }
            if (MODE == 1) {
                float2 ra  = *(const float2*)(res + (size_t)r0 * N + col);
                float2 rbv = *(const float2*)(res + (size_t)(r0 + 8) * N + col);
                d0 += ra.x; d1 += ra.y; d2 += rbv.x; d3 += rbv.y;
            }
            if (MODE == 2) {
                d0 = fmaxf(d0, 0.f); d1 = fmaxf(d1, 0.f);
                d2 = fmaxf(d2, 0.f); d3 = fmaxf(d3, 0.f);
                f16 h0, l0, h1, l1;
                split_h(d0, h0, l0); split_h(d1, h1, l1);
                *(__half2*)(out_hi + (size_t)r0 * N + col) = __halves2half2(h0, h1);
                *(__half2*)(out_lo + (size_t)r0 * N + col) = __halves2half2(l0, l1);
                split_h(d2, h0, l0); split_h(d3, h1, l1);
                *(__half2*)(out_hi + (size_t)(r0 + 8) * N + col) = __halves2half2(h0, h1);
                *(__half2*)(out_lo + (size_t)(r0 + 8) * N + col) = __halves2half2(l0, l1);
            } else {
                *(float2*)(outf + (size_t)r0 * N + col)       = make_float2(d0, d1);
                *(float2*)(outf + (size_t)(r0 + 8) * N + col) = make_float2(d2, d3);
            }
        }
    }
}

// ---------------- attention: one CTA per (batch, head), fp32, fp16-split output ----------------
__global__ __launch_bounds__(128) void attn_kernel(const float* __restrict__ qkv,
                                                   f16* __restrict__ out_hi,
                                                   f16* __restrict__ out_lo) {
    extern __shared__ float sm[];
    float* qs = sm;                   // [64][48]
    float* ks = qs + 64 * 48;
    float* vs = ks + 64 * 48;
    float* ws = vs + 64 * 48;         // [64][64]

    const int bh = blockIdx.x;
    const int b  = bh >> 3;
    const int h  = bh & 7;
    const int tid = threadIdx.x;
    const size_t base = (size_t)b * TT * QKVN + (size_t)h * HD;

    for (int idx = tid; idx < 64 * 12; idx += 128) {
        int t  = idx / 12;
        int c4 = (idx % 12) * 4;
        const float* p = qkv + base + (size_t)t * QKVN + c4;
        *(float4*)&qs[t * 48 + c4] = *(const float4*)p;
        *(float4*)&ks[t * 48 + c4] = *(const float4*)(p + C);
        *(float4*)&vs[t * 48 + c4] = *(const float4*)(p + 2 * C);
    }
    __syncthreads();

    const float scale = 2.449489742783178f;  // 48 * 384^-0.5

    for (int idx = tid; idx < 64 * 64; idx += 128) {
        int i = idx >> 6, j = idx & 63;
        if (j > i) continue;
        float sx = 0.f, sy = 0.f, sz = 0.f, sw = 0.f;
#pragma unroll
        for (int d4 = 0; d4 < 12; d4++) {
            float4 qv = *(const float4*)&qs[i * 48 + d4 * 4];
            float4 kv = *(const float4*)&ks[j * 48 + d4 * 4];
            sx += qv.x * kv.x; sy += qv.y * kv.y;
            sz += qv.z * kv.z; sw += qv.w * kv.w;
        }
        ws[i * 64 + j] = (sx + sy + sz + sw) * scale;
    }
    __syncthreads();

    if (tid < 64) {
        int i = tid;
        float m = -1e30f;
        for (int j = 0; j <= i; j++) m = fmaxf(m, ws[i * 64 + j]);
        float s = 0.f;
        for (int j = 0; j <= i; j++) {
            float e = expf(ws[i * 64 + j] - m);
            ws[i * 64 + j] = e;
            s += e;
        }
        float inv = 1.f / s;
        for (int j = 0; j <= i; j++) ws[i * 64 + j] *= inv;
    }
    __syncthreads();

    for (int idx = tid; idx < 64 * 12; idx += 128) {
        int i  = idx / 12;
        int d4 = (idx % 12) * 4;
        float ax = 0.f, ay = 0.f, az = 0.f, aw = 0.f;
        for (int j = 0; j <= i; j++) {
            float w = ws[i * 64 + j];
            float4 vv = *(const float4*)&vs[j * 48 + d4];
            ax += w * vv.x; ay += w * vv.y; az += w * vv.z; aw += w * vv.w;
        }
        size_t o = (size_t)(b * TT + i) * C + h * HD + d4;
        f16 h0, l0, h1, l1, h2, l2, h3, l3;
        split_h(ax, h0, l0); split_h(ay, h1, l1);
        split_h(az, h2, l2); split_h(aw, h3, l3);
        *(__half2*)(out_hi + o)     = __halves2half2(h0, h1);
        *(__half2*)(out_hi + o + 2) = __halves2half2(h2, h3);
        *(__half2*)(out_lo + o)     = __halves2half2(l0, l1);
        *(__half2*)(out_lo + o + 2) = __halves2half2(l2, l3);
    }
}

// ---------------- launch ----------------
extern "C" void kernel_launch(void* const* d_in, const int* in_sizes, int n_in,
                              void* d_out, int out_size) {
    const float* x     = (const float*)d_in[0];
    const float* ln1_g = (const float*)d_in[1];
    const float* ln1_b = (const float*)d_in[2];
    const float* ln2_g = (const float*)d_in[3];
    const float* ln2_b = (const float*)d_in[4];
    const float* Wq    = (const float*)d_in[5];
    const float* Wk    = (const float*)d_in[6];
    const float* Wv    = (const float*)d_in[7];
    const float* Wp    = (const float*)d_in[8];
    const float* bp    = (const float*)d_in[9];
    const float* W1    = (const float*)d_in[10];
    const float* b1    = (const float*)d_in[11];
    const float* W2    = (const float*)d_in[12];
    const float* b2    = (const float*)d_in[13];
    float* out = (float*)d_out;

    f16 *ph_hi, *ph_lo, *pattn_hi, *pattn_lo, *phid_hi, *phid_lo;
    f16 *pwqkv_hi, *pwqkv_lo, *pwp_hi, *pwp_lo, *pw1_hi, *pw1_lo, *pw2_hi, *pw2_lo;
    float *pqkv, *px2;
    cudaGetSymbolAddress((void**)&ph_hi, g_h_hi);     cudaGetSymbolAddress((void**)&ph_lo, g_h_lo);
    cudaGetSymbolAddress((void**)&pqkv, g_qkv);
    cudaGetSymbolAddress((void**)&pattn_hi, g_attn_hi); cudaGetSymbolAddress((void**)&pattn_lo, g_attn_lo);
    cudaGetSymbolAddress((void**)&px2, g_x2);
    cudaGetSymbolAddress((void**)&phid_hi, g_hid_hi); cudaGetSymbolAddress((void**)&phid_lo, g_hid_lo);
    cudaGetSymbolAddress((void**)&pwqkv_hi, g_wqkv_hi); cudaGetSymbolAddress((void**)&pwqkv_lo, g_wqkv_lo);
    cudaGetSymbolAddress((void**)&pwp_hi, g_wp_hi);   cudaGetSymbolAddress((void**)&pwp_lo, g_wp_lo);
    cudaGetSymbolAddress((void**)&pw1_hi, g_w1_hi);   cudaGetSymbolAddress((void**)&pw1_lo, g_w1_lo);
    cudaGetSymbolAddress((void**)&pw2_hi, g_w2_hi);   cudaGetSymbolAddress((void**)&pw2_lo, g_w2_lo);

    static int attr_set = 0;
    const int attn_smem = (3 * 64 * 48 + 64 * 64) * (int)sizeof(float);
    if (!attr_set) {
        cudaFuncSetAttribute(attn_kernel, cudaFuncAttributeMaxDynamicSharedMemorySize, attn_smem);
        cudaFuncSetAttribute(mma_gemm<0>, cudaFuncAttributeMaxDynamicSharedMemorySize, GEMM_SMEM);
        cudaFuncSetAttribute(mma_gemm<1>, cudaFuncAttributeMaxDynamicSharedMemorySize, GEMM_SMEM);
        cudaFuncSetAttribute(mma_gemm<2>, cudaFuncAttributeMaxDynamicSharedMemorySize, GEMM_SMEM);
        attr_set = 1;
    }

    // weight prep (split + transpose to [N,K])
    prep_qkv_kernel<<<(QKVN * C + 255) / 256, 256>>>(Wq, Wk, Wv, pwqkv_hi, pwqkv_lo);
    prep_t_kernel<<<(C * C + 255) / 256, 256>>>(Wp, pwp_hi, pwp_lo, C, C);
    prep_t_kernel<<<(C * C4 + 255) / 256, 256>>>(W1, pw1_hi, pw1_lo, C, C4);
    prep_t_kernel<<<(C4 * C + 255) / 256, 256>>>(W2, pw2_hi, pw2_lo, C4, C);

    // LN1
    ln_kernel<<<BT / 8, dim3(32, 8)>>>(x, ln1_g, ln1_b, ph_hi, ph_lo);
    // QKV: q,k columns (0..767) 3-term; v columns 2-term
    mma_gemm<0><<<dim3(QKVN / 128, BT / 128), 256, GEMM_SMEM>>>(
        ph_hi, ph_lo, pwqkv_hi, pwqkv_lo, nullptr, nullptr, pqkv, nullptr, nullptr,
        QKVN, C, 2 * C);
    // attention
    attn_kernel<<<BATCH * NH, 128, attn_smem>>>(pqkv, pattn_hi, pattn_lo);
    // proj + bias + residual -> x2 (2-term)
    mma_gemm<1><<<dim3(C / 128, BT / 128), 256, GEMM_SMEM>>>(
        pattn_hi, pattn_lo, pwp_hi, pwp_lo, bp, x, px2, nullptr, nullptr, C, C, 0);
    // LN2
    ln_kernel<<<BT / 8, dim3(32, 8)>>>(px2, ln2_g, ln2_b, ph_hi, ph_lo);
    // FFN1 + bias + relu -> hidden (2-term)
    mma_gemm<2><<<dim3(C4 / 128, BT / 128), 256, GEMM_SMEM>>>(
        ph_hi, ph_lo, pw1_hi, pw1_lo, b1, nullptr, nullptr, phid_hi, phid_lo, C4, C, 0);
    // FFN2 + bias + residual -> out (2-term)
    mma_gemm<1><<<dim3(C / 128, BT / 128), 256, GEMM_SMEM>>>(
        phid_hi, phid_lo, pw2_hi, pw2_lo, b2, px2, out, nullptr, nullptr, C, C4, 0);
}

// round 7
// speedup vs baseline: 3.7117x; 1.2694x over previous
#include <cuda_runtime.h>
#include <cuda_fp16.h>
#include <math.h>
#include <stdint.h>

// ---------------- problem constants ----------------
#define BATCH   2048
#define TT      64
#define BT      (BATCH * TT)      // 131072 rows
#define C       384
#define NH      8
#define HD      48
#define C4      1536
#define QKVN    1152

typedef __half f16;

// ---------------- device scratch ----------------
__device__ __align__(256) f16   g_h_hi[BT * C],   g_h_lo[BT * C];
__device__ __align__(256) float g_qkv[BT * QKVN];
__device__ __align__(256) f16   g_attn_hi[BT * C];
__device__ __align__(256) float g_x2[BT * C];
__device__ __align__(256) f16   g_hid_hi[BT * C4];
__device__ __align__(256) f16   g_wqkv_hi[QKVN * C], g_wqkv_lo[QKVN * C];
__device__ __align__(256) f16   g_wp_hi[C * C];
__device__ __align__(256) f16   g_w1_hi[C4 * C];
__device__ __align__(256) f16   g_w2_hi[C * C4];

// ---------------- PTX helpers (base-arch only) ----------------
__device__ __forceinline__ uint32_t smem_u32(const void* p) {
    uint32_t a;
    asm("{ .reg .u64 t; cvta.to.shared.u64 t, %1; cvt.u32.u64 %0, t; }" : "=r"(a) : "l"(p));
    return a;
}
__device__ __forceinline__ void cpa16(uint32_t dst, const void* src) {
    asm volatile("cp.async.cg.shared.global [%0], [%1], 16;" :: "r"(dst), "l"(src));
}
#define CP_COMMIT() asm volatile("cp.async.commit_group;" ::: "memory")
#define CP_WAIT(n)  asm volatile("cp.async.wait_group %0;" :: "n"(n) : "memory")

__device__ __forceinline__ void ldsm_x4(uint32_t a, uint32_t* r) {
    asm volatile("ldmatrix.sync.aligned.m8n8.x4.shared.b16 {%0,%1,%2,%3}, [%4];"
                 : "=r"(r[0]), "=r"(r[1]), "=r"(r[2]), "=r"(r[3]) : "r"(a));
}
__device__ __forceinline__ void mma_16816(float* d, const uint32_t* a, const uint32_t* b) {
    asm volatile("mma.sync.aligned.m16n8k16.row.col.f32.f16.f16.f32 "
                 "{%0,%1,%2,%3}, {%4,%5,%6,%7}, {%8,%9}, {%0,%1,%2,%3};"
                 : "+f"(d[0]), "+f"(d[1]), "+f"(d[2]), "+f"(d[3])
                 : "r"(a[0]), "r"(a[1]), "r"(a[2]), "r"(a[3]), "r"(b[0]), "r"(b[1]));
}

// ---------------- fp16 hi/lo split ----------------
__device__ __forceinline__ void split_h(float v, f16& h, f16& l) {
    h = __float2half_rn(v);
    l = __float2half_rn(v - __half2float(h));
}

// ---------------- weight prep ----------------
__global__ void prep_qkv_kernel(const float* __restrict__ Wq, const float* __restrict__ Wk,
                                const float* __restrict__ Wv,
                                f16* __restrict__ hi, f16* __restrict__ lo) {
    int idx = blockIdx.x * blockDim.x + threadIdx.x;
    if (idx >= QKVN * C) return;
    int n = idx / C, k = idx % C;
    int m = n / C, hd = n % C;
    int h = hd / HD, d = hd % HD;
    const float* W = (m == 0) ? Wq : ((m == 1) ? Wk : Wv);
    split_h(W[(size_t)h * C * HD + (size_t)k * HD + d], hi[idx], lo[idx]);
}

__global__ void prep_t_kernel(const float* __restrict__ src, f16* __restrict__ hi,
                              int K, int N) {
    int idx = blockIdx.x * blockDim.x + threadIdx.x;
    if (idx >= K * N) return;
    int k = idx / N, n = idx % N;
    hi[(size_t)n * K + k] = __float2half_rn(src[idx]);
}

// ---------------- layernorm: one warp per row, outputs hi (+lo optional) fp16 ----------------
__global__ void ln_kernel(const float* __restrict__ x, const float* __restrict__ g,
                          const float* __restrict__ b,
                          f16* __restrict__ out_hi, f16* __restrict__ out_lo) {
    int row  = blockIdx.x * blockDim.y + threadIdx.y;
    int lane = threadIdx.x;
    const float* xr = x + (size_t)row * C;
    float4 v[3];
    float sum = 0.f, sq = 0.f;
#pragma unroll
    for (int i = 0; i < 3; i++) {
        v[i] = *(const float4*)(xr + i * 128 + lane * 4);
        sum += v[i].x + v[i].y + v[i].z + v[i].w;
        sq  += v[i].x * v[i].x + v[i].y * v[i].y + v[i].z * v[i].z + v[i].w * v[i].w;
    }
#pragma unroll
    for (int o = 16; o; o >>= 1) {
        sum += __shfl_xor_sync(0xffffffffu, sum, o);
        sq  += __shfl_xor_sync(0xffffffffu, sq, o);
    }
    float mean = sum * (1.0f / C);
    float var  = sq * (1.0f / C) - mean * mean;
    float rstd = rsqrtf(var + 1e-5f);
    size_t rbase = (size_t)row * C;
#pragma unroll
    for (int i = 0; i < 3; i++) {
        int col = i * 128 + lane * 4;
        float4 gg = *(const float4*)(g + col);
        float4 bb = *(const float4*)(b + col);
        float o0 = (v[i].x - mean) * rstd * gg.x + bb.x;
        float o1 = (v[i].y - mean) * rstd * gg.y + bb.y;
        float o2 = (v[i].z - mean) * rstd * gg.z + bb.z;
        float o3 = (v[i].w - mean) * rstd * gg.w + bb.w;
        f16 h0, l0, h1, l1, h2, l2, h3, l3;
        split_h(o0, h0, l0); split_h(o1, h1, l1);
        split_h(o2, h2, l2); split_h(o3, h3, l3);
        *(__half2*)(out_hi + rbase + col)     = __halves2half2(h0, h1);
        *(__half2*)(out_hi + rbase + col + 2) = __halves2half2(h2, h3);
        if (out_lo) {
            *(__half2*)(out_lo + rbase + col)     = __halves2half2(l0, l1);
            *(__half2*)(out_lo + rbase + col + 2) = __halves2half2(l2, l3);
        }
    }
}

// ---------------- HMMA GEMM: out[M,N] = A[M,K] @ B[N,K]^T, fp16 hi/lo split ----------------
// terms per CTA: 3 (hi*hi + hi*lo + lo*hi) when cb < n3, else `tlo` (1 = hi*hi only,
// 2 = hi*hi + hi*lo). Unused planes are neither loaded nor multiplied.
// MODE 0: store fp32 | MODE 1: +bias +res, fp32 | MODE 2: +bias, relu, fp16 (lo optional)
#define BMT 128
#define BNT 128
#define BKT 32
#define STAGE_BYTES 32768
#define NSTAGE 3
#define GEMM_SMEM (NSTAGE * STAGE_BYTES)
// stage: Ahi @0, Alo @8192, Bhi @16384, Blo @24576; row = 64B (32 f16)
// 16B-chunk swizzle: chunk c of row r at c ^ ((r>>1)&3)

__device__ __forceinline__ void tile_load(uint32_t sdst, const f16* __restrict__ g,
                                          int ld, int tid) {
#pragma unroll
    for (int i = 0; i < 2; i++) {
        int id = tid + i * 256;
        int r = id >> 2, c = id & 3;
        uint32_t dst = sdst + r * 64 + ((c ^ ((r >> 1) & 3)) << 4);
        cpa16(dst, g + (size_t)r * ld + c * 8);
    }
}

__device__ __forceinline__ void compute_stage(uint32_t st, int arow, int a_kc,
                                              int bn, int b_kc, int terms,
                                              float (&acc)[4][4][4]) {
#pragma unroll
    for (int ks = 0; ks < 2; ks++) {
        const int akc = ks * 2 + a_kc;
        const int bkc = ks * 2 + b_kc;
        uint32_t a[4][4], bh[2][4], bl[2][4];
        // A_hi
#pragma unroll
        for (int ma = 0; ma < 4; ma++) {
            int r = arow + ma * 16;
            ldsm_x4(st + r * 64 + ((akc ^ ((r >> 1) & 3)) << 4), a[ma]);
        }
        // B_hi
#pragma unroll
        for (int p = 0; p < 2; p++) {
            int n = bn + p * 16;
            ldsm_x4(st + 16384 + n * 64 + ((bkc ^ ((n >> 1) & 3)) << 4), bh[p]);
        }
#pragma unroll
        for (int ma = 0; ma < 4; ma++)
#pragma unroll
            for (int na = 0; na < 4; na++)
                mma_16816(acc[ma][na], a[ma], &bh[na >> 1][(na & 1) * 2]);
        if (terms >= 2) {
            // B_lo
#pragma unroll
            for (int p = 0; p < 2; p++) {
                int n = bn + p * 16;
                ldsm_x4(st + 24576 + n * 64 + ((bkc ^ ((n >> 1) & 3)) << 4), bl[p]);
            }
#pragma unroll
            for (int ma = 0; ma < 4; ma++)
#pragma unroll
                for (int na = 0; na < 4; na++)
                    mma_16816(acc[ma][na], a[ma], &bl[na >> 1][(na & 1) * 2]);
        }
        if (terms >= 3) {
            // A_lo overwrites A_hi
#pragma unroll
            for (int ma = 0; ma < 4; ma++) {
                int r = arow + ma * 16;
                ldsm_x4(st + 8192 + r * 64 + ((akc ^ ((r >> 1) & 3)) << 4), a[ma]);
            }
#pragma unroll
            for (int ma = 0; ma < 4; ma++)
#pragma unroll
                for (int na = 0; na < 4; na++)
                    mma_16816(acc[ma][na], a[ma], &bh[na >> 1][(na & 1) * 2]);
        }
    }
}

template <int MODE>
__global__ __launch_bounds__(256, 2) void mma_gemm(
    const f16* __restrict__ Ahi, const f16* __restrict__ Alo,
    const f16* __restrict__ Bhi, const f16* __restrict__ Blo,
    const float* __restrict__ bias, const float* __restrict__ res,
    float* __restrict__ outf, f16* __restrict__ out_hi, f16* __restrict__ out_lo,
    int N, int K, int n3, int tlo)
{
    extern __shared__ char smem[];
    const uint32_t sb = smem_u32(smem);
    const int tid  = threadIdx.x;
    const int lane = tid & 31;
    const int wid  = tid >> 5;
    const int wm   = wid >> 2;     // 0..1
    const int wn   = wid & 3;      // 0..3
    const int cb   = blockIdx.x * BNT;
    const int rb   = blockIdx.y * BMT;
    const int NC   = K / BKT;
    const int terms = (cb < n3) ? 3 : tlo;

    const f16* Ahi_t = Ahi + (size_t)rb * K;
    const f16* Alo_t = Alo ? Alo + (size_t)rb * K : nullptr;
    const f16* Bhi_t = Bhi + (size_t)cb * K;
    const f16* Blo_t = Blo ? Blo + (size_t)cb * K : nullptr;

    float acc[4][4][4];
#pragma unroll
    for (int i = 0; i < 4; i++)
#pragma unroll
        for (int j = 0; j < 4; j++)
#pragma unroll
            for (int q = 0; q < 4; q++) acc[i][j][q] = 0.f;

    const int arow = wm * 64 + (lane & 15);
    const int a_kc = lane >> 4;
    const int bn   = wn * 32 + ((lane >> 4) << 3) + (lane & 7);
    const int b_kc = (lane >> 3) & 1;

#define ISSUE(cn, s) do {                                              \
        int _kc = (cn) * BKT;                                          \
        uint32_t _st = sb + (s) * STAGE_BYTES;                         \
        tile_load(_st,         Ahi_t + _kc, K, tid);                   \
        if (terms >= 3) tile_load(_st + 8192,  Alo_t + _kc, K, tid);   \
        tile_load(_st + 16384, Bhi_t + _kc, K, tid);                   \
        if (terms >= 2) tile_load(_st + 24576, Blo_t + _kc, K, tid);   \
        CP_COMMIT();                                                   \
    } while (0)

    ISSUE(0, 0);
    ISSUE(1, 1);

    int s = 0, s2 = 2;
    for (int c = 0; c < NC; c++) {
        if (c + 1 < NC) CP_WAIT(1); else CP_WAIT(0);
        __syncthreads();
        if (c + 2 < NC) ISSUE(c + 2, s2);
        compute_stage(sb + s * STAGE_BYTES, arow, a_kc, bn, b_kc, terms, acc);
        s  = (s == 2)  ? 0 : s + 1;
        s2 = (s2 == 2) ? 0 : s2 + 1;
    }
#undef ISSUE

    // epilogue
    const int g  = lane >> 2;
    const int tg = lane & 3;
#pragma unroll
    for (int ma = 0; ma < 4; ma++) {
        int r0 = rb + wm * 64 + ma * 16 + g;
#pragma unroll
        for (int na = 0; na < 4; na++) {
            int col = cb + wn * 32 + na * 8 + tg * 2;
            float d0 = acc[ma][na][0], d1 = acc[ma][na][1];
            float d2 = acc[ma][na][2], d3 = acc[ma][na][3];
            if (MODE >= 1) {
                float2 bb = *(const float2*)(bias + col);
                d0 += bb.x; d1 += bb.y; d2 += bb.x; d3 += bb.y;
            }
            if (MODE == 1) {
                float2 ra  = *(const float2*)(res + (size_t)r0 * N + col);
                float2 rbv = *(const float2*)(res + (size_t)(r0 + 8) * N + col);
                d0 += ra.x; d1 += ra.y; d2 += rbv.x; d3 += rbv.y;
            }
            if (MODE == 2) {
                d0 = fmaxf(d0, 0.f); d1 = fmaxf(d1, 0.f);
                d2 = fmaxf(d2, 0.f); d3 = fmaxf(d3, 0.f);
                *(__half2*)(out_hi + (size_t)r0 * N + col) =
                    __halves2half2(__float2half_rn(d0), __float2half_rn(d1));
                *(__half2*)(out_hi + (size_t)(r0 + 8) * N + col) =
                    __halves2half2(__float2half_rn(d2), __float2half_rn(d3));
                if (out_lo) {
                    f16 h0, l0, h1, l1;
                    split_h(d0, h0, l0); split_h(d1, h1, l1);
                    *(__half2*)(out_lo + (size_t)r0 * N + col) = __halves2half2(l0, l1);
                    split_h(d2, h0, l0); split_h(d3, h1, l1);
                    *(__half2*)(out_lo + (size_t)(r0 + 8) * N + col) = __halves2half2(l0, l1);
                }
            } else {
                *(float2*)(outf + (size_t)r0 * N + col)       = make_float2(d0, d1);
                *(float2*)(outf + (size_t)(r0 + 8) * N + col) = make_float2(d2, d3);
            }
        }
    }
}

// ---------------- attention: one CTA per (batch, head), fp32, fp16 output (hi only) ----------------
__global__ __launch_bounds__(128) void attn_kernel(const float* __restrict__ qkv,
                                                   f16* __restrict__ out_hi) {
    extern __shared__ float sm[];
    float* qs = sm;                   // [64][48]
    float* ks = qs + 64 * 48;
    float* vs = ks + 64 * 48;
    float* ws = vs + 64 * 48;         // [64][64]

    const int bh = blockIdx.x;
    const int b  = bh >> 3;
    const int h  = bh & 7;
    const int tid = threadIdx.x;
    const size_t base = (size_t)b * TT * QKVN + (size_t)h * HD;

    for (int idx = tid; idx < 64 * 12; idx += 128) {
        int t  = idx / 12;
        int c4 = (idx % 12) * 4;
        const float* p = qkv + base + (size_t)t * QKVN + c4;
        *(float4*)&qs[t * 48 + c4] = *(const float4*)p;
        *(float4*)&ks[t * 48 + c4] = *(const float4*)(p + C);
        *(float4*)&vs[t * 48 + c4] = *(const float4*)(p + 2 * C);
    }
    __syncthreads();

    const float scale = 2.449489742783178f;  // 48 * 384^-0.5

    for (int idx = tid; idx < 64 * 64; idx += 128) {
        int i = idx >> 6, j = idx & 63;
        if (j > i) continue;
        float sx = 0.f, sy = 0.f, sz = 0.f, sw = 0.f;
#pragma unroll
        for (int d4 = 0; d4 < 12; d4++) {
            float4 qv = *(const float4*)&qs[i * 48 + d4 * 4];
            float4 kv = *(const float4*)&ks[j * 48 + d4 * 4];
            sx += qv.x * kv.x; sy += qv.y * kv.y;
            sz += qv.z * kv.z; sw += qv.w * kv.w;
        }
        ws[i * 64 + j] = (sx + sy + sz + sw) * scale;
    }
    __syncthreads();

    if (tid < 64) {
        int i = tid;
        float m = -1e30f;
        for (int j = 0; j <= i; j++) m = fmaxf(m, ws[i * 64 + j]);
        float s = 0.f;
        for (int j = 0; j <= i; j++) {
            float e = expf(ws[i * 64 + j] - m);
            ws[i * 64 + j] = e;
            s += e;
        }
        float inv = 1.f / s;
        for (int j = 0; j <= i; j++) ws[i * 64 + j] *= inv;
    }
    __syncthreads();

    for (int idx = tid; idx < 64 * 12; idx += 128) {
        int i  = idx / 12;
        int d4 = (idx % 12) * 4;
        float ax = 0.f, ay = 0.f, az = 0.f, aw = 0.f;
        for (int j = 0; j <= i; j++) {
            float w = ws[i * 64 + j];
            float4 vv = *(const float4*)&vs[j * 48 + d4];
            ax += w * vv.x; ay += w * vv.y; az += w * vv.z; aw += w * vv.w;
        }
        size_t o = (size_t)(b * TT + i) * C + h * HD + d4;
        *(__half2*)(out_hi + o)     = __halves2half2(__float2half_rn(ax), __float2half_rn(ay));
        *(__half2*)(out_hi + o + 2) = __halves2half2(__float2half_rn(az), __float2half_rn(aw));
    }
}

// ---------------- launch ----------------
extern "C" void kernel_launch(void* const* d_in, const int* in_sizes, int n_in,
                              void* d_out, int out_size) {
    const float* x     = (const float*)d_in[0];
    const float* ln1_g = (const float*)d_in[1];
    const float* ln1_b = (const float*)d_in[2];
    const float* ln2_g = (const float*)d_in[3];
    const float* ln2_b = (const float*)d_in[4];
    const float* Wq    = (const float*)d_in[5];
    const float* Wk    = (const float*)d_in[6];
    const float* Wv    = (const float*)d_in[7];
    const float* Wp    = (const float*)d_in[8];
    const float* bp    = (const float*)d_in[9];
    const float* W1    = (const float*)d_in[10];
    const float* b1    = (const float*)d_in[11];
    const float* W2    = (const float*)d_in[12];
    const float* b2    = (const float*)d_in[13];
    float* out = (float*)d_out;

    f16 *ph_hi, *ph_lo, *pattn_hi, *phid_hi;
    f16 *pwqkv_hi, *pwqkv_lo, *pwp_hi, *pw1_hi, *pw2_hi;
    float *pqkv, *px2;
    cudaGetSymbolAddress((void**)&ph_hi, g_h_hi);     cudaGetSymbolAddress((void**)&ph_lo, g_h_lo);
    cudaGetSymbolAddress((void**)&pqkv, g_qkv);
    cudaGetSymbolAddress((void**)&pattn_hi, g_attn_hi);
    cudaGetSymbolAddress((void**)&px2, g_x2);
    cudaGetSymbolAddress((void**)&phid_hi, g_hid_hi);
    cudaGetSymbolAddress((void**)&pwqkv_hi, g_wqkv_hi); cudaGetSymbolAddress((void**)&pwqkv_lo, g_wqkv_lo);
    cudaGetSymbolAddress((void**)&pwp_hi, g_wp_hi);
    cudaGetSymbolAddress((void**)&pw1_hi, g_w1_hi);
    cudaGetSymbolAddress((void**)&pw2_hi, g_w2_hi);

    static int attr_set = 0;
    const int attn_smem = (3 * 64 * 48 + 64 * 64) * (int)sizeof(float);
    if (!attr_set) {
        cudaFuncSetAttribute(attn_kernel, cudaFuncAttributeMaxDynamicSharedMemorySize, attn_smem);
        cudaFuncSetAttribute(mma_gemm<0>, cudaFuncAttributeMaxDynamicSharedMemorySize, GEMM_SMEM);
        cudaFuncSetAttribute(mma_gemm<1>, cudaFuncAttributeMaxDynamicSharedMemorySize, GEMM_SMEM);
        cudaFuncSetAttribute(mma_gemm<2>, cudaFuncAttributeMaxDynamicSharedMemorySize, GEMM_SMEM);
        attr_set = 1;
    }

    // weight prep
    prep_qkv_kernel<<<(QKVN * C + 255) / 256, 256>>>(Wq, Wk, Wv, pwqkv_hi, pwqkv_lo);
    prep_t_kernel<<<(C * C + 255) / 256, 256>>>(Wp, pwp_hi, C, C);
    prep_t_kernel<<<(C * C4 + 255) / 256, 256>>>(W1, pw1_hi, C, C4);
    prep_t_kernel<<<(C4 * C + 255) / 256, 256>>>(W2, pw2_hi, C4, C);

    // LN1 (lo needed: q,k are 3-term)
    ln_kernel<<<BT / 8, dim3(32, 8)>>>(x, ln1_g, ln1_b, ph_hi, ph_lo);
    // QKV: q,k cols (0..767) 3-term; v cols 1-term
    mma_gemm<0><<<dim3(QKVN / 128, BT / 128), 256, GEMM_SMEM>>>(
        ph_hi, ph_lo, pwqkv_hi, pwqkv_lo, nullptr, nullptr, pqkv, nullptr, nullptr,
        QKVN, C, 2 * C, 1);
    // attention (hi output only)
    attn_kernel<<<BATCH * NH, 128, attn_smem>>>(pqkv, pattn_hi);
    // proj + bias + residual -> x2 (1-term)
    mma_gemm<1><<<dim3(C / 128, BT / 128), 256, GEMM_SMEM>>>(
        pattn_hi, nullptr, pwp_hi, nullptr, bp, x, px2, nullptr, nullptr, C, C, 0, 1);
    // LN2 (hi only — FFN1 is 1-term)
    ln_kernel<<<BT / 8, dim3(32, 8)>>>(px2, ln2_g, ln2_b, ph_hi, nullptr);
    // FFN1 + bias + relu -> hidden hi (1-term)
    mma_gemm<2><<<dim3(C4 / 128, BT / 128), 256, GEMM_SMEM>>>(
        ph_hi, nullptr, pw1_hi, nullptr, b1, nullptr, nullptr, phid_hi, nullptr,
        C4, C, 0, 1);
    // FFN2 + bias + residual -> out (1-term)
    mma_gemm<1><<<dim3(C / 128, BT / 128), 256, GEMM_SMEM>>>(
        phid_hi, nullptr, pw2_hi, nullptr, b2, px2, out, nullptr, nullptr, C, C4, 0, 1);
}

// round 8
// speedup vs baseline: 5.3813x; 1.4499x over previous
#include <cuda_runtime.h>
#include <cuda_fp16.h>
#include <math.h>
#include <stdint.h>

// ---------------- problem constants ----------------
#define BATCH   2048
#define TT      64
#define BT      (BATCH * TT)      // 131072 rows
#define C       384
#define NH      8
#define HD      48
#define C4      1536
#define QKVN    1152

typedef __half f16;

// ---------------- device scratch ----------------
__device__ __align__(256) f16   g_h_hi[BT * C],   g_h_lo[BT * C];
__device__ __align__(256) f16   g_qkv_hi[BT * QKVN], g_qkv_lo[BT * QKVN];
__device__ __align__(256) f16   g_attn_hi[BT * C];
__device__ __align__(256) float g_x2[BT * C];
__device__ __align__(256) f16   g_hid_hi[BT * C4];
__device__ __align__(256) f16   g_wqkv_hi[QKVN * C], g_wqkv_lo[QKVN * C];
__device__ __align__(256) f16   g_wp_hi[C * C];
__device__ __align__(256) f16   g_w1_hi[C4 * C];
__device__ __align__(256) f16   g_w2_hi[C * C4];

// ---------------- PTX helpers (base-arch only) ----------------
__device__ __forceinline__ uint32_t smem_u32(const void* p) {
    uint32_t a;
    asm("{ .reg .u64 t; cvta.to.shared.u64 t, %1; cvt.u32.u64 %0, t; }" : "=r"(a) : "l"(p));
    return a;
}
__device__ __forceinline__ void cpa16(uint32_t dst, const void* src) {
    asm volatile("cp.async.cg.shared.global [%0], [%1], 16;" :: "r"(dst), "l"(src));
}
#define CP_COMMIT() asm volatile("cp.async.commit_group;" ::: "memory")
#define CP_WAIT(n)  asm volatile("cp.async.wait_group %0;" :: "n"(n) : "memory")

__device__ __forceinline__ void ldsm_x4(uint32_t a, uint32_t* r) {
    asm volatile("ldmatrix.sync.aligned.m8n8.x4.shared.b16 {%0,%1,%2,%3}, [%4];"
                 : "=r"(r[0]), "=r"(r[1]), "=r"(r[2]), "=r"(r[3]) : "r"(a));
}
__device__ __forceinline__ void mma_16816(float* d, const uint32_t* a, const uint32_t* b) {
    asm volatile("mma.sync.aligned.m16n8k16.row.col.f32.f16.f16.f32 "
                 "{%0,%1,%2,%3}, {%4,%5,%6,%7}, {%8,%9}, {%0,%1,%2,%3};"
                 : "+f"(d[0]), "+f"(d[1]), "+f"(d[2]), "+f"(d[3])
                 : "r"(a[0]), "r"(a[1]), "r"(a[2]), "r"(a[3]), "r"(b[0]), "r"(b[1]));
}

// ---------------- fp16 hi/lo split ----------------
__device__ __forceinline__ void split_h(float v, f16& h, f16& l) {
    h = __float2half_rn(v);
    l = __float2half_rn(v - __half2float(h));
}
__device__ __forceinline__ uint32_t pack_h2(float a, float b) {
    __half2 h = __floats2half2_rn(a, b);
    return *(uint32_t*)&h;
}

// ---------------- weight prep ----------------
__global__ void prep_qkv_kernel(const float* __restrict__ Wq, const float* __restrict__ Wk,
                                const float* __restrict__ Wv,
                                f16* __restrict__ hi, f16* __restrict__ lo) {
    int idx = blockIdx.x * blockDim.x + threadIdx.x;
    if (idx >= QKVN * C) return;
    int n = idx / C, k = idx % C;
    int m = n / C, hd = n % C;
    int h = hd / HD, d = hd % HD;
    const float* W = (m == 0) ? Wq : ((m == 1) ? Wk : Wv);
    split_h(W[(size_t)h * C * HD + (size_t)k * HD + d], hi[idx], lo[idx]);
}

__global__ void prep_t_kernel(const float* __restrict__ src, f16* __restrict__ hi,
                              int K, int N) {
    int idx = blockIdx.x * blockDim.x + threadIdx.x;
    if (idx >= K * N) return;
    int k = idx / N, n = idx % N;
    hi[(size_t)n * K + k] = __float2half_rn(src[idx]);
}

// ---------------- layernorm: one warp per row, outputs hi (+lo optional) fp16 ----------------
__global__ void ln_kernel(const float* __restrict__ x, const float* __restrict__ g,
                          const float* __restrict__ b,
                          f16* __restrict__ out_hi, f16* __restrict__ out_lo) {
    int row  = blockIdx.x * blockDim.y + threadIdx.y;
    int lane = threadIdx.x;
    const float* xr = x + (size_t)row * C;
    float4 v[3];
    float sum = 0.f, sq = 0.f;
#pragma unroll
    for (int i = 0; i < 3; i++) {
        v[i] = *(const float4*)(xr + i * 128 + lane * 4);
        sum += v[i].x + v[i].y + v[i].z + v[i].w;
        sq  += v[i].x * v[i].x + v[i].y * v[i].y + v[i].z * v[i].z + v[i].w * v[i].w;
    }
#pragma unroll
    for (int o = 16; o; o >>= 1) {
        sum += __shfl_xor_sync(0xffffffffu, sum, o);
        sq  += __shfl_xor_sync(0xffffffffu, sq, o);
    }
    float mean = sum * (1.0f / C);
    float var  = sq * (1.0f / C) - mean * mean;
    float rstd = rsqrtf(var + 1e-5f);
    size_t rbase = (size_t)row * C;
#pragma unroll
    for (int i = 0; i < 3; i++) {
        int col = i * 128 + lane * 4;
        float4 gg = *(const float4*)(g + col);
        float4 bb = *(const float4*)(b + col);
        float o0 = (v[i].x - mean) * rstd * gg.x + bb.x;
        float o1 = (v[i].y - mean) * rstd * gg.y + bb.y;
        float o2 = (v[i].z - mean) * rstd * gg.z + bb.z;
        float o3 = (v[i].w - mean) * rstd * gg.w + bb.w;
        f16 h0, l0, h1, l1, h2, l2, h3, l3;
        split_h(o0, h0, l0); split_h(o1, h1, l1);
        split_h(o2, h2, l2); split_h(o3, h3, l3);
        *(__half2*)(out_hi + rbase + col)     = __halves2half2(h0, h1);
        *(__half2*)(out_hi + rbase + col + 2) = __halves2half2(h2, h3);
        if (out_lo) {
            *(__half2*)(out_lo + rbase + col)     = __halves2half2(l0, l1);
            *(__half2*)(out_lo + rbase + col + 2) = __halves2half2(l2, l3);
        }
    }
}

// ---------------- HMMA GEMM: out[M,N] = A[M,K] @ B[N,K]^T, fp16 hi/lo split ----------------
// terms per CTA: 3 when cb < n3, else tlo (1 or 2).
// MODE 1: +bias +res, fp32 | MODE 2: +bias, relu, fp16 hi | MODE 3: fp16 hi (+lo if terms>=3)
#define BMT 128
#define BNT 128
#define BKT 32
#define STAGE_BYTES 32768
#define NSTAGE 3
#define GEMM_SMEM (NSTAGE * STAGE_BYTES)

__device__ __forceinline__ void tile_load(uint32_t sdst, const f16* __restrict__ g,
                                          int ld, int tid) {
#pragma unroll
    for (int i = 0; i < 2; i++) {
        int id = tid + i * 256;
        int r = id >> 2, c = id & 3;
        uint32_t dst = sdst + r * 64 + ((c ^ ((r >> 1) & 3)) << 4);
        cpa16(dst, g + (size_t)r * ld + c * 8);
    }
}

__device__ __forceinline__ void compute_stage(uint32_t st, int arow, int a_kc,
                                              int bn, int b_kc, int terms,
                                              float (&acc)[4][4][4]) {
#pragma unroll
    for (int ks = 0; ks < 2; ks++) {
        const int akc = ks * 2 + a_kc;
        const int bkc = ks * 2 + b_kc;
        uint32_t a[4][4], bh[2][4], bl[2][4];
#pragma unroll
        for (int ma = 0; ma < 4; ma++) {
            int r = arow + ma * 16;
            ldsm_x4(st + r * 64 + ((akc ^ ((r >> 1) & 3)) << 4), a[ma]);
        }
#pragma unroll
        for (int p = 0; p < 2; p++) {
            int n = bn + p * 16;
            ldsm_x4(st + 16384 + n * 64 + ((bkc ^ ((n >> 1) & 3)) << 4), bh[p]);
        }
#pragma unroll
        for (int ma = 0; ma < 4; ma++)
#pragma unroll
            for (int na = 0; na < 4; na++)
                mma_16816(acc[ma][na], a[ma], &bh[na >> 1][(na & 1) * 2]);
        if (terms >= 2) {
#pragma unroll
            for (int p = 0; p < 2; p++) {
                int n = bn + p * 16;
                ldsm_x4(st + 24576 + n * 64 + ((bkc ^ ((n >> 1) & 3)) << 4), bl[p]);
            }
#pragma unroll
            for (int ma = 0; ma < 4; ma++)
#pragma unroll
                for (int na = 0; na < 4; na++)
                    mma_16816(acc[ma][na], a[ma], &bl[na >> 1][(na & 1) * 2]);
        }
        if (terms >= 3) {
#pragma unroll
            for (int ma = 0; ma < 4; ma++) {
                int r = arow + ma * 16;
                ldsm_x4(st + 8192 + r * 64 + ((akc ^ ((r >> 1) & 3)) << 4), a[ma]);
            }
#pragma unroll
            for (int ma = 0; ma < 4; ma++)
#pragma unroll
                for (int na = 0; na < 4; na++)
                    mma_16816(acc[ma][na], a[ma], &bh[na >> 1][(na & 1) * 2]);
        }
    }
}

template <int MODE>
__global__ __launch_bounds__(256, 2) void mma_gemm(
    const f16* __restrict__ Ahi, const f16* __restrict__ Alo,
    const f16* __restrict__ Bhi, const f16* __restrict__ Blo,
    const float* __restrict__ bias, const float* __restrict__ res,
    float* __restrict__ outf, f16* __restrict__ out_hi, f16* __restrict__ out_lo,
    int N, int K, int n3, int tlo)
{
    extern __shared__ char smem[];
    const uint32_t sb = smem_u32(smem);
    const int tid  = threadIdx.x;
    const int lane = tid & 31;
    const int wid  = tid >> 5;
    const int wm   = wid >> 2;
    const int wn   = wid & 3;
    const int cb   = blockIdx.x * BNT;
    const int rb   = blockIdx.y * BMT;
    const int NC   = K / BKT;
    const int terms = (cb < n3) ? 3 : tlo;

    const f16* Ahi_t = Ahi + (size_t)rb * K;
    const f16* Alo_t = Alo ? Alo + (size_t)rb * K : nullptr;
    const f16* Bhi_t = Bhi + (size_t)cb * K;
    const f16* Blo_t = Blo ? Blo + (size_t)cb * K : nullptr;

    float acc[4][4][4];
#pragma unroll
    for (int i = 0; i < 4; i++)
#pragma unroll
        for (int j = 0; j < 4; j++)
#pragma unroll
            for (int q = 0; q < 4; q++) acc[i][j][q] = 0.f;

    const int arow = wm * 64 + (lane & 15);
    const int a_kc = lane >> 4;
    const int bn   = wn * 32 + ((lane >> 4) << 3) + (lane & 7);
    const int b_kc = (lane >> 3) & 1;

#define ISSUE(cn, s) do {                                              \
        int _kc = (cn) * BKT;                                          \
        uint32_t _st = sb + (s) * STAGE_BYTES;                         \
        tile_load(_st,         Ahi_t + _kc, K, tid);                   \
        if (terms >= 3) tile_load(_st + 8192,  Alo_t + _kc, K, tid);   \
        tile_load(_st + 16384, Bhi_t + _kc, K, tid);                   \
        if (terms >= 2) tile_load(_st + 24576, Blo_t + _kc, K, tid);   \
        CP_COMMIT();                                                   \
    } while (0)

    ISSUE(0, 0);
    ISSUE(1, 1);

    int s = 0, s2 = 2;
    for (int c = 0; c < NC; c++) {
        if (c + 1 < NC) CP_WAIT(1); else CP_WAIT(0);
        __syncthreads();
        if (c + 2 < NC) ISSUE(c + 2, s2);
        compute_stage(sb + s * STAGE_BYTES, arow, a_kc, bn, b_kc, terms, acc);
        s  = (s == 2)  ? 0 : s + 1;
        s2 = (s2 == 2) ? 0 : s2 + 1;
    }
#undef ISSUE

    const int g  = lane >> 2;
    const int tg = lane & 3;
#pragma unroll
    for (int ma = 0; ma < 4; ma++) {
        int r0 = rb + wm * 64 + ma * 16 + g;
#pragma unroll
        for (int na = 0; na < 4; na++) {
            int col = cb + wn * 32 + na * 8 + tg * 2;
            float d0 = acc[ma][na][0], d1 = acc[ma][na][1];
            float d2 = acc[ma][na][2], d3 = acc[ma][na][3];
            if (MODE == 1 || MODE == 2) {
                float2 bb = *(const float2*)(bias + col);
                d0 += bb.x; d1 += bb.y; d2 += bb.x; d3 += bb.y;
            }
            if (MODE == 1) {
                float2 ra  = *(const float2*)(res + (size_t)r0 * N + col);
                float2 rbv = *(const float2*)(res + (size_t)(r0 + 8) * N + col);
                d0 += ra.x; d1 += ra.y; d2 += rbv.x; d3 += rbv.y;
                *(float2*)(outf + (size_t)r0 * N + col)       = make_float2(d0, d1);
                *(float2*)(outf + (size_t)(r0 + 8) * N + col) = make_float2(d2, d3);
            }
            if (MODE == 2) {
                d0 = fmaxf(d0, 0.f); d1 = fmaxf(d1, 0.f);
                d2 = fmaxf(d2, 0.f); d3 = fmaxf(d3, 0.f);
                *(__half2*)(out_hi + (size_t)r0 * N + col) =
                    __halves2half2(__float2half_rn(d0), __float2half_rn(d1));
                *(__half2*)(out_hi + (size_t)(r0 + 8) * N + col) =
                    __halves2half2(__float2half_rn(d2), __float2half_rn(d3));
            }
            if (MODE == 3) {
                f16 h0, l0, h1, l1, h2, l2, h3, l3;
                split_h(d0, h0, l0); split_h(d1, h1, l1);
                split_h(d2, h2, l2); split_h(d3, h3, l3);
                *(__half2*)(out_hi + (size_t)r0 * N + col)       = __halves2half2(h0, h1);
                *(__half2*)(out_hi + (size_t)(r0 + 8) * N + col) = __halves2half2(h2, h3);
                if (terms >= 3) {
                    *(__half2*)(out_lo + (size_t)r0 * N + col)       = __halves2half2(l0, l1);
                    *(__half2*)(out_lo + (size_t)(r0 + 8) * N + col) = __halves2half2(l2, l3);
                }
            }
        }
    }
}

// ---------------- attention: flash-v2 style HMMA, one CTA per (batch, head) ----------------
// smem: Qh/Ql/Kh/Kl [64 rows][112B stride], VT [48 rows(d)][144B stride]
#define AQH 0
#define AQL 7168
#define AKH 14336
#define AKL 21504
#define AVT 28672
#define ATTN_SMEM (28672 + 48 * 144)   // 35584

__global__ __launch_bounds__(128) void attn_mma_kernel(
    const f16* __restrict__ qkv_hi, const f16* __restrict__ qkv_lo,
    f16* __restrict__ out_hi)
{
    __shared__ __align__(16) char sm[ATTN_SMEM];
    const uint32_t sb = smem_u32(sm);
    const int bh = blockIdx.x;
    const int b  = bh >> 3;
    const int h  = bh & 7;
    const int tid  = threadIdx.x;
    const int lane = tid & 31;
    const int w    = tid >> 5;

    // cooperative load: q,k hi/lo -> padded smem; v -> transposed smem
    const f16* base_hi = qkv_hi + (size_t)b * TT * QKVN + h * HD;
    const f16* base_lo = qkv_lo + (size_t)b * TT * QKVN + h * HD;
    for (int idx = tid; idx < 64 * 24; idx += 128) {
        int t  = idx / 24;
        int c2 = (idx % 24) * 2;         // half index within the 48
        size_t go = (size_t)t * QKVN + c2;
        *(__half2*)(sm + AQH + t * 112 + c2 * 2) = *(const __half2*)(base_hi + go);
        *(__half2*)(sm + AQL + t * 112 + c2 * 2) = *(const __half2*)(base_lo + go);
        *(__half2*)(sm + AKH + t * 112 + c2 * 2) = *(const __half2*)(base_hi + go + C);
        *(__half2*)(sm + AKL + t * 112 + c2 * 2) = *(const __half2*)(base_lo + go + C);
        __half2 vv = *(const __half2*)(base_hi + go + 2 * C);
        *(f16*)(sm + AVT + c2 * 144 + t * 2)       = __low2half(vv);
        *(f16*)(sm + AVT + (c2 + 1) * 144 + t * 2) = __high2half(vv);
    }
    __syncthreads();

    // fragment addressing
    const uint32_t qaddr = sb + AQH + (16 * w + (lane & 15)) * 112 + (lane >> 4) * 16;
    const uint32_t kaddr = sb + AKH + (((lane >> 4) << 3) + (lane & 7)) * 112
                              + ((lane >> 3) & 1) * 16;
    const uint32_t vaddr = sb + AVT + (((lane >> 4) << 3) + (lane & 7)) * 144
                              + ((lane >> 3) & 1) * 16;

    // S = q k^T (3-term), tiles nt2 > w are fully masked -> skipped
    float s[8][4];
#pragma unroll
    for (int i = 0; i < 8; i++)
#pragma unroll
        for (int q = 0; q < 4; q++) s[i][q] = 0.f;

    for (int kt = 0; kt < 3; kt++) {
        uint32_t qh[4], ql[4];
        ldsm_x4(qaddr + kt * 32, qh);
        ldsm_x4(qaddr + (AQL - AQH) + kt * 32, ql);
        for (int nt2 = 0; nt2 <= w; nt2++) {
            uint32_t kh[4], kl[4];
            ldsm_x4(kaddr + nt2 * 1792 + kt * 32, kh);
            ldsm_x4(kaddr + (AKL - AKH) + nt2 * 1792 + kt * 32, kl);
            mma_16816(s[2 * nt2],     qh, kh);
            mma_16816(s[2 * nt2 + 1], qh, kh + 2);
            mma_16816(s[2 * nt2],     qh, kl);
            mma_16816(s[2 * nt2 + 1], qh, kl + 2);
            mma_16816(s[2 * nt2],     ql, kh);
            mma_16816(s[2 * nt2 + 1], ql, kh + 2);
        }
    }

    // scale + causal mask + register softmax
    const int g  = lane >> 2;
    const int tq = lane & 3;
    const int r0 = 16 * w + g;
    const int r1 = r0 + 8;
    const float scl = 2.449489742783178f;   // 48 * 384^-0.5
    float mx0 = -1e30f, mx1 = -1e30f;
    const int ntmax = 2 * w + 2;             // tiles beyond are fully masked
#pragma unroll
    for (int nt = 0; nt < 8; nt++) {
        if (nt >= ntmax) { s[nt][0] = s[nt][1] = s[nt][2] = s[nt][3] = 0.f; continue; }
        int c0 = nt * 8 + tq * 2, c1 = c0 + 1;
        s[nt][0] = (c0 <= r0) ? s[nt][0] * scl : -1e30f;
        s[nt][1] = (c1 <= r0) ? s[nt][1] * scl : -1e30f;
        s[nt][2] = (c0 <= r1) ? s[nt][2] * scl : -1e30f;
        s[nt][3] = (c1 <= r1) ? s[nt][3] * scl : -1e30f;
        mx0 = fmaxf(mx0, fmaxf(s[nt][0], s[nt][1]));
        mx1 = fmaxf(mx1, fmaxf(s[nt][2], s[nt][3]));
    }
    mx0 = fmaxf(mx0, __shfl_xor_sync(0xffffffffu, mx0, 1));
    mx0 = fmaxf(mx0, __shfl_xor_sync(0xffffffffu, mx0, 2));
    mx1 = fmaxf(mx1, __shfl_xor_sync(0xffffffffu, mx1, 1));
    mx1 = fmaxf(mx1, __shfl_xor_sync(0xffffffffu, mx1, 2));

    const float l2e = 1.4426950408889634f;
    float sum0 = 0.f, sum1 = 0.f;
#pragma unroll
    for (int nt = 0; nt < 8; nt++) {
        if (nt >= ntmax) continue;
        s[nt][0] = exp2f((s[nt][0] - mx0) * l2e);
        s[nt][1] = exp2f((s[nt][1] - mx0) * l2e);
        s[nt][2] = exp2f((s[nt][2] - mx1) * l2e);
        s[nt][3] = exp2f((s[nt][3] - mx1) * l2e);
        sum0 += s[nt][0] + s[nt][1];
        sum1 += s[nt][2] + s[nt][3];
    }
    sum0 += __shfl_xor_sync(0xffffffffu, sum0, 1);
    sum0 += __shfl_xor_sync(0xffffffffu, sum0, 2);
    sum1 += __shfl_xor_sync(0xffffffffu, sum1, 1);
    sum1 += __shfl_xor_sync(0xffffffffu, sum1, 2);
    const float inv0 = 1.f / sum0, inv1 = 1.f / sum1;

    // pack P into a-fragments (c-frag -> a-frag layout identity)
    uint32_t ap[4][4];
    for (int kt = 0; kt <= w; kt++) {
        ap[kt][0] = pack_h2(s[2 * kt][0] * inv0,     s[2 * kt][1] * inv0);
        ap[kt][1] = pack_h2(s[2 * kt][2] * inv1,     s[2 * kt][3] * inv1);
        ap[kt][2] = pack_h2(s[2 * kt + 1][0] * inv0, s[2 * kt + 1][1] * inv0);
        ap[kt][3] = pack_h2(s[2 * kt + 1][2] * inv1, s[2 * kt + 1][3] * inv1);
    }

    // O = P V  (V^T in smem, plain ldsm)
    float o[6][4];
#pragma unroll
    for (int i = 0; i < 6; i++)
#pragma unroll
        for (int q = 0; q < 4; q++) o[i][q] = 0.f;
    for (int kt = 0; kt <= w; kt++) {
        for (int nt2 = 0; nt2 < 3; nt2++) {
            uint32_t vb[4];
            ldsm_x4(vaddr + nt2 * 2304 + kt * 32, vb);
            mma_16816(o[2 * nt2],     ap[kt], vb);
            mma_16816(o[2 * nt2 + 1], ap[kt], vb + 2);
        }
    }

    // write O (fp16 hi)
    f16* op = out_hi + (size_t)b * TT * C + h * HD;
#pragma unroll
    for (int nt = 0; nt < 6; nt++) {
        int d = nt * 8 + tq * 2;
        *(__half2*)(op + (size_t)r0 * C + d) = __floats2half2_rn(o[nt][0], o[nt][1]);
        *(__half2*)(op + (size_t)r1 * C + d) = __floats2half2_rn(o[nt][2], o[nt][3]);
    }
}

// ---------------- launch ----------------
extern "C" void kernel_launch(void* const* d_in, const int* in_sizes, int n_in,
                              void* d_out, int out_size) {
    const float* x     = (const float*)d_in[0];
    const float* ln1_g = (const float*)d_in[1];
    const float* ln1_b = (const float*)d_in[2];
    const float* ln2_g = (const float*)d_in[3];
    const float* ln2_b = (const float*)d_in[4];
    const float* Wq    = (const float*)d_in[5];
    const float* Wk    = (const float*)d_in[6];
    const float* Wv    = (const float*)d_in[7];
    const float* Wp    = (const float*)d_in[8];
    const float* bp    = (const float*)d_in[9];
    const float* W1    = (const float*)d_in[10];
    const float* b1    = (const float*)d_in[11];
    const float* W2    = (const float*)d_in[12];
    const float* b2    = (const float*)d_in[13];
    float* out = (float*)d_out;

    f16 *ph_hi, *ph_lo, *pqkv_hi, *pqkv_lo, *pattn_hi, *phid_hi;
    f16 *pwqkv_hi, *pwqkv_lo, *pwp_hi, *pw1_hi, *pw2_hi;
    float *px2;
    cudaGetSymbolAddress((void**)&ph_hi, g_h_hi);     cudaGetSymbolAddress((void**)&ph_lo, g_h_lo);
    cudaGetSymbolAddress((void**)&pqkv_hi, g_qkv_hi); cudaGetSymbolAddress((void**)&pqkv_lo, g_qkv_lo);
    cudaGetSymbolAddress((void**)&pattn_hi, g_attn_hi);
    cudaGetSymbolAddress((void**)&px2, g_x2);
    cudaGetSymbolAddress((void**)&phid_hi, g_hid_hi);
    cudaGetSymbolAddress((void**)&pwqkv_hi, g_wqkv_hi); cudaGetSymbolAddress((void**)&pwqkv_lo, g_wqkv_lo);
    cudaGetSymbolAddress((void**)&pwp_hi, g_wp_hi);
    cudaGetSymbolAddress((void**)&pw1_hi, g_w1_hi);
    cudaGetSymbolAddress((void**)&pw2_hi, g_w2_hi);

    static int attr_set = 0;
    if (!attr_set) {
        cudaFuncSetAttribute(mma_gemm<1>, cudaFuncAttributeMaxDynamicSharedMemorySize, GEMM_SMEM);
        cudaFuncSetAttribute(mma_gemm<2>, cudaFuncAttributeMaxDynamicSharedMemorySize, GEMM_SMEM);
        cudaFuncSetAttribute(mma_gemm<3>, cudaFuncAttributeMaxDynamicSharedMemorySize, GEMM_SMEM);
        attr_set = 1;
    }

    // weight prep
    prep_qkv_kernel<<<(QKVN * C + 255) / 256, 256>>>(Wq, Wk, Wv, pwqkv_hi, pwqkv_lo);
    prep_t_kernel<<<(C * C + 255) / 256, 256>>>(Wp, pwp_hi, C, C);
    prep_t_kernel<<<(C * C4 + 255) / 256, 256>>>(W1, pw1_hi, C, C4);
    prep_t_kernel<<<(C4 * C + 255) / 256, 256>>>(W2, pw2_hi, C4, C);

    // LN1 (hi+lo: q,k GEMM is 3-term)
    ln_kernel<<<BT / 8, dim3(32, 8)>>>(x, ln1_g, ln1_b, ph_hi, ph_lo);
    // QKV: q,k cols 3-term -> fp16 hi/lo; v cols 1-term -> fp16 hi
    mma_gemm<3><<<dim3(QKVN / 128, BT / 128), 256, GEMM_SMEM>>>(
        ph_hi, ph_lo, pwqkv_hi, pwqkv_lo, nullptr, nullptr, nullptr, pqkv_hi, pqkv_lo,
        QKVN, C, 2 * C, 1);
    // attention (HMMA flash-style)
    attn_mma_kernel<<<BATCH * NH, 128>>>(pqkv_hi, pqkv_lo, pattn_hi);
    // proj + bias + residual -> x2 (1-term)
    mma_gemm<1><<<dim3(C / 128, BT / 128), 256, GEMM_SMEM>>>(
        pattn_hi, nullptr, pwp_hi, nullptr, bp, x, px2, nullptr, nullptr, C, C, 0, 1);
    // LN2 (hi only)
    ln_kernel<<<BT / 8, dim3(32, 8)>>>(px2, ln2_g, ln2_b, ph_hi, nullptr);
    // FFN1 + bias + relu -> hidden hi (1-term)
    mma_gemm<2><<<dim3(C4 / 128, BT / 128), 256, GEMM_SMEM>>>(
        ph_hi, nullptr, pw1_hi, nullptr, b1, nullptr, nullptr, phid_hi, nullptr,
        C4, C, 0, 1);
    // FFN2 + bias + residual -> out (1-term)
    mma_gemm<1><<<dim3(C / 128, BT / 128), 256, GEMM_SMEM>>>(
        phid_hi, nullptr, pw2_hi, nullptr, b2, px2, out, nullptr, nullptr, C, C4, 0, 1);
}

// round 9
// speedup vs baseline: 5.5471x; 1.0308x over previous
#include <cuda_runtime.h>
#include <cuda_fp16.h>
#include <math.h>
#include <stdint.h>

// ---------------- problem constants ----------------
#define BATCH   2048
#define TT      64
#define BT      (BATCH * TT)      // 131072 rows
#define C       384
#define NH      8
#define HD      48
#define C4      1536
#define QKVN    1152

typedef __half f16;

// ---------------- device scratch ----------------
__device__ __align__(256) f16   g_h_hi[BT * C],   g_h_lo[BT * C];
__device__ __align__(256) f16   g_qkv_hi[BT * QKVN], g_qkv_lo[BT * QKVN];
__device__ __align__(256) f16   g_attn_hi[BT * C];
__device__ __align__(256) float g_x2[BT * C];
__device__ __align__(256) f16   g_hid_hi[BT * C4];
__device__ __align__(256) f16   g_wqkv_hi[QKVN * C], g_wqkv_lo[QKVN * C];
__device__ __align__(256) f16   g_wp_hi[C * C];
__device__ __align__(256) f16   g_w1_hi[C4 * C];
__device__ __align__(256) f16   g_w2_hi[C * C4];

// ---------------- PTX helpers (base-arch only) ----------------
__device__ __forceinline__ uint32_t smem_u32(const void* p) {
    uint32_t a;
    asm("{ .reg .u64 t; cvta.to.shared.u64 t, %1; cvt.u32.u64 %0, t; }" : "=r"(a) : "l"(p));
    return a;
}
__device__ __forceinline__ void cpa16(uint32_t dst, const void* src) {
    asm volatile("cp.async.cg.shared.global [%0], [%1], 16;" :: "r"(dst), "l"(src));
}
#define CP_COMMIT() asm volatile("cp.async.commit_group;" ::: "memory")
#define CP_WAIT(n)  asm volatile("cp.async.wait_group %0;" :: "n"(n) : "memory")

__device__ __forceinline__ void ldsm_x4(uint32_t a, uint32_t* r) {
    asm volatile("ldmatrix.sync.aligned.m8n8.x4.shared.b16 {%0,%1,%2,%3}, [%4];"
                 : "=r"(r[0]), "=r"(r[1]), "=r"(r[2]), "=r"(r[3]) : "r"(a));
}
__device__ __forceinline__ void mma_16816(float* d, const uint32_t* a, const uint32_t* b) {
    asm volatile("mma.sync.aligned.m16n8k16.row.col.f32.f16.f16.f32 "
                 "{%0,%1,%2,%3}, {%4,%5,%6,%7}, {%8,%9}, {%0,%1,%2,%3};"
                 : "+f"(d[0]), "+f"(d[1]), "+f"(d[2]), "+f"(d[3])
                 : "r"(a[0]), "r"(a[1]), "r"(a[2]), "r"(a[3]), "r"(b[0]), "r"(b[1]));
}

// ---------------- fp16 hi/lo split ----------------
__device__ __forceinline__ void split_h(float v, f16& h, f16& l) {
    h = __float2half_rn(v);
    l = __float2half_rn(v - __half2float(h));
}
__device__ __forceinline__ uint32_t pack_h2(float a, float b) {
    __half2 h = __floats2half2_rn(a, b);
    return *(uint32_t*)&h;
}

// ---------------- fused weight prep (one launch) ----------------
__global__ void prep_all_kernel(const float* __restrict__ Wq, const float* __restrict__ Wk,
                                const float* __restrict__ Wv, const float* __restrict__ Wp,
                                const float* __restrict__ W1, const float* __restrict__ W2,
                                f16* __restrict__ wqkv_hi, f16* __restrict__ wqkv_lo,
                                f16* __restrict__ wp_hi, f16* __restrict__ w1_hi,
                                f16* __restrict__ w2_hi) {
    int idx = blockIdx.x * blockDim.x + threadIdx.x;
    const int NQKV = QKVN * C;   // 442368
    const int NP   = C * C;      // 147456
    const int N1   = C * C4;     // 589824
    if (idx < NQKV) {
        int n = idx / C, k = idx % C;
        int m = n / C, hd = n % C;
        int h = hd / HD, d = hd % HD;
        const float* W = (m == 0) ? Wq : ((m == 1) ? Wk : Wv);
        split_h(W[(size_t)h * C * HD + (size_t)k * HD + d], wqkv_hi[idx], wqkv_lo[idx]);
        return;
    }
    idx -= NQKV;
    if (idx < NP) {
        int k = idx / C, n = idx % C;
        wp_hi[(size_t)n * C + k] = __float2half_rn(Wp[idx]);
        return;
    }
    idx -= NP;
    if (idx < N1) {
        int k = idx / C4, n = idx % C4;
        w1_hi[(size_t)n * C + k] = __float2half_rn(W1[idx]);
        return;
    }
    idx -= N1;
    if (idx < N1) {
        int k = idx / C, n = idx % C;
        w2_hi[(size_t)n * C4 + k] = __float2half_rn(W2[idx]);
    }
}
#define PREP_TOTAL (QKVN * C + C * C + 2 * C * C4)

// ---------------- layernorm: one warp per row, outputs hi (+lo optional) fp16 ----------------
__global__ void ln_kernel(const float* __restrict__ x, const float* __restrict__ g,
                          const float* __restrict__ b,
                          f16* __restrict__ out_hi, f16* __restrict__ out_lo) {
    int row  = blockIdx.x * blockDim.y + threadIdx.y;
    int lane = threadIdx.x;
    const float* xr = x + (size_t)row * C;
    float4 v[3];
    float sum = 0.f, sq = 0.f;
#pragma unroll
    for (int i = 0; i < 3; i++) {
        v[i] = *(const float4*)(xr + i * 128 + lane * 4);
        sum += v[i].x + v[i].y + v[i].z + v[i].w;
        sq  += v[i].x * v[i].x + v[i].y * v[i].y + v[i].z * v[i].z + v[i].w * v[i].w;
    }
#pragma unroll
    for (int o = 16; o; o >>= 1) {
        sum += __shfl_xor_sync(0xffffffffu, sum, o);
        sq  += __shfl_xor_sync(0xffffffffu, sq, o);
    }
    float mean = sum * (1.0f / C);
    float var  = sq * (1.0f / C) - mean * mean;
    float rstd = rsqrtf(var + 1e-5f);
    size_t rbase = (size_t)row * C;
#pragma unroll
    for (int i = 0; i < 3; i++) {
        int col = i * 128 + lane * 4;
        float4 gg = *(const float4*)(g + col);
        float4 bb = *(const float4*)(b + col);
        float o0 = (v[i].x - mean) * rstd * gg.x + bb.x;
        float o1 = (v[i].y - mean) * rstd * gg.y + bb.y;
        float o2 = (v[i].z - mean) * rstd * gg.z + bb.z;
        float o3 = (v[i].w - mean) * rstd * gg.w + bb.w;
        f16 h0, l0, h1, l1, h2, l2, h3, l3;
        split_h(o0, h0, l0); split_h(o1, h1, l1);
        split_h(o2, h2, l2); split_h(o3, h3, l3);
        *(__half2*)(out_hi + rbase + col)     = __halves2half2(h0, h1);
        *(__half2*)(out_hi + rbase + col + 2) = __halves2half2(h2, h3);
        if (out_lo) {
            *(__half2*)(out_lo + rbase + col)     = __halves2half2(l0, l1);
            *(__half2*)(out_lo + rbase + col + 2) = __halves2half2(l2, l3);
        }
    }
}

// ---------------- HMMA GEMM: 128 threads, 4 warps, warp tile 64x64 ----------------
// terms per CTA: 3 when cb < n3, else tlo (1 or 2).
// MODE 1: +bias +res, fp32 | MODE 2: +bias, relu, fp16 hi | MODE 3: fp16 hi (+lo if terms>=3)
#define BMT 128
#define BNT 128
#define BKT 32
#define STAGE_BYTES 32768
#define NSTAGE 3
#define GEMM_SMEM (NSTAGE * STAGE_BYTES)
// stage: Ahi @0, Alo @8192, Bhi @16384, Blo @24576; row = 64B (32 f16)
// 16B-chunk swizzle: chunk c of row r at c ^ ((r>>1)&3)

__device__ __forceinline__ void tile_load(uint32_t sdst, const f16* __restrict__ g,
                                          int ld, int tid) {
#pragma unroll
    for (int i = 0; i < 4; i++) {
        int id = tid + i * 128;
        int r = id >> 2, c = id & 3;
        uint32_t dst = sdst + r * 64 + ((c ^ ((r >> 1) & 3)) << 4);
        cpa16(dst, g + (size_t)r * ld + c * 8);
    }
}

__device__ __forceinline__ void compute_stage(uint32_t st, int arow, int a_kc,
                                              int bn, int b_kc, int terms,
                                              float (&acc)[4][8][4]) {
#pragma unroll
    for (int ks = 0; ks < 2; ks++) {
        const int akc = ks * 2 + a_kc;
        const int bkc = ks * 2 + b_kc;
        uint32_t a[4][4], bh[4][4], bl[4][4];
        // A_hi (4 m16 tiles)
#pragma unroll
        for (int ma = 0; ma < 4; ma++) {
            int r = arow + ma * 16;
            ldsm_x4(st + r * 64 + ((akc ^ ((r >> 1) & 3)) << 4), a[ma]);
        }
        // B_hi (4 n16 tiles = 64 cols)
#pragma unroll
        for (int p = 0; p < 4; p++) {
            int n = bn + p * 16;
            ldsm_x4(st + 16384 + n * 64 + ((bkc ^ ((n >> 1) & 3)) << 4), bh[p]);
        }
#pragma unroll
        for (int ma = 0; ma < 4; ma++)
#pragma unroll
            for (int na = 0; na < 8; na++)
                mma_16816(acc[ma][na], a[ma], &bh[na >> 1][(na & 1) * 2]);
        if (terms >= 2) {
#pragma unroll
            for (int p = 0; p < 4; p++) {
                int n = bn + p * 16;
                ldsm_x4(st + 24576 + n * 64 + ((bkc ^ ((n >> 1) & 3)) << 4), bl[p]);
            }
#pragma unroll
            for (int ma = 0; ma < 4; ma++)
#pragma unroll
                for (int na = 0; na < 8; na++)
                    mma_16816(acc[ma][na], a[ma], &bl[na >> 1][(na & 1) * 2]);
        }
        if (terms >= 3) {
#pragma unroll
            for (int ma = 0; ma < 4; ma++) {
                int r = arow + ma * 16;
                ldsm_x4(st + 8192 + r * 64 + ((akc ^ ((r >> 1) & 3)) << 4), a[ma]);
            }
#pragma unroll
            for (int ma = 0; ma < 4; ma++)
#pragma unroll
                for (int na = 0; na < 8; na++)
                    mma_16816(acc[ma][na], a[ma], &bh[na >> 1][(na & 1) * 2]);
        }
    }
}

template <int MODE>
__global__ __launch_bounds__(128, 2) void mma_gemm(
    const f16* __restrict__ Ahi, const f16* __restrict__ Alo,
    const f16* __restrict__ Bhi, const f16* __restrict__ Blo,
    const float* __restrict__ bias, const float* __restrict__ res,
    float* __restrict__ outf, f16* __restrict__ out_hi, f16* __restrict__ out_lo,
    int N, int K, int n3, int tlo)
{
    extern __shared__ char smem[];
    const uint32_t sb = smem_u32(smem);
    const int tid  = threadIdx.x;
    const int lane = tid & 31;
    const int wid  = tid >> 5;       // 0..3
    const int wm   = wid >> 1;       // 0..1
    const int wn   = wid & 1;        // 0..1
    const int cb   = blockIdx.x * BNT;
    const int rb   = blockIdx.y * BMT;
    const int NC   = K / BKT;
    const int terms = (cb < n3) ? 3 : tlo;

    const f16* Ahi_t = Ahi + (size_t)rb * K;
    const f16* Alo_t = Alo ? Alo + (size_t)rb * K : nullptr;
    const f16* Bhi_t = Bhi + (size_t)cb * K;
    const f16* Blo_t = Blo ? Blo + (size_t)cb * K : nullptr;

    float acc[4][8][4];
#pragma unroll
    for (int i = 0; i < 4; i++)
#pragma unroll
        for (int j = 0; j < 8; j++)
#pragma unroll
            for (int q = 0; q < 4; q++) acc[i][j][q] = 0.f;

    const int arow = wm * 64 + (lane & 15);
    const int a_kc = lane >> 4;
    const int bn   = wn * 64 + ((lane >> 4) << 3) + (lane & 7);
    const int b_kc = (lane >> 3) & 1;

#define ISSUE(cn, s) do {                                              \
        int _kc = (cn) * BKT;                                          \
        uint32_t _st = sb + (s) * STAGE_BYTES;                         \
        tile_load(_st,         Ahi_t + _kc, K, tid);                   \
        if (terms >= 3) tile_load(_st + 8192,  Alo_t + _kc, K, tid);   \
        tile_load(_st + 16384, Bhi_t + _kc, K, tid);                   \
        if (terms >= 2) tile_load(_st + 24576, Blo_t + _kc, K, tid);   \
        CP_COMMIT();                                                   \
    } while (0)

    ISSUE(0, 0);
    ISSUE(1, 1);

    int s = 0, s2 = 2;
    for (int c = 0; c < NC; c++) {
        if (c + 1 < NC) CP_WAIT(1); else CP_WAIT(0);
        __syncthreads();
        if (c + 2 < NC) ISSUE(c + 2, s2);
        compute_stage(sb + s * STAGE_BYTES, arow, a_kc, bn, b_kc, terms, acc);
        s  = (s == 2)  ? 0 : s + 1;
        s2 = (s2 == 2) ? 0 : s2 + 1;
    }
#undef ISSUE

    const int g  = lane >> 2;
    const int tg = lane & 3;
#pragma unroll
    for (int ma = 0; ma < 4; ma++) {
        int r0 = rb + wm * 64 + ma * 16 + g;
#pragma unroll
        for (int na = 0; na < 8; na++) {
            int col = cb + wn * 64 + na * 8 + tg * 2;
            float d0 = acc[ma][na][0], d1 = acc[ma][na][1];
            float d2 = acc[ma][na][2], d3 = acc[ma][na][3];
            if (MODE == 1 || MODE == 2) {
                float2 bb = *(const float2*)(bias + col);
                d0 += bb.x; d1 += bb.y; d2 += bb.x; d3 += bb.y;
            }
            if (MODE == 1) {
                float2 ra  = *(const float2*)(res + (size_t)r0 * N + col);
                float2 rbv = *(const float2*)(res + (size_t)(r0 + 8) * N + col);
                d0 += ra.x; d1 += ra.y; d2 += rbv.x; d3 += rbv.y;
                *(float2*)(outf + (size_t)r0 * N + col)       = make_float2(d0, d1);
                *(float2*)(outf + (size_t)(r0 + 8) * N + col) = make_float2(d2, d3);
            }
            if (MODE == 2) {
                d0 = fmaxf(d0, 0.f); d1 = fmaxf(d1, 0.f);
                d2 = fmaxf(d2, 0.f); d3 = fmaxf(d3, 0.f);
                *(__half2*)(out_hi + (size_t)r0 * N + col) =
                    __halves2half2(__float2half_rn(d0), __float2half_rn(d1));
                *(__half2*)(out_hi + (size_t)(r0 + 8) * N + col) =
                    __halves2half2(__float2half_rn(d2), __float2half_rn(d3));
            }
            if (MODE == 3) {
                f16 h0, l0, h1, l1, h2, l2, h3, l3;
                split_h(d0, h0, l0); split_h(d1, h1, l1);
                split_h(d2, h2, l2); split_h(d3, h3, l3);
                *(__half2*)(out_hi + (size_t)r0 * N + col)       = __halves2half2(h0, h1);
                *(__half2*)(out_hi + (size_t)(r0 + 8) * N + col) = __halves2half2(h2, h3);
                if (terms >= 3) {
                    *(__half2*)(out_lo + (size_t)r0 * N + col)       = __halves2half2(l0, l1);
                    *(__half2*)(out_lo + (size_t)(r0 + 8) * N + col) = __halves2half2(l2, l3);
                }
            }
        }
    }
}

// ---------------- attention: flash-v2 style HMMA, one CTA per (batch, head) ----------------
// smem: Qh/Ql/Kh/Kl [64 rows][112B stride], VT [48 rows(d)][144B stride]
#define AQH 0
#define AQL 7168
#define AKH 14336
#define AKL 21504
#define AVT 28672
#define ATTN_SMEM (28672 + 48 * 144)   // 35584

__global__ __launch_bounds__(128) void attn_mma_kernel(
    const f16* __restrict__ qkv_hi, const f16* __restrict__ qkv_lo,
    f16* __restrict__ out_hi)
{
    __shared__ __align__(16) char sm[ATTN_SMEM];
    const uint32_t sb = smem_u32(sm);
    const int bh = blockIdx.x;
    const int b  = bh >> 3;
    const int h  = bh & 7;
    const int tid  = threadIdx.x;
    const int lane = tid & 31;
    const int w    = tid >> 5;

    const f16* base_hi = qkv_hi + (size_t)b * TT * QKVN + h * HD;
    const f16* base_lo = qkv_lo + (size_t)b * TT * QKVN + h * HD;
    for (int idx = tid; idx < 64 * 24; idx += 128) {
        int t  = idx / 24;
        int c2 = (idx % 24) * 2;
        size_t go = (size_t)t * QKVN + c2;
        *(__half2*)(sm + AQH + t * 112 + c2 * 2) = *(const __half2*)(base_hi + go);
        *(__half2*)(sm + AQL + t * 112 + c2 * 2) = *(const __half2*)(base_lo + go);
        *(__half2*)(sm + AKH + t * 112 + c2 * 2) = *(const __half2*)(base_hi + go + C);
        *(__half2*)(sm + AKL + t * 112 + c2 * 2) = *(const __half2*)(base_lo + go + C);
        __half2 vv = *(const __half2*)(base_hi + go + 2 * C);
        *(f16*)(sm + AVT + c2 * 144 + t * 2)       = __low2half(vv);
        *(f16*)(sm + AVT + (c2 + 1) * 144 + t * 2) = __high2half(vv);
    }
    __syncthreads();

    const uint32_t qaddr = sb + AQH + (16 * w + (lane & 15)) * 112 + (lane >> 4) * 16;
    const uint32_t kaddr = sb + AKH + (((lane >> 4) << 3) + (lane & 7)) * 112
                              + ((lane >> 3) & 1) * 16;
    const uint32_t vaddr = sb + AVT + (((lane >> 4) << 3) + (lane & 7)) * 144
                              + ((lane >> 3) & 1) * 16;

    float s[8][4];
#pragma unroll
    for (int i = 0; i < 8; i++)
#pragma unroll
        for (int q = 0; q < 4; q++) s[i][q] = 0.f;

    for (int kt = 0; kt < 3; kt++) {
        uint32_t qh[4], ql[4];
        ldsm_x4(qaddr + kt * 32, qh);
        ldsm_x4(qaddr + (AQL - AQH) + kt * 32, ql);
        for (int nt2 = 0; nt2 <= w; nt2++) {
            uint32_t kh[4], kl[4];
            ldsm_x4(kaddr + nt2 * 1792 + kt * 32, kh);
            ldsm_x4(kaddr + (AKL - AKH) + nt2 * 1792 + kt * 32, kl);
            mma_16816(s[2 * nt2],     qh, kh);
            mma_16816(s[2 * nt2 + 1], qh, kh + 2);
            mma_16816(s[2 * nt2],     qh, kl);
            mma_16816(s[2 * nt2 + 1], qh, kl + 2);
            mma_16816(s[2 * nt2],     ql, kh);
            mma_16816(s[2 * nt2 + 1], ql, kh + 2);
        }
    }

    const int g  = lane >> 2;
    const int tq = lane & 3;
    const int r0 = 16 * w + g;
    const int r1 = r0 + 8;
    const float scl = 2.449489742783178f;   // 48 * 384^-0.5
    float mx0 = -1e30f, mx1 = -1e30f;
    const int ntmax = 2 * w + 2;
#pragma unroll
    for (int nt = 0; nt < 8; nt++) {
        if (nt >= ntmax) { s[nt][0] = s[nt][1] = s[nt][2] = s[nt][3] = 0.f; continue; }
        int c0 = nt * 8 + tq * 2, c1 = c0 + 1;
        s[nt][0] = (c0 <= r0) ? s[nt][0] * scl : -1e30f;
        s[nt][1] = (c1 <= r0) ? s[nt][1] * scl : -1e30f;
        s[nt][2] = (c0 <= r1) ? s[nt][2] * scl : -1e30f;
        s[nt][3] = (c1 <= r1) ? s[nt][3] * scl : -1e30f;
        mx0 = fmaxf(mx0, fmaxf(s[nt][0], s[nt][1]));
        mx1 = fmaxf(mx1, fmaxf(s[nt][2], s[nt][3]));
    }
    mx0 = fmaxf(mx0, __shfl_xor_sync(0xffffffffu, mx0, 1));
    mx0 = fmaxf(mx0, __shfl_xor_sync(0xffffffffu, mx0, 2));
    mx1 = fmaxf(mx1, __shfl_xor_sync(0xffffffffu, mx1, 1));
    mx1 = fmaxf(mx1, __shfl_xor_sync(0xffffffffu, mx1, 2));

    const float l2e = 1.4426950408889634f;
    float sum0 = 0.f, sum1 = 0.f;
#pragma unroll
    for (int nt = 0; nt < 8; nt++) {
        if (nt >= ntmax) continue;
        s[nt][0] = exp2f((s[nt][0] - mx0) * l2e);
        s[nt][1] = exp2f((s[nt][1] - mx0) * l2e);
        s[nt][2] = exp2f((s[nt][2] - mx1) * l2e);
        s[nt][3] = exp2f((s[nt][3] - mx1) * l2e);
        sum0 += s[nt][0] + s[nt][1];
        sum1 += s[nt][2] + s[nt][3];
    }
    sum0 += __shfl_xor_sync(0xffffffffu, sum0, 1);
    sum0 += __shfl_xor_sync(0xffffffffu, sum0, 2);
    sum1 += __shfl_xor_sync(0xffffffffu, sum1, 1);
    sum1 += __shfl_xor_sync(0xffffffffu, sum1, 2);
    const float inv0 = 1.f / sum0, inv1 = 1.f / sum1;

    uint32_t ap[4][4];
    for (int kt = 0; kt <= w; kt++) {
        ap[kt][0] = pack_h2(s[2 * kt][0] * inv0,     s[2 * kt][1] * inv0);
        ap[kt][1] = pack_h2(s[2 * kt][2] * inv1,     s[2 * kt][3] * inv1);
        ap[kt][2] = pack_h2(s[2 * kt + 1][0] * inv0, s[2 * kt + 1][1] * inv0);
        ap[kt][3] = pack_h2(s[2 * kt + 1][2] * inv1, s[2 * kt + 1][3] * inv1);
    }

    float o[6][4];
#pragma unroll
    for (int i = 0; i < 6; i++)
#pragma unroll
        for (int q = 0; q < 4; q++) o[i][q] = 0.f;
    for (int kt = 0; kt <= w; kt++) {
        for (int nt2 = 0; nt2 < 3; nt2++) {
            uint32_t vb[4];
            ldsm_x4(vaddr + nt2 * 2304 + kt * 32, vb);
            mma_16816(o[2 * nt2],     ap[kt], vb);
            mma_16816(o[2 * nt2 + 1], ap[kt], vb + 2);
        }
    }

    f16* op = out_hi + (size_t)b * TT * C + h * HD;
#pragma unroll
    for (int nt = 0; nt < 6; nt++) {
        int d = nt * 8 + tq * 2;
        *(__half2*)(op + (size_t)r0 * C + d) = __floats2half2_rn(o[nt][0], o[nt][1]);
        *(__half2*)(op + (size_t)r1 * C + d) = __floats2half2_rn(o[nt][2], o[nt][3]);
    }
}

// ---------------- launch ----------------
extern "C" void kernel_launch(void* const* d_in, const int* in_sizes, int n_in,
                              void* d_out, int out_size) {
    const float* x     = (const float*)d_in[0];
    const float* ln1_g = (const float*)d_in[1];
    const float* ln1_b = (const float*)d_in[2];
    const float* ln2_g = (const float*)d_in[3];
    const float* ln2_b = (const float*)d_in[4];
    const float* Wq    = (const float*)d_in[5];
    const float* Wk    = (const float*)d_in[6];
    const float* Wv    = (const float*)d_in[7];
    const float* Wp    = (const float*)d_in[8];
    const float* bp    = (const float*)d_in[9];
    const float* W1    = (const float*)d_in[10];
    const float* b1    = (const float*)d_in[11];
    const float* W2    = (const float*)d_in[12];
    const float* b2    = (const float*)d_in[13];
    float* out = (float*)d_out;

    f16 *ph_hi, *ph_lo, *pqkv_hi, *pqkv_lo, *pattn_hi, *phid_hi;
    f16 *pwqkv_hi, *pwqkv_lo, *pwp_hi, *pw1_hi, *pw2_hi;
    float *px2;
    cudaGetSymbolAddress((void**)&ph_hi, g_h_hi);     cudaGetSymbolAddress((void**)&ph_lo, g_h_lo);
    cudaGetSymbolAddress((void**)&pqkv_hi, g_qkv_hi); cudaGetSymbolAddress((void**)&pqkv_lo, g_qkv_lo);
    cudaGetSymbolAddress((void**)&pattn_hi, g_attn_hi);
    cudaGetSymbolAddress((void**)&px2, g_x2);
    cudaGetSymbolAddress((void**)&phid_hi, g_hid_hi);
    cudaGetSymbolAddress((void**)&pwqkv_hi, g_wqkv_hi); cudaGetSymbolAddress((void**)&pwqkv_lo, g_wqkv_lo);
    cudaGetSymbolAddress((void**)&pwp_hi, g_wp_hi);
    cudaGetSymbolAddress((void**)&pw1_hi, g_w1_hi);
    cudaGetSymbolAddress((void**)&pw2_hi, g_w2_hi);

    static int attr_set = 0;
    if (!attr_set) {
        cudaFuncSetAttribute(mma_gemm<1>, cudaFuncAttributeMaxDynamicSharedMemorySize, GEMM_SMEM);
        cudaFuncSetAttribute(mma_gemm<2>, cudaFuncAttributeMaxDynamicSharedMemorySize, GEMM_SMEM);
        cudaFuncSetAttribute(mma_gemm<3>, cudaFuncAttributeMaxDynamicSharedMemorySize, GEMM_SMEM);
        attr_set = 1;
    }

    // fused weight prep (single launch)
    prep_all_kernel<<<(PREP_TOTAL + 255) / 256, 256>>>(
        Wq, Wk, Wv, Wp, W1, W2, pwqkv_hi, pwqkv_lo, pwp_hi, pw1_hi, pw2_hi);

    // LN1 (hi+lo: q,k GEMM is 3-term)
    ln_kernel<<<BT / 8, dim3(32, 8)>>>(x, ln1_g, ln1_b, ph_hi, ph_lo);
    // QKV: q,k cols 3-term -> fp16 hi/lo; v cols 1-term -> fp16 hi
    mma_gemm<3><<<dim3(QKVN / 128, BT / 128), 128, GEMM_SMEM>>>(
        ph_hi, ph_lo, pwqkv_hi, pwqkv_lo, nullptr, nullptr, nullptr, pqkv_hi, pqkv_lo,
        QKVN, C, 2 * C, 1);
    // attention (HMMA flash-style)
    attn_mma_kernel<<<BATCH * NH, 128>>>(pqkv_hi, pqkv_lo, pattn_hi);
    // proj + bias + residual -> x2 (1-term)
    mma_gemm<1><<<dim3(C / 128, BT / 128), 128, GEMM_SMEM>>>(
        pattn_hi, nullptr, pwp_hi, nullptr, bp, x, px2, nullptr, nullptr, C, C, 0, 1);
    // LN2 (hi only)
    ln_kernel<<<BT / 8, dim3(32, 8)>>>(px2, ln2_g, ln2_b, ph_hi, nullptr);
    // FFN1 + bias + relu -> hidden hi (1-term)
    mma_gemm<2><<<dim3(C4 / 128, BT / 128), 128, GEMM_SMEM>>>(
        ph_hi, nullptr, pw1_hi, nullptr, b1, nullptr, nullptr, phid_hi, nullptr,
        C4, C, 0, 1);
    // FFN2 + bias + residual -> out (1-term)
    mma_gemm<1><<<dim3(C / 128, BT / 128), 128, GEMM_SMEM>>>(
        phid_hi, nullptr, pw2_hi, nullptr, b2, px2, out, nullptr, nullptr, C, C4, 0, 1);
}

// round 11
// speedup vs baseline: 5.9521x; 1.0730x over previous
#include <cuda_runtime.h>
#include <cuda_fp16.h>
#include <math.h>
#include <stdint.h>

// ---------------- problem constants ----------------
#define BATCH   2048
#define TT      64
#define BT      (BATCH * TT)      // 131072 rows
#define C       384
#define NH      8
#define HD      48
#define C4      1536
#define QKVN    1152

typedef __half f16;

// ---------------- device scratch ----------------
__device__ __align__(256) f16   g_h_hi[BT * C],   g_h_lo[BT * C];
__device__ __align__(256) f16   g_qkv_hi[BT * QKVN], g_qkv_lo[BT * QKVN];
__device__ __align__(256) f16   g_attn_hi[BT * C];
__device__ __align__(256) float g_x2[BT * C];
__device__ __align__(256) f16   g_hid_hi[BT * C4];
__device__ __align__(256) f16   g_wqkv_hi[QKVN * C], g_wqkv_lo[QKVN * C];
__device__ __align__(256) f16   g_wp_hi[C * C];
__device__ __align__(256) f16   g_w1_hi[C4 * C];
__device__ __align__(256) f16   g_w2_hi[C * C4];

// ---------------- PTX helpers (base-arch only) ----------------
__device__ __forceinline__ uint32_t smem_u32(const void* p) {
    uint32_t a;
    asm("{ .reg .u64 t; cvta.to.shared.u64 t, %1; cvt.u32.u64 %0, t; }" : "=r"(a) : "l"(p));
    return a;
}
__device__ __forceinline__ void cpa16(uint32_t dst, const void* src) {
    asm volatile("cp.async.cg.shared.global [%0], [%1], 16;" :: "r"(dst), "l"(src));
}
#define CP_COMMIT() asm volatile("cp.async.commit_group;" ::: "memory")
#define CP_WAIT(n)  asm volatile("cp.async.wait_group %0;" :: "n"(n) : "memory")

__device__ __forceinline__ void ldsm_x4(uint32_t a, uint32_t* r) {
    asm volatile("ldmatrix.sync.aligned.m8n8.x4.shared.b16 {%0,%1,%2,%3}, [%4];"
                 : "=r"(r[0]), "=r"(r[1]), "=r"(r[2]), "=r"(r[3]) : "r"(a));
}
__device__ __forceinline__ void mma_16816(float* d, const uint32_t* a, const uint32_t* b) {
    asm volatile("mma.sync.aligned.m16n8k16.row.col.f32.f16.f16.f32 "
                 "{%0,%1,%2,%3}, {%4,%5,%6,%7}, {%8,%9}, {%0,%1,%2,%3};"
                 : "+f"(d[0]), "+f"(d[1]), "+f"(d[2]), "+f"(d[3])
                 : "r"(a[0]), "r"(a[1]), "r"(a[2]), "r"(a[3]), "r"(b[0]), "r"(b[1]));
}

// ---------------- fp16 hi/lo split ----------------
__device__ __forceinline__ void split_h(float v, f16& h, f16& l) {
    h = __float2half_rn(v);
    l = __float2half_rn(v - __half2float(h));
}
__device__ __forceinline__ uint32_t pack_h2(float a, float b) {
    __half2 h = __floats2half2_rn(a, b);
    return *(uint32_t*)&h;
}

// ---------------- fused weight prep (one launch) ----------------
__global__ void prep_all_kernel(const float* __restrict__ Wq, const float* __restrict__ Wk,
                                const float* __restrict__ Wv, const float* __restrict__ Wp,
                                const float* __restrict__ W1, const float* __restrict__ W2,
                                f16* __restrict__ wqkv_hi, f16* __restrict__ wqkv_lo,
                                f16* __restrict__ wp_hi, f16* __restrict__ w1_hi,
                                f16* __restrict__ w2_hi) {
    int idx = blockIdx.x * blockDim.x + threadIdx.x;
    const int NQKV = QKVN * C;
    const int NP   = C * C;
    const int N1   = C * C4;
    if (idx < NQKV) {
        int n = idx / C, k = idx % C;
        int m = n / C, hd = n % C;
        int h = hd / HD, d = hd % HD;
        const float* W = (m == 0) ? Wq : ((m == 1) ? Wk : Wv);
        split_h(W[(size_t)h * C * HD + (size_t)k * HD + d], wqkv_hi[idx], wqkv_lo[idx]);
        return;
    }
    idx -= NQKV;
    if (idx < NP) {
        int k = idx / C, n = idx % C;
        wp_hi[(size_t)n * C + k] = __float2half_rn(Wp[idx]);
        return;
    }
    idx -= NP;
    if (idx < N1) {
        int k = idx / C4, n = idx % C4;
        w1_hi[(size_t)n * C + k] = __float2half_rn(W1[idx]);
        return;
    }
    idx -= N1;
    if (idx < N1) {
        int k = idx / C, n = idx % C;
        w2_hi[(size_t)n * C4 + k] = __float2half_rn(W2[idx]);
    }
}
#define PREP_TOTAL (QKVN * C + C * C + 2 * C * C4)

// ---------------- layernorm: one warp per row, outputs hi (+lo optional) fp16 ----------------
__global__ void ln_kernel(const float* __restrict__ x, const float* __restrict__ g,
                          const float* __restrict__ b,
                          f16* __restrict__ out_hi, f16* __restrict__ out_lo) {
    int row  = blockIdx.x * blockDim.y + threadIdx.y;
    int lane = threadIdx.x;
    const float* xr = x + (size_t)row * C;
    float4 v[3];
    float sum = 0.f, sq = 0.f;
#pragma unroll
    for (int i = 0; i < 3; i++) {
        v[i] = *(const float4*)(xr + i * 128 + lane * 4);
        sum += v[i].x + v[i].y + v[i].z + v[i].w;
        sq  += v[i].x * v[i].x + v[i].y * v[i].y + v[i].z * v[i].z + v[i].w * v[i].w;
    }
#pragma unroll
    for (int o = 16; o; o >>= 1) {
        sum += __shfl_xor_sync(0xffffffffu, sum, o);
        sq  += __shfl_xor_sync(0xffffffffu, sq, o);
    }
    float mean = sum * (1.0f / C);
    float var  = sq * (1.0f / C) - mean * mean;
    float rstd = rsqrtf(var + 1e-5f);
    size_t rbase = (size_t)row * C;
#pragma unroll
    for (int i = 0; i < 3; i++) {
        int col = i * 128 + lane * 4;
        float4 gg = *(const float4*)(g + col);
        float4 bb = *(const float4*)(b + col);
        float o0 = (v[i].x - mean) * rstd * gg.x + bb.x;
        float o1 = (v[i].y - mean) * rstd * gg.y + bb.y;
        float o2 = (v[i].z - mean) * rstd * gg.z + bb.z;
        float o3 = (v[i].w - mean) * rstd * gg.w + bb.w;
        f16 h0, l0, h1, l1, h2, l2, h3, l3;
        split_h(o0, h0, l0); split_h(o1, h1, l1);
        split_h(o2, h2, l2); split_h(o3, h3, l3);
        *(__half2*)(out_hi + rbase + col)     = __halves2half2(h0, h1);
        *(__half2*)(out_hi + rbase + col + 2) = __halves2half2(h2, h3);
        if (out_lo) {
            *(__half2*)(out_lo + rbase + col)     = __halves2half2(l0, l1);
            *(__half2*)(out_lo + rbase + col + 2) = __halves2half2(l2, l3);
        }
    }
}

// ---------------- HMMA GEMM: 128 threads, 4 warps, warp tile 64x64 ----------------
// BK = 32: full hi/lo layout (stage: Ahi@0, Alo@8192, Bhi@16384, Blo@24576; 64B rows,
//          swizzle c^((r>>1)&3), c in 0..3)
// BK = 64: 1-term only (stage: Ahi@0 16K, Bhi@16384 16K; 128B rows, swizzle c^(r&7), c 0..7)
// terms per CTA: 3 when cb < n3, else tlo.
// MODE 1: +bias +res, fp32 | MODE 2: +bias, relu, fp16 hi | MODE 3: fp16 hi (+lo if 3-term)
#define BMT 128
#define BNT 128
#define STAGE_BYTES 32768
#define NSTAGE 3
#define GEMM_SMEM (NSTAGE * STAGE_BYTES)

template <int BK>
__device__ __forceinline__ uint32_t sw_off(int r, int c) {
    if (BK == 32) return (uint32_t)(r * 64  + ((c ^ ((r >> 1) & 3)) << 4));
    else          return (uint32_t)(r * 128 + ((c ^ (r & 7)) << 4));
}

template <int BK>
__device__ __forceinline__ void tile_load(uint32_t sdst, const f16* __restrict__ g,
                                          int ld, int tid) {
    if (BK == 32) {
#pragma unroll
        for (int i = 0; i < 4; i++) {
            int id = tid + i * 128;
            int r = id >> 2, c = id & 3;
            cpa16(sdst + sw_off<32>(r, c), g + (size_t)r * ld + c * 8);
        }
    } else {
#pragma unroll
        for (int i = 0; i < 8; i++) {
            int id = tid + i * 128;
            int r = id >> 3, c = id & 7;
            cpa16(sdst + sw_off<64>(r, c), g + (size_t)r * ld + c * 8);
        }
    }
}

// NOTE: A fragments use a_kc = lane>>4; B fragments use b_kc = (lane>>3)&1.
// (Round-10 bug: collapsing these broke the B ldsm geometry.)
template <int BK>
__device__ __forceinline__ void compute_stage(uint32_t st, int arow, int a_kc,
                                              int bn, int b_kc, int terms,
                                              float (&acc)[4][8][4]) {
#pragma unroll
    for (int ks = 0; ks < BK / 16; ks++) {
        const int akc = ks * 2 + a_kc;
        const int bkc = ks * 2 + b_kc;
        uint32_t a[4][4], bh[4][4], bl[4][4];
#pragma unroll
        for (int ma = 0; ma < 4; ma++) {
            int r = arow + ma * 16;
            ldsm_x4(st + sw_off<BK>(r, akc), a[ma]);
        }
#pragma unroll
        for (int p = 0; p < 4; p++) {
            int n = bn + p * 16;
            ldsm_x4(st + 16384 + sw_off<BK>(n, bkc), bh[p]);
        }
#pragma unroll
        for (int ma = 0; ma < 4; ma++)
#pragma unroll
            for (int na = 0; na < 8; na++)
                mma_16816(acc[ma][na], a[ma], &bh[na >> 1][(na & 1) * 2]);
        if (BK == 32 && terms >= 2) {
#pragma unroll
            for (int p = 0; p < 4; p++) {
                int n = bn + p * 16;
                ldsm_x4(st + 24576 + sw_off<32>(n, bkc), bl[p]);
            }
#pragma unroll
            for (int ma = 0; ma < 4; ma++)
#pragma unroll
                for (int na = 0; na < 8; na++)
                    mma_16816(acc[ma][na], a[ma], &bl[na >> 1][(na & 1) * 2]);
        }
        if (BK == 32 && terms >= 3) {
#pragma unroll
            for (int ma = 0; ma < 4; ma++) {
                int r = arow + ma * 16;
                ldsm_x4(st + 8192 + sw_off<32>(r, akc), a[ma]);
            }
#pragma unroll
            for (int ma = 0; ma < 4; ma++)
#pragma unroll
                for (int na = 0; na < 8; na++)
                    mma_16816(acc[ma][na], a[ma], &bh[na >> 1][(na & 1) * 2]);
        }
    }
}

template <int MODE, int BK>
__global__ __launch_bounds__(128, 2) void mma_gemm(
    const f16* __restrict__ Ahi, const f16* __restrict__ Alo,
    const f16* __restrict__ Bhi, const f16* __restrict__ Blo,
    const float* __restrict__ bias, const float* __restrict__ res,
    float* __restrict__ outf, f16* __restrict__ out_hi, f16* __restrict__ out_lo,
    int N, int K, int n3, int tlo)
{
    extern __shared__ char smem[];
    const uint32_t sb = smem_u32(smem);
    const int tid  = threadIdx.x;
    const int lane = tid & 31;
    const int wid  = tid >> 5;
    const int wm   = wid >> 1;
    const int wn   = wid & 1;
    const int cb   = blockIdx.x * BNT;
    const int rb   = blockIdx.y * BMT;
    const int NC   = K / BK;
    const int terms = (cb < n3) ? 3 : tlo;

    const f16* Ahi_t = Ahi + (size_t)rb * K;
    const f16* Alo_t = Alo ? Alo + (size_t)rb * K : nullptr;
    const f16* Bhi_t = Bhi + (size_t)cb * K;
    const f16* Blo_t = Blo ? Blo + (size_t)cb * K : nullptr;

    float acc[4][8][4];
#pragma unroll
    for (int i = 0; i < 4; i++)
#pragma unroll
        for (int j = 0; j < 8; j++)
#pragma unroll
            for (int q = 0; q < 4; q++) acc[i][j][q] = 0.f;

    const int arow = wm * 64 + (lane & 15);
    const int a_kc = lane >> 4;
    const int bn   = wn * 64 + ((lane >> 4) << 3) + (lane & 7);
    const int b_kc = (lane >> 3) & 1;

#define ISSUE(cn, s) do {                                                  \
        int _kc = (cn) * BK;                                               \
        uint32_t _st = sb + (s) * STAGE_BYTES;                             \
        tile_load<BK>(_st, Ahi_t + _kc, K, tid);                           \
        if (BK == 32 && terms >= 3) tile_load<32>(_st + 8192,  Alo_t + _kc, K, tid); \
        tile_load<BK>(_st + 16384, Bhi_t + _kc, K, tid);                   \
        if (BK == 32 && terms >= 2) tile_load<32>(_st + 24576, Blo_t + _kc, K, tid); \
        CP_COMMIT();                                                       \
    } while (0)

    ISSUE(0, 0);
    ISSUE(1, 1);

    int s = 0, s2 = 2;
    for (int c = 0; c < NC; c++) {
        if (c + 1 < NC) CP_WAIT(1); else CP_WAIT(0);
        __syncthreads();
        if (c + 2 < NC) ISSUE(c + 2, s2);
        compute_stage<BK>(sb + s * STAGE_BYTES, arow, a_kc, bn, b_kc, terms, acc);
        s  = (s == 2)  ? 0 : s + 1;
        s2 = (s2 == 2) ? 0 : s2 + 1;
    }
#undef ISSUE

    const int g  = lane >> 2;
    const int tg = lane & 3;
#pragma unroll
    for (int ma = 0; ma < 4; ma++) {
        int r0 = rb + wm * 64 + ma * 16 + g;
#pragma unroll
        for (int na = 0; na < 8; na++) {
            int col = cb + wn * 64 + na * 8 + tg * 2;
            float d0 = acc[ma][na][0], d1 = acc[ma][na][1];
            float d2 = acc[ma][na][2], d3 = acc[ma][na][3];
            if (MODE == 1 || MODE == 2) {
                float2 bb = *(const float2*)(bias + col);
                d0 += bb.x; d1 += bb.y; d2 += bb.x; d3 += bb.y;
            }
            if (MODE == 1) {
                float2 ra  = *(const float2*)(res + (size_t)r0 * N + col);
                float2 rbv = *(const float2*)(res + (size_t)(r0 + 8) * N + col);
                d0 += ra.x; d1 += ra.y; d2 += rbv.x; d3 += rbv.y;
                *(float2*)(outf + (size_t)r0 * N + col)       = make_float2(d0, d1);
                *(float2*)(outf + (size_t)(r0 + 8) * N + col) = make_float2(d2, d3);
            }
            if (MODE == 2) {
                d0 = fmaxf(d0, 0.f); d1 = fmaxf(d1, 0.f);
                d2 = fmaxf(d2, 0.f); d3 = fmaxf(d3, 0.f);
                *(__half2*)(out_hi + (size_t)r0 * N + col) =
                    __halves2half2(__float2half_rn(d0), __float2half_rn(d1));
                *(__half2*)(out_hi + (size_t)(r0 + 8) * N + col) =
                    __halves2half2(__float2half_rn(d2), __float2half_rn(d3));
            }
            if (MODE == 3) {
                f16 h0, l0, h1, l1, h2, l2, h3, l3;
                split_h(d0, h0, l0); split_h(d1, h1, l1);
                split_h(d2, h2, l2); split_h(d3, h3, l3);
                *(__half2*)(out_hi + (size_t)r0 * N + col)       = __halves2half2(h0, h1);
                *(__half2*)(out_hi + (size_t)(r0 + 8) * N + col) = __halves2half2(h2, h3);
                if (terms >= 3) {
                    *(__half2*)(out_lo + (size_t)r0 * N + col)       = __halves2half2(l0, l1);
                    *(__half2*)(out_lo + (size_t)(r0 + 8) * N + col) = __halves2half2(l2, l3);
                }
            }
        }
    }
}

// ---------------- attention: flash-v2 style HMMA, one CTA per (batch, head) ----------------
// smem: Kh [64][112B], Kl [64][112B], VT [48][144B]; Q fragments loaded direct from GMEM
#define AKH 0
#define AKL 7168
#define AVT 14336
#define ATTN_SMEM (14336 + 48 * 144)   // 21248

__global__ __launch_bounds__(128, 8) void attn_mma_kernel(
    const f16* __restrict__ qkv_hi, const f16* __restrict__ qkv_lo,
    f16* __restrict__ out_hi)
{
    __shared__ __align__(16) char sm[ATTN_SMEM];
    const uint32_t sb = smem_u32(sm);
    const int bh = blockIdx.x;
    const int b  = bh >> 3;
    const int h  = bh & 7;
    const int tid  = threadIdx.x;
    const int lane = tid & 31;
    const int w    = tid >> 5;

    const f16* base_hi = qkv_hi + (size_t)b * TT * QKVN + h * HD;
    const f16* base_lo = qkv_lo + (size_t)b * TT * QKVN + h * HD;
    // cooperative load: k hi/lo -> padded smem; v -> transposed smem
    for (int idx = tid; idx < 64 * 24; idx += 128) {
        int t  = idx / 24;
        int c2 = (idx % 24) * 2;
        size_t go = (size_t)t * QKVN + c2;
        *(__half2*)(sm + AKH + t * 112 + c2 * 2) = *(const __half2*)(base_hi + go + C);
        *(__half2*)(sm + AKL + t * 112 + c2 * 2) = *(const __half2*)(base_lo + go + C);
        __half2 vv = *(const __half2*)(base_hi + go + 2 * C);
        *(f16*)(sm + AVT + c2 * 144 + t * 2)       = __low2half(vv);
        *(f16*)(sm + AVT + (c2 + 1) * 144 + t * 2) = __high2half(vv);
    }
    __syncthreads();

    const int g  = lane >> 2;
    const int tq = lane & 3;
    const uint32_t kaddr = sb + AKH + (((lane >> 4) << 3) + (lane & 7)) * 112
                              + ((lane >> 3) & 1) * 16;
    const uint32_t vaddr = sb + AVT + (((lane >> 4) << 3) + (lane & 7)) * 144
                              + ((lane >> 3) & 1) * 16;
    // direct-GMEM q fragment base (a-frag m16k16 layout)
    const f16* q0_hi = base_hi + (size_t)(16 * w + g) * QKVN + 2 * tq;
    const f16* q0_lo = base_lo + (size_t)(16 * w + g) * QKVN + 2 * tq;

    float s[8][4];
#pragma unroll
    for (int i = 0; i < 8; i++)
#pragma unroll
        for (int q = 0; q < 4; q++) s[i][q] = 0.f;

    for (int kt = 0; kt < 3; kt++) {
        uint32_t qh[4], ql[4];
        qh[0] = *(const uint32_t*)(q0_hi + kt * 16);
        qh[1] = *(const uint32_t*)(q0_hi + 8 * QKVN + kt * 16);
        qh[2] = *(const uint32_t*)(q0_hi + kt * 16 + 8);
        qh[3] = *(const uint32_t*)(q0_hi + 8 * QKVN + kt * 16 + 8);
        ql[0] = *(const uint32_t*)(q0_lo + kt * 16);
        ql[1] = *(const uint32_t*)(q0_lo + 8 * QKVN + kt * 16);
        ql[2] = *(const uint32_t*)(q0_lo + kt * 16 + 8);
        ql[3] = *(const uint32_t*)(q0_lo + 8 * QKVN + kt * 16 + 8);
        for (int nt2 = 0; nt2 <= w; nt2++) {
            uint32_t kh[4], kl[4];
            ldsm_x4(kaddr + nt2 * 1792 + kt * 32, kh);
            ldsm_x4(kaddr + (AKL - AKH) + nt2 * 1792 + kt * 32, kl);
            mma_16816(s[2 * nt2],     qh, kh);
            mma_16816(s[2 * nt2 + 1], qh, kh + 2);
            mma_16816(s[2 * nt2],     qh, kl);
            mma_16816(s[2 * nt2 + 1], qh, kl + 2);
            mma_16816(s[2 * nt2],     ql, kh);
            mma_16816(s[2 * nt2 + 1], ql, kh + 2);
        }
    }

    const int r0 = 16 * w + g;
    const int r1 = r0 + 8;
    const float scl = 2.449489742783178f;   // 48 * 384^-0.5
    float mx0 = -1e30f, mx1 = -1e30f;
    const int ntmax = 2 * w + 2;
#pragma unroll
    for (int nt = 0; nt < 8; nt++) {
        if (nt >= ntmax) { s[nt][0] = s[nt][1] = s[nt][2] = s[nt][3] = 0.f; continue; }
        int c0 = nt * 8 + tq * 2, c1 = c0 + 1;
        s[nt][0] = (c0 <= r0) ? s[nt][0] * scl : -1e30f;
        s[nt][1] = (c1 <= r0) ? s[nt][1] * scl : -1e30f;
        s[nt][2] = (c0 <= r1) ? s[nt][2] * scl : -1e30f;
        s[nt][3] = (c1 <= r1) ? s[nt][3] * scl : -1e30f;
        mx0 = fmaxf(mx0, fmaxf(s[nt][0], s[nt][1]));
        mx1 = fmaxf(mx1, fmaxf(s[nt][2], s[nt][3]));
    }
    mx0 = fmaxf(mx0, __shfl_xor_sync(0xffffffffu, mx0, 1));
    mx0 = fmaxf(mx0, __shfl_xor_sync(0xffffffffu, mx0, 2));
    mx1 = fmaxf(mx1, __shfl_xor_sync(0xffffffffu, mx1, 1));
    mx1 = fmaxf(mx1, __shfl_xor_sync(0xffffffffu, mx1, 2));

    const float l2e = 1.4426950408889634f;
    float sum0 = 0.f, sum1 = 0.f;
#pragma unroll
    for (int nt = 0; nt < 8; nt++) {
        if (nt >= ntmax) continue;
        s[nt][0] = exp2f((s[nt][0] - mx0) * l2e);
        s[nt][1] = exp2f((s[nt][1] - mx0) * l2e);
        s[nt][2] = exp2f((s[nt][2] - mx1) * l2e);
        s[nt][3] = exp2f((s[nt][3] - mx1) * l2e);
        sum0 += s[nt][0] + s[nt][1];
        sum1 += s[nt][2] + s[nt][3];
    }
    sum0 += __shfl_xor_sync(0xffffffffu, sum0, 1);
    sum0 += __shfl_xor_sync(0xffffffffu, sum0, 2);
    sum1 += __shfl_xor_sync(0xffffffffu, sum1, 1);
    sum1 += __shfl_xor_sync(0xffffffffu, sum1, 2);
    const float inv0 = 1.f / sum0, inv1 = 1.f / sum1;

    uint32_t ap[4][4];
    for (int kt = 0; kt <= w; kt++) {
        ap[kt][0] = pack_h2(s[2 * kt][0] * inv0,     s[2 * kt][1] * inv0);
        ap[kt][1] = pack_h2(s[2 * kt][2] * inv1,     s[2 * kt][3] * inv1);
        ap[kt][2] = pack_h2(s[2 * kt + 1][0] * inv0, s[2 * kt + 1][1] * inv0);
        ap[kt][3] = pack_h2(s[2 * kt + 1][2] * inv1, s[2 * kt + 1][3] * inv1);
    }

    float o[6][4];
#pragma unroll
    for (int i = 0; i < 6; i++)
#pragma unroll
        for (int q = 0; q < 4; q++) o[i][q] = 0.f;
    for (int kt = 0; kt <= w; kt++) {
        for (int nt2 = 0; nt2 < 3; nt2++) {
            uint32_t vb[4];
            ldsm_x4(vaddr + nt2 * 2304 + kt * 32, vb);
            mma_16816(o[2 * nt2],     ap[kt], vb);
            mma_16816(o[2 * nt2 + 1], ap[kt], vb + 2);
        }
    }

    f16* op = out_hi + (size_t)b * TT * C + h * HD;
#pragma unroll
    for (int nt = 0; nt < 6; nt++) {
        int d = nt * 8 + tq * 2;
        *(__half2*)(op + (size_t)r0 * C + d) = __floats2half2_rn(o[nt][0], o[nt][1]);
        *(__half2*)(op + (size_t)r1 * C + d) = __floats2half2_rn(o[nt][2], o[nt][3]);
    }
}

// ---------------- launch ----------------
extern "C" void kernel_launch(void* const* d_in, const int* in_sizes, int n_in,
                              void* d_out, int out_size) {
    const float* x     = (const float*)d_in[0];
    const float* ln1_g = (const float*)d_in[1];
    const float* ln1_b = (const float*)d_in[2];
    const float* ln2_g = (const float*)d_in[3];
    const float* ln2_b = (const float*)d_in[4];
    const float* Wq    = (const float*)d_in[5];
    const float* Wk    = (const float*)d_in[6];
    const float* Wv    = (const float*)d_in[7];
    const float* Wp    = (const float*)d_in[8];
    const float* bp    = (const float*)d_in[9];
    const float* W1    = (const float*)d_in[10];
    const float* b1    = (const float*)d_in[11];
    const float* W2    = (const float*)d_in[12];
    const float* b2    = (const float*)d_in[13];
    float* out = (float*)d_out;

    f16 *ph_hi, *ph_lo, *pqkv_hi, *pqkv_lo, *pattn_hi, *phid_hi;
    f16 *pwqkv_hi, *pwqkv_lo, *pwp_hi, *pw1_hi, *pw2_hi;
    float *px2;
    cudaGetSymbolAddress((void**)&ph_hi, g_h_hi);     cudaGetSymbolAddress((void**)&ph_lo, g_h_lo);
    cudaGetSymbolAddress((void**)&pqkv_hi, g_qkv_hi); cudaGetSymbolAddress((void**)&pqkv_lo, g_qkv_lo);
    cudaGetSymbolAddress((void**)&pattn_hi, g_attn_hi);
    cudaGetSymbolAddress((void**)&px2, g_x2);
    cudaGetSymbolAddress((void**)&phid_hi, g_hid_hi);
    cudaGetSymbolAddress((void**)&pwqkv_hi, g_wqkv_hi); cudaGetSymbolAddress((void**)&pwqkv_lo, g_wqkv_lo);
    cudaGetSymbolAddress((void**)&pwp_hi, g_wp_hi);
    cudaGetSymbolAddress((void**)&pw1_hi, g_w1_hi);
    cudaGetSymbolAddress((void**)&pw2_hi, g_w2_hi);

    static int attr_set = 0;
    if (!attr_set) {
        cudaFuncSetAttribute((const void*)mma_gemm<3,32>, cudaFuncAttributeMaxDynamicSharedMemorySize, GEMM_SMEM);
        cudaFuncSetAttribute((const void*)mma_gemm<1,64>, cudaFuncAttributeMaxDynamicSharedMemorySize, GEMM_SMEM);
        cudaFuncSetAttribute((const void*)mma_gemm<2,64>, cudaFuncAttributeMaxDynamicSharedMemorySize, GEMM_SMEM);
        attr_set = 1;
    }

    // fused weight prep
    prep_all_kernel<<<(PREP_TOTAL + 255) / 256, 256>>>(
        Wq, Wk, Wv, Wp, W1, W2, pwqkv_hi, pwqkv_lo, pwp_hi, pw1_hi, pw2_hi);

    // LN1 (hi+lo: q,k GEMM is 3-term)
    ln_kernel<<<BT / 8, dim3(32, 8)>>>(x, ln1_g, ln1_b, ph_hi, ph_lo);
    // QKV (BK=32): q,k cols 3-term -> fp16 hi/lo; v cols 1-term -> fp16 hi
    mma_gemm<3,32><<<dim3(QKVN / 128, BT / 128), 128, GEMM_SMEM>>>(
        ph_hi, ph_lo, pwqkv_hi, pwqkv_lo, nullptr, nullptr, nullptr, pqkv_hi, pqkv_lo,
        QKVN, C, 2 * C, 1);
    // attention (HMMA flash-style, direct-GMEM Q fragments)
    attn_mma_kernel<<<BATCH * NH, 128>>>(pqkv_hi, pqkv_lo, pattn_hi);
    // proj + bias + residual -> x2 (1-term, BK=64)
    mma_gemm<1,64><<<dim3(C / 128, BT / 128), 128, GEMM_SMEM>>>(
        pattn_hi, nullptr, pwp_hi, nullptr, bp, x, px2, nullptr, nullptr, C, C, 0, 1);
    // LN2 (hi only)
    ln_kernel<<<BT / 8, dim3(32, 8)>>>(px2, ln2_g, ln2_b, ph_hi, nullptr);
    // FFN1 + bias + relu -> hidden hi (1-term, BK=64)
    mma_gemm<2,64><<<dim3(C4 / 128, BT / 128), 128, GEMM_SMEM>>>(
        ph_hi, nullptr, pw1_hi, nullptr, b1, nullptr, nullptr, phid_hi, nullptr,
        C4, C, 0, 1);
    // FFN2 + bias + residual -> out (1-term, BK=64)
    mma_gemm<1,64><<<dim3(C / 128, BT / 128), 128, GEMM_SMEM>>>(
        phid_hi, nullptr, pw2_hi, nullptr, b2, px2, out, nullptr, nullptr, C, C4, 0, 1);
}

// round 13
// speedup vs baseline: 6.1646x; 1.0357x over previous
#include <cuda_runtime.h>
#include <cuda_fp16.h>
#include <math.h>
#include <stdint.h>

// ---------------- problem constants ----------------
#define BATCH   2048
#define TT      64
#define BT      (BATCH * TT)      // 131072 rows
#define C       384
#define NH      8
#define HD      48
#define C4      1536
#define QKVN    1152
#define PLANE   ((size_t)BATCH * NH * TT * HD)

typedef __half f16;

// ---------------- device scratch ----------------
__device__ __align__(256) f16   g_h_hi[BT * C], g_h_lo[BT * C];
__device__ __align__(256) f16   g_qkvh[5 * PLANE];   // planes: q_hi,q_lo,k_hi,k_lo,v_hi
__device__ __align__(256) f16   g_attn_hi[BT * C];
__device__ __align__(256) float g_x2[BT * C];
__device__ __align__(256) f16   g_hid_hi[BT * C4];
__device__ __align__(256) f16   g_wqkv_hi[QKVN * C], g_wqkv_lo[QKVN * C];
__device__ __align__(256) f16   g_wp_hi[C * C];
__device__ __align__(256) f16   g_w1_hi[C4 * C];
__device__ __align__(256) f16   g_w2_hi[C * C4];

// ---------------- PTX helpers (base-arch only) ----------------
__device__ __forceinline__ uint32_t smem_u32(const void* p) {
    uint32_t a;
    asm("{ .reg .u64 t; cvta.to.shared.u64 t, %1; cvt.u32.u64 %0, t; }" : "=r"(a) : "l"(p));
    return a;
}
__device__ __forceinline__ void cpa16(uint32_t dst, const void* src) {
    asm volatile("cp.async.cg.shared.global [%0], [%1], 16;" :: "r"(dst), "l"(src));
}
#define CP_COMMIT() asm volatile("cp.async.commit_group;" ::: "memory")
#define CP_WAIT(n)  asm volatile("cp.async.wait_group %0;" :: "n"(n) : "memory")

__device__ __forceinline__ void ldsm_x4(uint32_t a, uint32_t* r) {
    asm volatile("ldmatrix.sync.aligned.m8n8.x4.shared.b16 {%0,%1,%2,%3}, [%4];"
                 : "=r"(r[0]), "=r"(r[1]), "=r"(r[2]), "=r"(r[3]) : "r"(a));
}
__device__ __forceinline__ void mma_16816(float* d, const uint32_t* a, const uint32_t* b) {
    asm volatile("mma.sync.aligned.m16n8k16.row.col.f32.f16.f16.f32 "
                 "{%0,%1,%2,%3}, {%4,%5,%6,%7}, {%8,%9}, {%0,%1,%2,%3};"
                 : "+f"(d[0]), "+f"(d[1]), "+f"(d[2]), "+f"(d[3])
                 : "r"(a[0]), "r"(a[1]), "r"(a[2]), "r"(a[3]), "r"(b[0]), "r"(b[1]));
}

// ---------------- fp16 hi/lo split ----------------
__device__ __forceinline__ void split_h(float v, f16& h, f16& l) {
    h = __float2half_rn(v);
    l = __float2half_rn(v - __half2float(h));
}
__device__ __forceinline__ uint32_t pack_h2(float a, float b) {
    __half2 h = __floats2half2_rn(a, b);
    return *(uint32_t*)&h;
}

// ---------------- fused weight prep (one launch) ----------------
__global__ void prep_all_kernel(const float* __restrict__ Wq, const float* __restrict__ Wk,
                                const float* __restrict__ Wv, const float* __restrict__ Wp,
                                const float* __restrict__ W1, const float* __restrict__ W2,
                                f16* __restrict__ wqkv_hi, f16* __restrict__ wqkv_lo,
                                f16* __restrict__ wp_hi, f16* __restrict__ w1_hi,
                                f16* __restrict__ w2_hi) {
    int idx = blockIdx.x * blockDim.x + threadIdx.x;
    const int NQKV = QKVN * C;
    const int NP   = C * C;
    const int N1   = C * C4;
    if (idx < NQKV) {
        int n = idx / C, k = idx % C;
        int m = n / C, hd = n % C;
        int h = hd / HD, d = hd % HD;
        const float* W = (m == 0) ? Wq : ((m == 1) ? Wk : Wv);
        split_h(W[(size_t)h * C * HD + (size_t)k * HD + d], wqkv_hi[idx], wqkv_lo[idx]);
        return;
    }
    idx -= NQKV;
    if (idx < NP) {
        int k = idx / C, n = idx % C;
        wp_hi[(size_t)n * C + k] = __float2half_rn(Wp[idx]);
        return;
    }
    idx -= NP;
    if (idx < N1) {
        int k = idx / C4, n = idx % C4;
        w1_hi[(size_t)n * C + k] = __float2half_rn(W1[idx]);
        return;
    }
    idx -= N1;
    if (idx < N1) {
        int k = idx / C, n = idx % C;
        w2_hi[(size_t)n * C4 + k] = __float2half_rn(W2[idx]);
    }
}
#define PREP_TOTAL (QKVN * C + C * C + 2 * C * C4)

// ---------------- layernorm: one warp per row, hi (+lo optional) fp16 ----------------
__global__ void ln_kernel(const float* __restrict__ x, const float* __restrict__ g,
                          const float* __restrict__ b,
                          f16* __restrict__ out_hi, f16* __restrict__ out_lo) {
    int row  = blockIdx.x * blockDim.y + threadIdx.y;
    int lane = threadIdx.x;
    const float* xr = x + (size_t)row * C;
    float4 v[3];
    float sum = 0.f, sq = 0.f;
#pragma unroll
    for (int i = 0; i < 3; i++) {
        v[i] = *(const float4*)(xr + i * 128 + lane * 4);
        sum += v[i].x + v[i].y + v[i].z + v[i].w;
        sq  += v[i].x * v[i].x + v[i].y * v[i].y + v[i].z * v[i].z + v[i].w * v[i].w;
    }
#pragma unroll
    for (int o = 16; o; o >>= 1) {
        sum += __shfl_xor_sync(0xffffffffu, sum, o);
        sq  += __shfl_xor_sync(0xffffffffu, sq, o);
    }
    float mean = sum * (1.0f / C);
    float var  = sq * (1.0f / C) - mean * mean;
    float rstd = rsqrtf(var + 1e-5f);
    size_t rbase = (size_t)row * C;
#pragma unroll
    for (int i = 0; i < 3; i++) {
        int col = i * 128 + lane * 4;
        float4 gg = *(const float4*)(g + col);
        float4 bb = *(const float4*)(b + col);
        float o0 = (v[i].x - mean) * rstd * gg.x + bb.x;
        float o1 = (v[i].y - mean) * rstd * gg.y + bb.y;
        float o2 = (v[i].z - mean) * rstd * gg.z + bb.z;
        float o3 = (v[i].w - mean) * rstd * gg.w + bb.w;
        f16 h0, l0, h1, l1, h2, l2, h3, l3;
        split_h(o0, h0, l0); split_h(o1, h1, l1);
        split_h(o2, h2, l2); split_h(o3, h3, l3);
        *(__half2*)(out_hi + rbase + col)     = __halves2half2(h0, h1);
        *(__half2*)(out_hi + rbase + col + 2) = __halves2half2(h2, h3);
        if (out_lo) {
            *(__half2*)(out_lo + rbase + col)     = __halves2half2(l0, l1);
            *(__half2*)(out_lo + rbase + col + 2) = __halves2half2(l2, l3);
        }
    }
}

// ---------------- HMMA GEMM: 128 threads, 4 warps, warp tile 64x64 ----------------
// BK = 32: hi/lo stage layout (Ahi@0, Alo@8192, Bhi@16384, Blo@24576; 64B rows)
// BK = 64: 1-term only (Ahi@0 16K, Bhi@16384 16K; 128B rows)
// terms per CTA: 3 when cb < n3, else tlo.
// MODE 1: +bias +res -> fp32 | MODE 2: +bias, relu -> fp16 | MODE 3: head-major qkv planes
#define BMT 128
#define BNT 128
#define STAGE_BYTES 32768
#define NSTAGE 3
#define GEMM_SMEM (NSTAGE * STAGE_BYTES)

template <int BK>
__device__ __forceinline__ uint32_t sw_off(int r, int c) {
    if (BK == 32) return (uint32_t)(r * 64  + ((c ^ ((r >> 1) & 3)) << 4));
    else          return (uint32_t)(r * 128 + ((c ^ (r & 7)) << 4));
}

template <int BK>
__device__ __forceinline__ void tile_load(uint32_t sdst, const f16* __restrict__ g,
                                          int ld, int tid) {
    if (BK == 32) {
#pragma unroll
        for (int i = 0; i < 4; i++) {
            int id = tid + i * 128;
            int r = id >> 2, c = id & 3;
            cpa16(sdst + sw_off<32>(r, c), g + (size_t)r * ld + c * 8);
        }
    } else {
#pragma unroll
        for (int i = 0; i < 8; i++) {
            int id = tid + i * 128;
            int r = id >> 3, c = id & 7;
            cpa16(sdst + sw_off<64>(r, c), g + (size_t)r * ld + c * 8);
        }
    }
}

// A fragments use a_kc = lane>>4; B fragments use b_kc = (lane>>3)&1.
template <int BK>
__device__ __forceinline__ void compute_stage(uint32_t st, int arow, int a_kc,
                                              int bn, int b_kc, int terms,
                                              float (&acc)[4][8][4]) {
#pragma unroll
    for (int ks = 0; ks < BK / 16; ks++) {
        const int akc = ks * 2 + a_kc;
        const int bkc = ks * 2 + b_kc;
        uint32_t a[4][4], bh[4][4], bl[4][4];
#pragma unroll
        for (int ma = 0; ma < 4; ma++) {
            int r = arow + ma * 16;
            ldsm_x4(st + sw_off<BK>(r, akc), a[ma]);
        }
#pragma unroll
        for (int p = 0; p < 4; p++) {
            int n = bn + p * 16;
            ldsm_x4(st + 16384 + sw_off<BK>(n, bkc), bh[p]);
        }
#pragma unroll
        for (int ma = 0; ma < 4; ma++)
#pragma unroll
            for (int na = 0; na < 8; na++)
                mma_16816(acc[ma][na], a[ma], &bh[na >> 1][(na & 1) * 2]);
        if (BK == 32 && terms >= 2) {
#pragma unroll
            for (int p = 0; p < 4; p++) {
                int n = bn + p * 16;
                ldsm_x4(st + 24576 + sw_off<32>(n, bkc), bl[p]);
            }
#pragma unroll
            for (int ma = 0; ma < 4; ma++)
#pragma unroll
                for (int na = 0; na < 8; na++)
                    mma_16816(acc[ma][na], a[ma], &bl[na >> 1][(na & 1) * 2]);
        }
        if (BK == 32 && terms >= 3) {
#pragma unroll
            for (int ma = 0; ma < 4; ma++) {
                int r = arow + ma * 16;
                ldsm_x4(st + 8192 + sw_off<32>(r, akc), a[ma]);
            }
#pragma unroll
            for (int ma = 0; ma < 4; ma++)
#pragma unroll
                for (int na = 0; na < 8; na++)
                    mma_16816(acc[ma][na], a[ma], &bh[na >> 1][(na & 1) * 2]);
        }
    }
}

template <int MODE, int BK>
__global__ __launch_bounds__(128, 2) void mma_gemm(
    const f16* __restrict__ Ahi, const f16* __restrict__ Alo,
    const f16* __restrict__ Bhi, const f16* __restrict__ Blo,
    const float* __restrict__ bias, const float* __restrict__ res,
    float* __restrict__ outf, f16* __restrict__ out_hi,
    int N, int K, int n3, int tlo)
{
    extern __shared__ char smem[];
    const uint32_t sb = smem_u32(smem);
    const int tid  = threadIdx.x;
    const int lane = tid & 31;
    const int wid  = tid >> 5;
    const int wm   = wid >> 1;
    const int wn   = wid & 1;
    const int cb   = blockIdx.x * BNT;
    const int rb   = blockIdx.y * BMT;
    const int NC   = K / BK;
    const int terms = (cb < n3) ? 3 : tlo;

    const f16* Ahi_t = Ahi + (size_t)rb * K;
    const f16* Alo_t = Alo ? Alo + (size_t)rb * K : nullptr;
    const f16* Bhi_t = Bhi + (size_t)cb * K;
    const f16* Blo_t = Blo ? Blo + (size_t)cb * K : nullptr;

    float acc[4][8][4];
#pragma unroll
    for (int i = 0; i < 4; i++)
#pragma unroll
        for (int j = 0; j < 8; j++)
#pragma unroll
            for (int q = 0; q < 4; q++) acc[i][j][q] = 0.f;

    const int arow = wm * 64 + (lane & 15);
    const int a_kc = lane >> 4;
    const int bn   = wn * 64 + ((lane >> 4) << 3) + (lane & 7);
    const int b_kc = (lane >> 3) & 1;

#define ISSUE(cn, s) do {                                                  \
        int _kc = (cn) * BK;                                               \
        uint32_t _st = sb + (s) * STAGE_BYTES;                             \
        tile_load<BK>(_st, Ahi_t + _kc, K, tid);                           \
        if (BK == 32 && terms >= 3) tile_load<32>(_st + 8192,  Alo_t + _kc, K, tid); \
        tile_load<BK>(_st + 16384, Bhi_t + _kc, K, tid);                   \
        if (BK == 32 && terms >= 2) tile_load<32>(_st + 24576, Blo_t + _kc, K, tid); \
        CP_COMMIT();                                                       \
    } while (0)

    ISSUE(0, 0);
    ISSUE(1, 1);

    int s = 0, s2 = 2;
    for (int c = 0; c < NC; c++) {
        if (c + 1 < NC) CP_WAIT(1); else CP_WAIT(0);
        __syncthreads();
        if (c + 2 < NC) ISSUE(c + 2, s2);
        compute_stage<BK>(sb + s * STAGE_BYTES, arow, a_kc, bn, b_kc, terms, acc);
        s  = (s == 2)  ? 0 : s + 1;
        s2 = (s2 == 2) ? 0 : s2 + 1;
    }
#undef ISSUE

    const int g  = lane >> 2;
    const int tg = lane & 3;
#pragma unroll
    for (int ma = 0; ma < 4; ma++) {
        int r0 = rb + wm * 64 + ma * 16 + g;
#pragma unroll
        for (int na = 0; na < 8; na++) {
            int col = cb + wn * 64 + na * 8 + tg * 2;
            float d0 = acc[ma][na][0], d1 = acc[ma][na][1];
            float d2 = acc[ma][na][2], d3 = acc[ma][na][3];
            if (MODE == 1 || MODE == 2) {
                float2 bb = *(const float2*)(bias + col);
                d0 += bb.x; d1 += bb.y; d2 += bb.x; d3 += bb.y;
            }
            if (MODE == 1) {
                float2 ra  = *(const float2*)(res + (size_t)r0 * N + col);
                float2 rbv = *(const float2*)(res + (size_t)(r0 + 8) * N + col);
                d0 += ra.x; d1 += ra.y; d2 += rbv.x; d3 += rbv.y;
                *(float2*)(outf + (size_t)r0 * N + col)       = make_float2(d0, d1);
                *(float2*)(outf + (size_t)(r0 + 8) * N + col) = make_float2(d2, d3);
            }
            if (MODE == 2) {
                d0 = fmaxf(d0, 0.f); d1 = fmaxf(d1, 0.f);
                d2 = fmaxf(d2, 0.f); d3 = fmaxf(d3, 0.f);
                *(__half2*)(out_hi + (size_t)r0 * N + col) =
                    __halves2half2(__float2half_rn(d0), __float2half_rn(d1));
                *(__half2*)(out_hi + (size_t)(r0 + 8) * N + col) =
                    __halves2half2(__float2half_rn(d2), __float2half_rn(d3));
            }
            if (MODE == 3) {
                // head-major planes: q_hi(0), q_lo(1), k_hi(2), k_lo(3), v_hi(4)
                int m  = col / C;
                int hd = col - m * C;
                int h  = hd / HD;
                int d  = hd - h * HD;
                size_t a0 = (((size_t)(r0 >> 6) * NH + h) * TT + (r0 & 63)) * HD + d;
                f16* hip = out_hi + (size_t)(m == 2 ? 4 : 2 * m) * PLANE;
                f16 h0, l0, h1, l1, h2, l2, h3, l3;
                split_h(d0, h0, l0); split_h(d1, h1, l1);
                split_h(d2, h2, l2); split_h(d3, h3, l3);
                *(__half2*)(hip + a0)          = __halves2half2(h0, h1);
                *(__half2*)(hip + a0 + 8 * HD) = __halves2half2(h2, h3);
                if (m < 2) {
                    f16* lop = out_hi + (size_t)(2 * m + 1) * PLANE;
                    *(__half2*)(lop + a0)          = __halves2half2(l0, l1);
                    *(__half2*)(lop + a0 + 8 * HD) = __halves2half2(l2, l3);
                }
            }
        }
    }
}

// ---------------- attention: flash-v2 style HMMA, one CTA per (batch, head) ----------------
// head-major planes. smem: Kh [64][112B], Kl [64][112B], VT [48][144B]; Q frags direct GMEM.
#define AKH 0
#define AKL 7168
#define AVT 14336
#define ATTN_SMEM (14336 + 48 * 144)   // 21248

__global__ __launch_bounds__(128, 8) void attn_mma_kernel(
    const f16* __restrict__ qkvh, f16* __restrict__ out_hi)
{
    __shared__ __align__(16) char sm[ATTN_SMEM];
    const uint32_t sb = smem_u32(sm);
    const int bh = blockIdx.x;
    const int b  = bh >> 3;
    const int h  = bh & 7;
    const int tid  = threadIdx.x;
    const int lane = tid & 31;
    const int w    = tid >> 5;

    const size_t blk = (size_t)bh * (TT * HD);
    const f16* qh_p = qkvh + blk;
    const f16* ql_p = qh_p + PLANE;
    const f16* kh_p = qh_p + 2 * PLANE;
    const f16* kl_p = qh_p + 3 * PLANE;
    const f16* v_p  = qh_p + 4 * PLANE;

    // cooperative load (fully coalesced): k hi/lo -> padded smem; v -> transposed smem
    for (int idx = tid; idx < 64 * 24; idx += 128) {
        int t  = idx / 24;
        int c2 = (idx % 24) * 2;
        int go = t * HD + c2;
        *(__half2*)(sm + AKH + t * 112 + c2 * 2) = *(const __half2*)(kh_p + go);
        *(__half2*)(sm + AKL + t * 112 + c2 * 2) = *(const __half2*)(kl_p + go);
        __half2 vv = *(const __half2*)(v_p + go);
        *(f16*)(sm + AVT + c2 * 144 + t * 2)       = __low2half(vv);
        *(f16*)(sm + AVT + (c2 + 1) * 144 + t * 2) = __high2half(vv);
    }
    __syncthreads();

    const int g  = lane >> 2;
    const int tq = lane & 3;
    const uint32_t kaddr = sb + AKH + (((lane >> 4) << 3) + (lane & 7)) * 112
                              + ((lane >> 3) & 1) * 16;
    const uint32_t vaddr = sb + AVT + (((lane >> 4) << 3) + (lane & 7)) * 144
                              + ((lane >> 3) & 1) * 16;
    const f16* q0_hi = qh_p + (16 * w + g) * HD + 2 * tq;
    const f16* q0_lo = ql_p + (16 * w + g) * HD + 2 * tq;

    float s[8][4];
#pragma unroll
    for (int i = 0; i < 8; i++)
#pragma unroll
        for (int q = 0; q < 4; q++) s[i][q] = 0.f;

    // S = q k^T (3-term), causal tile skipping
    for (int kt = 0; kt < 3; kt++) {
        uint32_t qh[4], ql[4];
        qh[0] = *(const uint32_t*)(q0_hi + kt * 16);
        qh[1] = *(const uint32_t*)(q0_hi + 8 * HD + kt * 16);
        qh[2] = *(const uint32_t*)(q0_hi + kt * 16 + 8);
        qh[3] = *(const uint32_t*)(q0_hi + 8 * HD + kt * 16 + 8);
        ql[0] = *(const uint32_t*)(q0_lo + kt * 16);
        ql[1] = *(const uint32_t*)(q0_lo + 8 * HD + kt * 16);
        ql[2] = *(const uint32_t*)(q0_lo + kt * 16 + 8);
        ql[3] = *(const uint32_t*)(q0_lo + 8 * HD + kt * 16 + 8);
        for (int nt2 = 0; nt2 <= w; nt2++) {
            uint32_t kh[4], kl[4];
            ldsm_x4(kaddr + nt2 * 1792 + kt * 32, kh);
            ldsm_x4(kaddr + (AKL - AKH) + nt2 * 1792 + kt * 32, kl);
            mma_16816(s[2 * nt2],     qh, kh);
            mma_16816(s[2 * nt2 + 1], qh, kh + 2);
            mma_16816(s[2 * nt2],     qh, kl);
            mma_16816(s[2 * nt2 + 1], qh, kl + 2);
            mma_16816(s[2 * nt2],     ql, kh);
            mma_16816(s[2 * nt2 + 1], ql, kh + 2);
        }
    }

    const int r0 = 16 * w + g;
    const int r1 = r0 + 8;
    const float scl = 2.449489742783178f;   // 48 * 384^-0.5
    float mx0 = -1e30f, mx1 = -1e30f;
    const int ntmax = 2 * w + 2;
#pragma unroll
    for (int nt = 0; nt < 8; nt++) {
        if (nt >= ntmax) { s[nt][0] = s[nt][1] = s[nt][2] = s[nt][3] = 0.f; continue; }
        int c0 = nt * 8 + tq * 2, c1 = c0 + 1;
        s[nt][0] = (c0 <= r0) ? s[nt][0] * scl : -1e30f;
        s[nt][1] = (c1 <= r0) ? s[nt][1] * scl : -1e30f;
        s[nt][2] = (c0 <= r1) ? s[nt][2] * scl : -1e30f;
        s[nt][3] = (c1 <= r1) ? s[nt][3] * scl : -1e30f;
        mx0 = fmaxf(mx0, fmaxf(s[nt][0], s[nt][1]));
        mx1 = fmaxf(mx1, fmaxf(s[nt][2], s[nt][3]));
    }
    mx0 = fmaxf(mx0, __shfl_xor_sync(0xffffffffu, mx0, 1));
    mx0 = fmaxf(mx0, __shfl_xor_sync(0xffffffffu, mx0, 2));
    mx1 = fmaxf(mx1, __shfl_xor_sync(0xffffffffu, mx1, 1));
    mx1 = fmaxf(mx1, __shfl_xor_sync(0xffffffffu, mx1, 2));

    const float l2e = 1.4426950408889634f;
    float sum0 = 0.f, sum1 = 0.f;
#pragma unroll
    for (int nt = 0; nt < 8; nt++) {
        if (nt >= ntmax) continue;
        s[nt][0] = exp2f((s[nt][0] - mx0) * l2e);
        s[nt][1] = exp2f((s[nt][1] - mx0) * l2e);
        s[nt][2] = exp2f((s[nt][2] - mx1) * l2e);
        s[nt][3] = exp2f((s[nt][3] - mx1) * l2e);
        sum0 += s[nt][0] + s[nt][1];
        sum1 += s[nt][2] + s[nt][3];
    }
    sum0 += __shfl_xor_sync(0xffffffffu, sum0, 1);
    sum0 += __shfl_xor_sync(0xffffffffu, sum0, 2);
    sum1 += __shfl_xor_sync(0xffffffffu, sum1, 1);
    sum1 += __shfl_xor_sync(0xffffffffu, sum1, 2);
    const float inv0 = 1.f / sum0, inv1 = 1.f / sum1;

    uint32_t ap[4][4];
    for (int kt = 0; kt <= w; kt++) {
        ap[kt][0] = pack_h2(s[2 * kt][0] * inv0,     s[2 * kt][1] * inv0);
        ap[kt][1] = pack_h2(s[2 * kt][2] * inv1,     s[2 * kt][3] * inv1);
        ap[kt][2] = pack_h2(s[2 * kt + 1][0] * inv0, s[2 * kt + 1][1] * inv0);
        ap[kt][3] = pack_h2(s[2 * kt + 1][2] * inv1, s[2 * kt + 1][3] * inv1);
    }

    float o[6][4];
#pragma unroll
    for (int i = 0; i < 6; i++)
#pragma unroll
        for (int q = 0; q < 4; q++) o[i][q] = 0.f;
    for (int kt = 0; kt <= w; kt++) {
        for (int nt2 = 0; nt2 < 3; nt2++) {
            uint32_t vb[4];
            ldsm_x4(vaddr + nt2 * 2304 + kt * 32, vb);
            mma_16816(o[2 * nt2],     ap[kt], vb);
            mma_16816(o[2 * nt2 + 1], ap[kt], vb + 2);
        }
    }

    f16* op = out_hi + (size_t)b * TT * C + h * HD;
#pragma unroll
    for (int nt = 0; nt < 6; nt++) {
        int d = nt * 8 + tq * 2;
        *(__half2*)(op + (size_t)r0 * C + d) = __floats2half2_rn(o[nt][0], o[nt][1]);
        *(__half2*)(op + (size_t)r1 * C + d) = __floats2half2_rn(o[nt][2], o[nt][3]);
    }
}

// ---------------- launch ----------------
extern "C" void kernel_launch(void* const* d_in, const int* in_sizes, int n_in,
                              void* d_out, int out_size) {
    const float* x     = (const float*)d_in[0];
    const float* ln1_g = (const float*)d_in[1];
    const float* ln1_b = (const float*)d_in[2];
    const float* ln2_g = (const float*)d_in[3];
    const float* ln2_b = (const float*)d_in[4];
    const float* Wq    = (const float*)d_in[5];
    const float* Wk    = (const float*)d_in[6];
    const float* Wv    = (const float*)d_in[7];
    const float* Wp    = (const float*)d_in[8];
    const float* bp    = (const float*)d_in[9];
    const float* W1    = (const float*)d_in[10];
    const float* b1    = (const float*)d_in[11];
    const float* W2    = (const float*)d_in[12];
    const float* b2    = (const float*)d_in[13];
    float* out = (float*)d_out;

    f16 *ph_hi, *ph_lo, *pqkvh, *pattn_hi, *phid_hi;
    f16 *pwqkv_hi, *pwqkv_lo, *pwp_hi, *pw1_hi, *pw2_hi;
    float *px2;
    cudaGetSymbolAddress((void**)&ph_hi, g_h_hi);
    cudaGetSymbolAddress((void**)&ph_lo, g_h_lo);
    cudaGetSymbolAddress((void**)&pqkvh, g_qkvh);
    cudaGetSymbolAddress((void**)&pattn_hi, g_attn_hi);
    cudaGetSymbolAddress((void**)&px2, g_x2);
    cudaGetSymbolAddress((void**)&phid_hi, g_hid_hi);
    cudaGetSymbolAddress((void**)&pwqkv_hi, g_wqkv_hi); cudaGetSymbolAddress((void**)&pwqkv_lo, g_wqkv_lo);
    cudaGetSymbolAddress((void**)&pwp_hi, g_wp_hi);
    cudaGetSymbolAddress((void**)&pw1_hi, g_w1_hi);
    cudaGetSymbolAddress((void**)&pw2_hi, g_w2_hi);

    static int attr_set = 0;
    if (!attr_set) {
        cudaFuncSetAttribute((const void*)mma_gemm<3,32>, cudaFuncAttributeMaxDynamicSharedMemorySize, GEMM_SMEM);
        cudaFuncSetAttribute((const void*)mma_gemm<1,64>, cudaFuncAttributeMaxDynamicSharedMemorySize, GEMM_SMEM);
        cudaFuncSetAttribute((const void*)mma_gemm<2,64>, cudaFuncAttributeMaxDynamicSharedMemorySize, GEMM_SMEM);
        attr_set = 1;
    }

    // fused weight prep
    prep_all_kernel<<<(PREP_TOTAL + 255) / 256, 256>>>(
        Wq, Wk, Wv, Wp, W1, W2, pwqkv_hi, pwqkv_lo, pwp_hi, pw1_hi, pw2_hi);

    // LN1 (hi+lo: q,k GEMM is 3-term)
    ln_kernel<<<BT / 8, dim3(32, 8)>>>(x, ln1_g, ln1_b, ph_hi, ph_lo);
    // QKV (BK=32): q,k cols 3-term, v cols 1-term -> head-major fp16 planes
    mma_gemm<3,32><<<dim3(QKVN / 128, BT / 128), 128, GEMM_SMEM>>>(
        ph_hi, ph_lo, pwqkv_hi, pwqkv_lo, nullptr, nullptr, nullptr, pqkvh,
        QKVN, C, 2 * C, 1);
    // attention (3-term S, contiguous head-major loads)
    attn_mma_kernel<<<BATCH * NH, 128>>>(pqkvh, pattn_hi);
    // proj + bias + residual -> x2 (1-term, BK=64)
    mma_gemm<1,64><<<dim3(C / 128, BT / 128), 128, GEMM_SMEM>>>(
        pattn_hi, nullptr, pwp_hi, nullptr, bp, x, px2, nullptr, C, C, 0, 1);
    // LN2 (hi only)
    ln_kernel<<<BT / 8, dim3(32, 8)>>>(px2, ln2_g, ln2_b, ph_hi, nullptr);
    // FFN1 + bias + relu -> hidden hi (1-term, BK=64)
    mma_gemm<2,64><<<dim3(C4 / 128, BT / 128), 128, GEMM_SMEM>>>(
        ph_hi, nullptr, pw1_hi, nullptr, b1, nullptr, nullptr, phid_hi, C4, C, 0, 1);
    // FFN2 + bias + residual -> out (1-term, BK=64)
    mma_gemm<1,64><<<dim3(C / 128, BT / 128), 128, GEMM_SMEM>>>(
        phid_hi, nullptr, pw2_hi, nullptr, b2, px2, out, nullptr, C, C4, 0, 1);
}

// round 14
// speedup vs baseline: 6.4552x; 1.0471x over previous
#include <cuda_runtime.h>
#include <cuda_fp16.h>
#include <math.h>
#include <stdint.h>

// ---------------- problem constants ----------------
#define BATCH   2048
#define TT      64
#define BT      (BATCH * TT)      // 131072 rows
#define C       384
#define NH      8
#define HD      48
#define C4      1536
#define QKVN    1152
#define PLANE   ((size_t)BATCH * NH * TT * HD)

typedef __half f16;

// ---------------- device scratch ----------------
__device__ __align__(256) f16   g_h_hi[BT * C], g_h_lo[BT * C];
__device__ __align__(256) f16   g_qkvh[4 * PLANE];   // planes: q_hi, k_hi, k_lo, v_hi
__device__ __align__(256) f16   g_attn_hi[BT * C];
__device__ __align__(256) float g_x2[BT * C];
__device__ __align__(256) f16   g_hid_hi[BT * C4];
__device__ __align__(256) f16   g_wqkv_hi[QKVN * C], g_wqkv_lo[QKVN * C];
__device__ __align__(256) f16   g_wp_hi[C * C];
__device__ __align__(256) f16   g_w1_hi[C4 * C];
__device__ __align__(256) f16   g_w2_hi[C * C4];

// ---------------- PTX helpers (base-arch only) ----------------
__device__ __forceinline__ uint32_t smem_u32(const void* p) {
    uint32_t a;
    asm("{ .reg .u64 t; cvta.to.shared.u64 t, %1; cvt.u32.u64 %0, t; }" : "=r"(a) : "l"(p));
    return a;
}
__device__ __forceinline__ void cpa16(uint32_t dst, const void* src) {
    asm volatile("cp.async.cg.shared.global [%0], [%1], 16;" :: "r"(dst), "l"(src));
}
#define CP_COMMIT() asm volatile("cp.async.commit_group;" ::: "memory")
#define CP_WAIT(n)  asm volatile("cp.async.wait_group %0;" :: "n"(n) : "memory")

__device__ __forceinline__ void ldsm_x4(uint32_t a, uint32_t* r) {
    asm volatile("ldmatrix.sync.aligned.m8n8.x4.shared.b16 {%0,%1,%2,%3}, [%4];"
                 : "=r"(r[0]), "=r"(r[1]), "=r"(r[2]), "=r"(r[3]) : "r"(a));
}
__device__ __forceinline__ void mma_16816(float* d, const uint32_t* a, const uint32_t* b) {
    asm volatile("mma.sync.aligned.m16n8k16.row.col.f32.f16.f16.f32 "
                 "{%0,%1,%2,%3}, {%4,%5,%6,%7}, {%8,%9}, {%0,%1,%2,%3};"
                 : "+f"(d[0]), "+f"(d[1]), "+f"(d[2]), "+f"(d[3])
                 : "r"(a[0]), "r"(a[1]), "r"(a[2]), "r"(a[3]), "r"(b[0]), "r"(b[1]));
}

// ---------------- fp16 hi/lo split ----------------
__device__ __forceinline__ void split_h(float v, f16& h, f16& l) {
    h = __float2half_rn(v);
    l = __float2half_rn(v - __half2float(h));
}
__device__ __forceinline__ uint32_t pack_h2(float a, float b) {
    __half2 h = __floats2half2_rn(a, b);
    return *(uint32_t*)&h;
}

// ---------------- fused weight prep (one launch) ----------------
__global__ void prep_all_kernel(const float* __restrict__ Wq, const float* __restrict__ Wk,
                                const float* __restrict__ Wv, const float* __restrict__ Wp,
                                const float* __restrict__ W1, const float* __restrict__ W2,
                                f16* __restrict__ wqkv_hi, f16* __restrict__ wqkv_lo,
                                f16* __restrict__ wp_hi, f16* __restrict__ w1_hi,
                                f16* __restrict__ w2_hi) {
    int idx = blockIdx.x * blockDim.x + threadIdx.x;
    const int NQKV = QKVN * C;
    const int NP   = C * C;
    const int N1   = C * C4;
    if (idx < NQKV) {
        int n = idx / C, k = idx % C;
        int m = n / C, hd = n % C;
        int h = hd / HD, d = hd % HD;
        const float* W = (m == 0) ? Wq : ((m == 1) ? Wk : Wv);
        split_h(W[(size_t)h * C * HD + (size_t)k * HD + d], wqkv_hi[idx], wqkv_lo[idx]);
        return;
    }
    idx -= NQKV;
    if (idx < NP) {
        int k = idx / C, n = idx % C;
        wp_hi[(size_t)n * C + k] = __float2half_rn(Wp[idx]);
        return;
    }
    idx -= NP;
    if (idx < N1) {
        int k = idx / C4, n = idx % C4;
        w1_hi[(size_t)n * C + k] = __float2half_rn(W1[idx]);
        return;
    }
    idx -= N1;
    if (idx < N1) {
        int k = idx / C, n = idx % C;
        w2_hi[(size_t)n * C4 + k] = __float2half_rn(W2[idx]);
    }
}
#define PREP_TOTAL (QKVN * C + C * C + 2 * C * C4)

// ---------------- layernorm: one warp per row, hi (+lo optional) fp16 ----------------
__global__ void ln_kernel(const float* __restrict__ x, const float* __restrict__ g,
                          const float* __restrict__ b,
                          f16* __restrict__ out_hi, f16* __restrict__ out_lo) {
    int row  = blockIdx.x * blockDim.y + threadIdx.y;
    int lane = threadIdx.x;
    const float* xr = x + (size_t)row * C;
    float4 v[3];
    float sum = 0.f, sq = 0.f;
#pragma unroll
    for (int i = 0; i < 3; i++) {
        v[i] = *(const float4*)(xr + i * 128 + lane * 4);
        sum += v[i].x + v[i].y + v[i].z + v[i].w;
        sq  += v[i].x * v[i].x + v[i].y * v[i].y + v[i].z * v[i].z + v[i].w * v[i].w;
    }
#pragma unroll
    for (int o = 16; o; o >>= 1) {
        sum += __shfl_xor_sync(0xffffffffu, sum, o);
        sq  += __shfl_xor_sync(0xffffffffu, sq, o);
    }
    float mean = sum * (1.0f / C);
    float var  = sq * (1.0f / C) - mean * mean;
    float rstd = rsqrtf(var + 1e-5f);
    size_t rbase = (size_t)row * C;
#pragma unroll
    for (int i = 0; i < 3; i++) {
        int col = i * 128 + lane * 4;
        float4 gg = *(const float4*)(g + col);
        float4 bb = *(const float4*)(b + col);
        float o0 = (v[i].x - mean) * rstd * gg.x + bb.x;
        float o1 = (v[i].y - mean) * rstd * gg.y + bb.y;
        float o2 = (v[i].z - mean) * rstd * gg.z + bb.z;
        float o3 = (v[i].w - mean) * rstd * gg.w + bb.w;
        f16 h0, l0, h1, l1, h2, l2, h3, l3;
        split_h(o0, h0, l0); split_h(o1, h1, l1);
        split_h(o2, h2, l2); split_h(o3, h3, l3);
        *(__half2*)(out_hi + rbase + col)     = __halves2half2(h0, h1);
        *(__half2*)(out_hi + rbase + col + 2) = __halves2half2(h2, h3);
        if (out_lo) {
            *(__half2*)(out_lo + rbase + col)     = __halves2half2(l0, l1);
            *(__half2*)(out_lo + rbase + col + 2) = __halves2half2(l2, l3);
        }
    }
}

// ---------------- HMMA GEMM: 128 threads, 4 warps, warp tile 64x64 ----------------
// BK = 32: hi/lo stage layout (Ahi@0, Alo@8192, Bhi@16384, Blo@24576; 64B rows)
// BK = 64: 1-term only (Ahi@0 16K, Bhi@16384 16K; 128B rows)
// terms per CTA: byte (cb/384) of tpack. 1 = AhiBhi, 2 = +AhiBlo, 3 = +AloBhi.
// MODE 1: +bias +res -> fp32 | MODE 2: +bias, relu -> fp16 | MODE 3: head-major qkv planes
#define BMT 128
#define BNT 128
#define STAGE_BYTES 32768
#define NSTAGE 3
#define GEMM_SMEM (NSTAGE * STAGE_BYTES)

template <int BK>
__device__ __forceinline__ uint32_t sw_off(int r, int c) {
    if (BK == 32) return (uint32_t)(r * 64  + ((c ^ ((r >> 1) & 3)) << 4));
    else          return (uint32_t)(r * 128 + ((c ^ (r & 7)) << 4));
}

template <int BK>
__device__ __forceinline__ void tile_load(uint32_t sdst, const f16* __restrict__ g,
                                          int ld, int tid) {
    if (BK == 32) {
#pragma unroll
        for (int i = 0; i < 4; i++) {
            int id = tid + i * 128;
            int r = id >> 2, c = id & 3;
            cpa16(sdst + sw_off<32>(r, c), g + (size_t)r * ld + c * 8);
        }
    } else {
#pragma unroll
        for (int i = 0; i < 8; i++) {
            int id = tid + i * 128;
            int r = id >> 3, c = id & 7;
            cpa16(sdst + sw_off<64>(r, c), g + (size_t)r * ld + c * 8);
        }
    }
}

// A fragments use a_kc = lane>>4; B fragments use b_kc = (lane>>3)&1.
template <int BK>
__device__ __forceinline__ void compute_stage(uint32_t st, int arow, int a_kc,
                                              int bn, int b_kc, int terms,
                                              float (&acc)[4][8][4]) {
#pragma unroll
    for (int ks = 0; ks < BK / 16; ks++) {
        const int akc = ks * 2 + a_kc;
        const int bkc = ks * 2 + b_kc;
        uint32_t a[4][4], bh[4][4], bl[4][4];
#pragma unroll
        for (int ma = 0; ma < 4; ma++) {
            int r = arow + ma * 16;
            ldsm_x4(st + sw_off<BK>(r, akc), a[ma]);
        }
#pragma unroll
        for (int p = 0; p < 4; p++) {
            int n = bn + p * 16;
            ldsm_x4(st + 16384 + sw_off<BK>(n, bkc), bh[p]);
        }
#pragma unroll
        for (int ma = 0; ma < 4; ma++)
#pragma unroll
            for (int na = 0; na < 8; na++)
                mma_16816(acc[ma][na], a[ma], &bh[na >> 1][(na & 1) * 2]);
        if (BK == 32 && terms >= 2) {
#pragma unroll
            for (int p = 0; p < 4; p++) {
                int n = bn + p * 16;
                ldsm_x4(st + 24576 + sw_off<32>(n, bkc), bl[p]);
            }
#pragma unroll
            for (int ma = 0; ma < 4; ma++)
#pragma unroll
                for (int na = 0; na < 8; na++)
                    mma_16816(acc[ma][na], a[ma], &bl[na >> 1][(na & 1) * 2]);
        }
        if (BK == 32 && terms >= 3) {
#pragma unroll
            for (int ma = 0; ma < 4; ma++) {
                int r = arow + ma * 16;
                ldsm_x4(st + 8192 + sw_off<32>(r, akc), a[ma]);
            }
#pragma unroll
            for (int ma = 0; ma < 4; ma++)
#pragma unroll
                for (int na = 0; na < 8; na++)
                    mma_16816(acc[ma][na], a[ma], &bh[na >> 1][(na & 1) * 2]);
        }
    }
}

template <int MODE, int BK>
__global__ __launch_bounds__(128, 2) void mma_gemm(
    const f16* __restrict__ Ahi, const f16* __restrict__ Alo,
    const f16* __restrict__ Bhi, const f16* __restrict__ Blo,
    const float* __restrict__ bias, const float* __restrict__ res,
    float* __restrict__ outf, f16* __restrict__ out_hi,
    int N, int K, int tpack)
{
    extern __shared__ char smem[];
    const uint32_t sb = smem_u32(smem);
    const int tid  = threadIdx.x;
    const int lane = tid & 31;
    const int wid  = tid >> 5;
    const int wm   = wid >> 1;
    const int wn   = wid & 1;
    const int cb   = blockIdx.x * BNT;
    const int rb   = blockIdx.y * BMT;
    const int NC   = K / BK;
    const int terms = (tpack >> (8 * (cb / C))) & 0xF;

    const f16* Ahi_t = Ahi + (size_t)rb * K;
    const f16* Alo_t = Alo ? Alo + (size_t)rb * K : nullptr;
    const f16* Bhi_t = Bhi + (size_t)cb * K;
    const f16* Blo_t = Blo ? Blo + (size_t)cb * K : nullptr;

    float acc[4][8][4];
#pragma unroll
    for (int i = 0; i < 4; i++)
#pragma unroll
        for (int j = 0; j < 8; j++)
#pragma unroll
            for (int q = 0; q < 4; q++) acc[i][j][q] = 0.f;

    const int arow = wm * 64 + (lane & 15);
    const int a_kc = lane >> 4;
    const int bn   = wn * 64 + ((lane >> 4) << 3) + (lane & 7);
    const int b_kc = (lane >> 3) & 1;

#define ISSUE(cn, s) do {                                                  \
        int _kc = (cn) * BK;                                               \
        uint32_t _st = sb + (s) * STAGE_BYTES;                             \
        tile_load<BK>(_st, Ahi_t + _kc, K, tid);                           \
        if (BK == 32 && terms >= 3) tile_load<32>(_st + 8192,  Alo_t + _kc, K, tid); \
        tile_load<BK>(_st + 16384, Bhi_t + _kc, K, tid);                   \
        if (BK == 32 && terms >= 2) tile_load<32>(_st + 24576, Blo_t + _kc, K, tid); \
        CP_COMMIT();                                                       \
    } while (0)

    ISSUE(0, 0);
    ISSUE(1, 1);

    int s = 0, s2 = 2;
    for (int c = 0; c < NC; c++) {
        if (c + 1 < NC) CP_WAIT(1); else CP_WAIT(0);
        __syncthreads();
        if (c + 2 < NC) ISSUE(c + 2, s2);
        compute_stage<BK>(sb + s * STAGE_BYTES, arow, a_kc, bn, b_kc, terms, acc);
        s  = (s == 2)  ? 0 : s + 1;
        s2 = (s2 == 2) ? 0 : s2 + 1;
    }
#undef ISSUE

    const int g  = lane >> 2;
    const int tg = lane & 3;
#pragma unroll
    for (int ma = 0; ma < 4; ma++) {
        int r0 = rb + wm * 64 + ma * 16 + g;
#pragma unroll
        for (int na = 0; na < 8; na++) {
            int col = cb + wn * 64 + na * 8 + tg * 2;
            float d0 = acc[ma][na][0], d1 = acc[ma][na][1];
            float d2 = acc[ma][na][2], d3 = acc[ma][na][3];
            if (MODE == 1 || MODE == 2) {
                float2 bb = *(const float2*)(bias + col);
                d0 += bb.x; d1 += bb.y; d2 += bb.x; d3 += bb.y;
            }
            if (MODE == 1) {
                float2 ra  = *(const float2*)(res + (size_t)r0 * N + col);
                float2 rbv = *(const float2*)(res + (size_t)(r0 + 8) * N + col);
                d0 += ra.x; d1 += ra.y; d2 += rbv.x; d3 += rbv.y;
                *(float2*)(outf + (size_t)r0 * N + col)       = make_float2(d0, d1);
                *(float2*)(outf + (size_t)(r0 + 8) * N + col) = make_float2(d2, d3);
            }
            if (MODE == 2) {
                d0 = fmaxf(d0, 0.f); d1 = fmaxf(d1, 0.f);
                d2 = fmaxf(d2, 0.f); d3 = fmaxf(d3, 0.f);
                *(__half2*)(out_hi + (size_t)r0 * N + col) =
                    __halves2half2(__float2half_rn(d0), __float2half_rn(d1));
                *(__half2*)(out_hi + (size_t)(r0 + 8) * N + col) =
                    __halves2half2(__float2half_rn(d2), __float2half_rn(d3));
            }
            if (MODE == 3) {
                // head-major planes: q_hi(0), k_hi(1), k_lo(2), v_hi(3)
                int m  = col / C;
                int hd = col - m * C;
                int h  = hd / HD;
                int d  = hd - h * HD;
                size_t a0 = (((size_t)(r0 >> 6) * NH + h) * TT + (r0 & 63)) * HD + d;
                f16* hip = out_hi + (size_t)(m == 2 ? 3 : m) * PLANE;
                f16 h0, l0, h1, l1, h2, l2, h3, l3;
                split_h(d0, h0, l0); split_h(d1, h1, l1);
                split_h(d2, h2, l2); split_h(d3, h3, l3);
                *(__half2*)(hip + a0)          = __halves2half2(h0, h1);
                *(__half2*)(hip + a0 + 8 * HD) = __halves2half2(h2, h3);
                if (m == 1) {
                    f16* lop = out_hi + 2 * PLANE;
                    *(__half2*)(lop + a0)          = __halves2half2(l0, l1);
                    *(__half2*)(lop + a0 + 8 * HD) = __halves2half2(l2, l3);
                }
            }
        }
    }
}

// ---------------- attention: flash-v2 style HMMA, one CTA per (batch, head) ----------------
// head-major planes q_hi,k_hi,k_lo,v. smem: Kh [64][112B], Kl [64][112B], VT [48][144B].
// Q fragments direct from GMEM (q_hi only; S = qh*kh + qh*kl, 2-term).
#define AKH 0
#define AKL 7168
#define AVT 14336
#define ATTN_SMEM (14336 + 48 * 144)   // 21248

__global__ __launch_bounds__(128, 8) void attn_mma_kernel(
    const f16* __restrict__ qkvh, f16* __restrict__ out_hi)
{
    __shared__ __align__(16) char sm[ATTN_SMEM];
    const uint32_t sb = smem_u32(sm);
    const int bh = blockIdx.x;
    const int b  = bh >> 3;
    const int h  = bh & 7;
    const int tid  = threadIdx.x;
    const int lane = tid & 31;
    const int w    = tid >> 5;

    const size_t blk = (size_t)bh * (TT * HD);
    const f16* q_p  = qkvh + blk;
    const f16* kh_p = q_p + PLANE;
    const f16* kl_p = q_p + 2 * PLANE;
    const f16* v_p  = q_p + 3 * PLANE;

    // k hi/lo: vectorized 16B loads into padded smem
    for (int idx = tid; idx < 64 * 6; idx += 128) {
        int t = idx / 6, c = idx % 6;
        int go = t * HD + c * 8;
        *(uint4*)(sm + AKH + t * 112 + c * 16) = *(const uint4*)(kh_p + go);
        *(uint4*)(sm + AKL + t * 112 + c * 16) = *(const uint4*)(kl_p + go);
    }
    // v -> transposed smem
    for (int idx = tid; idx < 64 * 24; idx += 128) {
        int t  = idx / 24;
        int c2 = (idx % 24) * 2;
        __half2 vv = *(const __half2*)(v_p + t * HD + c2);
        *(f16*)(sm + AVT + c2 * 144 + t * 2)       = __low2half(vv);
        *(f16*)(sm + AVT + (c2 + 1) * 144 + t * 2) = __high2half(vv);
    }
    __syncthreads();

    const int g  = lane >> 2;
    const int tq = lane & 3;
    const uint32_t kaddr = sb + AKH + (((lane >> 4) << 3) + (lane & 7)) * 112
                              + ((lane >> 3) & 1) * 16;
    const uint32_t vaddr = sb + AVT + (((lane >> 4) << 3) + (lane & 7)) * 144
                              + ((lane >> 3) & 1) * 16;
    const f16* q0 = q_p + (16 * w + g) * HD + 2 * tq;

    float s[8][4];
#pragma unroll
    for (int i = 0; i < 8; i++)
#pragma unroll
        for (int q = 0; q < 4; q++) s[i][q] = 0.f;

    // S = q k^T (2-term: qh*kh + qh*kl), causal tile skipping
    for (int kt = 0; kt < 3; kt++) {
        uint32_t qh[4];
        qh[0] = *(const uint32_t*)(q0 + kt * 16);
        qh[1] = *(const uint32_t*)(q0 + 8 * HD + kt * 16);
        qh[2] = *(const uint32_t*)(q0 + kt * 16 + 8);
        qh[3] = *(const uint32_t*)(q0 + 8 * HD + kt * 16 + 8);
        for (int nt2 = 0; nt2 <= w; nt2++) {
            uint32_t kh[4], kl[4];
            ldsm_x4(kaddr + nt2 * 1792 + kt * 32, kh);
            ldsm_x4(kaddr + (AKL - AKH) + nt2 * 1792 + kt * 32, kl);
            mma_16816(s[2 * nt2],     qh, kh);
            mma_16816(s[2 * nt2 + 1], qh, kh + 2);
            mma_16816(s[2 * nt2],     qh, kl);
            mma_16816(s[2 * nt2 + 1], qh, kl + 2);
        }
    }

    const int r0 = 16 * w + g;
    const int r1 = r0 + 8;
    const float scl = 2.449489742783178f;   // 48 * 384^-0.5
    float mx0 = -1e30f, mx1 = -1e30f;
    const int ntmax = 2 * w + 2;
#pragma unroll
    for (int nt = 0; nt < 8; nt++) {
        if (nt >= ntmax) { s[nt][0] = s[nt][1] = s[nt][2] = s[nt][3] = 0.f; continue; }
        int c0 = nt * 8 + tq * 2, c1 = c0 + 1;
        s[nt][0] = (c0 <= r0) ? s[nt][0] * scl : -1e30f;
        s[nt][1] = (c1 <= r0) ? s[nt][1] * scl : -1e30f;
        s[nt][2] = (c0 <= r1) ? s[nt][2] * scl : -1e30f;
        s[nt][3] = (c1 <= r1) ? s[nt][3] * scl : -1e30f;
        mx0 = fmaxf(mx0, fmaxf(s[nt][0], s[nt][1]));
        mx1 = fmaxf(mx1, fmaxf(s[nt][2], s[nt][3]));
    }
    mx0 = fmaxf(mx0, __shfl_xor_sync(0xffffffffu, mx0, 1));
    mx0 = fmaxf(mx0, __shfl_xor_sync(0xffffffffu, mx0, 2));
    mx1 = fmaxf(mx1, __shfl_xor_sync(0xffffffffu, mx1, 1));
    mx1 = fmaxf(mx1, __shfl_xor_sync(0xffffffffu, mx1, 2));

    const float l2e = 1.4426950408889634f;
    float sum0 = 0.f, sum1 = 0.f;
#pragma unroll
    for (int nt = 0; nt < 8; nt++) {
        if (nt >= ntmax) continue;
        s[nt][0] = exp2f((s[nt][0] - mx0) * l2e);
        s[nt][1] = exp2f((s[nt][1] - mx0) * l2e);
        s[nt][2] = exp2f((s[nt][2] - mx1) * l2e);
        s[nt][3] = exp2f((s[nt][3] - mx1) * l2e);
        sum0 += s[nt][0] + s[nt][1];
        sum1 += s[nt][2] + s[nt][3];
    }
    sum0 += __shfl_xor_sync(0xffffffffu, sum0, 1);
    sum0 += __shfl_xor_sync(0xffffffffu, sum0, 2);
    sum1 += __shfl_xor_sync(0xffffffffu, sum1, 1);
    sum1 += __shfl_xor_sync(0xffffffffu, sum1, 2);
    const float inv0 = 1.f / sum0, inv1 = 1.f / sum1;

    uint32_t ap[4][4];
    for (int kt = 0; kt <= w; kt++) {
        ap[kt][0] = pack_h2(s[2 * kt][0] * inv0,     s[2 * kt][1] * inv0);
        ap[kt][1] = pack_h2(s[2 * kt][2] * inv1,     s[2 * kt][3] * inv1);
        ap[kt][2] = pack_h2(s[2 * kt + 1][0] * inv0, s[2 * kt + 1][1] * inv0);
        ap[kt][3] = pack_h2(s[2 * kt + 1][2] * inv1, s[2 * kt + 1][3] * inv1);
    }

    float o[6][4];
#pragma unroll
    for (int i = 0; i < 6; i++)
#pragma unroll
        for (int q = 0; q < 4; q++) o[i][q] = 0.f;
    for (int kt = 0; kt <= w; kt++) {
        for (int nt2 = 0; nt2 < 3; nt2++) {
            uint32_t vb[4];
            ldsm_x4(vaddr + nt2 * 2304 + kt * 32, vb);
            mma_16816(o[2 * nt2],     ap[kt], vb);
            mma_16816(o[2 * nt2 + 1], ap[kt], vb + 2);
        }
    }

    f16* op = out_hi + (size_t)b * TT * C + h * HD;
#pragma unroll
    for (int nt = 0; nt < 6; nt++) {
        int d = nt * 8 + tq * 2;
        *(__half2*)(op + (size_t)r0 * C + d) = __floats2half2_rn(o[nt][0], o[nt][1]);
        *(__half2*)(op + (size_t)r1 * C + d) = __floats2half2_rn(o[nt][2], o[nt][3]);
    }
}

// ---------------- launch ----------------
extern "C" void kernel_launch(void* const* d_in, const int* in_sizes, int n_in,
                              void* d_out, int out_size) {
    const float* x     = (const float*)d_in[0];
    const float* ln1_g = (const float*)d_in[1];
    const float* ln1_b = (const float*)d_in[2];
    const float* ln2_g = (const float*)d_in[3];
    const float* ln2_b = (const float*)d_in[4];
    const float* Wq    = (const float*)d_in[5];
    const float* Wk    = (const float*)d_in[6];
    const float* Wv    = (const float*)d_in[7];
    const float* Wp    = (const float*)d_in[8];
    const float* bp    = (const float*)d_in[9];
    const float* W1    = (const float*)d_in[10];
    const float* b1    = (const float*)d_in[11];
    const float* W2    = (const float*)d_in[12];
    const float* b2    = (const float*)d_in[13];
    float* out = (float*)d_out;

    f16 *ph_hi, *ph_lo, *pqkvh, *pattn_hi, *phid_hi;
    f16 *pwqkv_hi, *pwqkv_lo, *pwp_hi, *pw1_hi, *pw2_hi;
    float *px2;
    cudaGetSymbolAddress((void**)&ph_hi, g_h_hi);
    cudaGetSymbolAddress((void**)&ph_lo, g_h_lo);
    cudaGetSymbolAddress((void**)&pqkvh, g_qkvh);
    cudaGetSymbolAddress((void**)&pattn_hi, g_attn_hi);
    cudaGetSymbolAddress((void**)&px2, g_x2);
    cudaGetSymbolAddress((void**)&phid_hi, g_hid_hi);
    cudaGetSymbolAddress((void**)&pwqkv_hi, g_wqkv_hi); cudaGetSymbolAddress((void**)&pwqkv_lo, g_wqkv_lo);
    cudaGetSymbolAddress((void**)&pwp_hi, g_wp_hi);
    cudaGetSymbolAddress((void**)&pw1_hi, g_w1_hi);
    cudaGetSymbolAddress((void**)&pw2_hi, g_w2_hi);

    static int attr_set = 0;
    if (!attr_set) {
        cudaFuncSetAttribute((const void*)mma_gemm<3,32>, cudaFuncAttributeMaxDynamicSharedMemorySize, GEMM_SMEM);
        cudaFuncSetAttribute((const void*)mma_gemm<1,64>, cudaFuncAttributeMaxDynamicSharedMemorySize, GEMM_SMEM);
        cudaFuncSetAttribute((const void*)mma_gemm<2,64>, cudaFuncAttributeMaxDynamicSharedMemorySize, GEMM_SMEM);
        attr_set = 1;
    }

    // fused weight prep
    prep_all_kernel<<<(PREP_TOTAL + 255) / 256, 256>>>(
        Wq, Wk, Wv, Wp, W1, W2, pwqkv_hi, pwqkv_lo, pwp_hi, pw1_hi, pw2_hi);

    // LN1 (hi+lo: k GEMM is 3-term)
    ln_kernel<<<BT / 8, dim3(32, 8)>>>(x, ln1_g, ln1_b, ph_hi, ph_lo);
    // QKV (BK=32): q cols 2-term, k cols 3-term, v cols 1-term -> head-major planes
    mma_gemm<3,32><<<dim3(QKVN / 128, BT / 128), 128, GEMM_SMEM>>>(
        ph_hi, ph_lo, pwqkv_hi, pwqkv_lo, nullptr, nullptr, nullptr, pqkvh,
        QKVN, C, 0x010302);
    // attention (2-term S, contiguous head-major loads)
    attn_mma_kernel<<<BATCH * NH, 128>>>(pqkvh, pattn_hi);
    // proj + bias + residual -> x2 (1-term, BK=64)
    mma_gemm<1,64><<<dim3(C / 128, BT / 128), 128, GEMM_SMEM>>>(
        pattn_hi, nullptr, pwp_hi, nullptr, bp, x, px2, nullptr, C, C, 0x01);
    // LN2 (hi only)
    ln_kernel<<<BT / 8, dim3(32, 8)>>>(px2, ln2_g, ln2_b, ph_hi, nullptr);
    // FFN1 + bias + relu -> hidden hi (1-term, BK=64)
    mma_gemm<2,64><<<dim3(C4 / 128, BT / 128), 128, GEMM_SMEM>>>(
        ph_hi, nullptr, pw1_hi, nullptr, b1, nullptr, nullptr, phid_hi,
        C4, C, 0x01010101);
    // FFN2 + bias + residual -> out (1-term, BK=64)
    mma_gemm<1,64><<<dim3(C / 128, BT / 128), 128, GEMM_SMEM>>>(
        phid_hi, nullptr, pw2_hi, nullptr, b2, px2, out, nullptr, C, C4, 0x01);
}